// round 1
// baseline (speedup 1.0000x reference)
#include <cuda_runtime.h>
#include <math.h>
#include <stdint.h>

// Problem dims (fixed per reference)
#define Bn 8
#define Tn 2048
#define Cn 2048
#define Hn 8192
#define Mn (Bn * Tn)   // 16384 rows

// ---------------------------------------------------------------------------
// Scratch (device globals — allocation-free per harness rules)
// ---------------------------------------------------------------------------
__device__ float g_b0[(size_t)Mn * Cn];
__device__ float g_b1[(size_t)Mn * Cn];
__device__ float g_b2[(size_t)Mn * Cn];
__device__ float g_b3[(size_t)Mn * Cn];
__device__ float g_b4[(size_t)Mn * Cn];
__device__ float g_b5[(size_t)Mn * Cn];
__device__ float g_b6[(size_t)Mn * Cn];
__device__ float g_h [(size_t)Mn * Hn];

// ---------------------------------------------------------------------------
// LayerNorm: one block per row (C = 2048, 256 threads x 8 elems)
// ---------------------------------------------------------------------------
__global__ __launch_bounds__(256) void ln_kernel(
    const float* __restrict__ x, const float* __restrict__ w,
    const float* __restrict__ b, float* __restrict__ out)
{
    const int row = blockIdx.x;
    const int tid = threadIdx.x;
    const float* xr = x + (size_t)row * Cn;

    float4 f0 = ((const float4*)xr)[tid];
    float4 f1 = ((const float4*)xr)[tid + 256];
    float v[8] = {f0.x, f0.y, f0.z, f0.w, f1.x, f1.y, f1.z, f1.w};

    float s = 0.f, s2 = 0.f;
#pragma unroll
    for (int i = 0; i < 8; i++) { s += v[i]; s2 += v[i] * v[i]; }

#pragma unroll
    for (int o = 16; o > 0; o >>= 1) {
        s  += __shfl_xor_sync(0xFFFFFFFFu, s,  o);
        s2 += __shfl_xor_sync(0xFFFFFFFFu, s2, o);
    }
    __shared__ float sh[16];
    const int wid = tid >> 5, lane = tid & 31;
    if (lane == 0) { sh[wid] = s; sh[wid + 8] = s2; }
    __syncthreads();
    if (tid < 32) {
        float a  = (tid < 8) ? sh[tid]     : 0.f;
        float a2 = (tid < 8) ? sh[tid + 8] : 0.f;
#pragma unroll
        for (int o = 4; o > 0; o >>= 1) {
            a  += __shfl_xor_sync(0xFFFFFFFFu, a,  o);
            a2 += __shfl_xor_sync(0xFFFFFFFFu, a2, o);
        }
        if (tid == 0) { sh[0] = a; sh[1] = a2; }
    }
    __syncthreads();

    const float mu  = sh[0] * (1.f / Cn);
    const float var = sh[1] * (1.f / Cn) - mu * mu;
    const float inv = rsqrtf(var + 1e-5f);

    float* orow = out + (size_t)row * Cn;
    const int c0 = tid * 4, c1 = (tid + 256) * 4;
    float4 o0, o1;
    o0.x = (v[0] - mu) * inv * w[c0 + 0] + b[c0 + 0];
    o0.y = (v[1] - mu) * inv * w[c0 + 1] + b[c0 + 1];
    o0.z = (v[2] - mu) * inv * w[c0 + 2] + b[c0 + 2];
    o0.w = (v[3] - mu) * inv * w[c0 + 3] + b[c0 + 3];
    o1.x = (v[4] - mu) * inv * w[c1 + 0] + b[c1 + 0];
    o1.y = (v[5] - mu) * inv * w[c1 + 1] + b[c1 + 1];
    o1.z = (v[6] - mu) * inv * w[c1 + 2] + b[c1 + 2];
    o1.w = (v[7] - mu) * inv * w[c1 + 3] + b[c1 + 3];
    ((float4*)orow)[tid]       = o0;
    ((float4*)orow)[tid + 256] = o1;
}

// ---------------------------------------------------------------------------
// Time-shift mixes: xk/xv/xr = xn*m + shift(xn)*(1-m). Shift is per-batch
// (t==0 row mixes with zeros).
// ---------------------------------------------------------------------------
__device__ __forceinline__ float4 lerp4(float4 cur, float4 prev, float4 m)
{
    float4 r;
    r.x = cur.x * m.x + prev.x * (1.f - m.x);
    r.y = cur.y * m.y + prev.y * (1.f - m.y);
    r.z = cur.z * m.z + prev.z * (1.f - m.z);
    r.w = cur.w * m.w + prev.w * (1.f - m.w);
    return r;
}

__global__ __launch_bounds__(256) void mix3_kernel(
    const float* __restrict__ xn,
    const float* __restrict__ tk, const float* __restrict__ tv,
    const float* __restrict__ tr,
    float* __restrict__ xk, float* __restrict__ xv, float* __restrict__ xr)
{
    const size_t i4 = (size_t)blockIdx.x * blockDim.x + threadIdx.x;
    const size_t idx = i4 * 4;
    const int c = (int)(idx % Cn);
    const int t = (int)((idx / Cn) % Tn);
    float4 cur = *(const float4*)(xn + idx);
    float4 prev = make_float4(0.f, 0.f, 0.f, 0.f);
    if (t > 0) prev = *(const float4*)(xn + idx - Cn);
    float4 mk = *(const float4*)(tk + c);
    float4 mv = *(const float4*)(tv + c);
    float4 mr = *(const float4*)(tr + c);
    *(float4*)(xk + idx) = lerp4(cur, prev, mk);
    *(float4*)(xv + idx) = lerp4(cur, prev, mv);
    *(float4*)(xr + idx) = lerp4(cur, prev, mr);
}

__global__ __launch_bounds__(256) void mix2_kernel(
    const float* __restrict__ xn,
    const float* __restrict__ tk, const float* __restrict__ tr,
    float* __restrict__ ck, float* __restrict__ cr)
{
    const size_t i4 = (size_t)blockIdx.x * blockDim.x + threadIdx.x;
    const size_t idx = i4 * 4;
    const int c = (int)(idx % Cn);
    const int t = (int)((idx / Cn) % Tn);
    float4 cur = *(const float4*)(xn + idx);
    float4 prev = make_float4(0.f, 0.f, 0.f, 0.f);
    if (t > 0) prev = *(const float4*)(xn + idx - Cn);
    float4 mk = *(const float4*)(tk + c);
    float4 mr = *(const float4*)(tr + c);
    *(float4*)(ck + idx) = lerp4(cur, prev, mk);
    *(float4*)(cr + idx) = lerp4(cur, prev, mr);
}

// ---------------------------------------------------------------------------
// NT GEMM: C[M,N] = A[M,K] @ W[N,K]^T  (both operands K-contiguous, fp32)
// 128x128 tile, BK=16, 256 threads, 8x8 per thread.
// EPI: 0 = plain, 1 = +res0, 2 = relu(acc)^2, 3 = res0 + sigmoid(acc)*res1
// ---------------------------------------------------------------------------
template <int EPI>
__global__ __launch_bounds__(256) void gemm_nt(
    const float* __restrict__ A, const float* __restrict__ Bm,
    float* __restrict__ Cm, int N, int K,
    const float* __restrict__ res0, const float* __restrict__ res1)
{
    __shared__ float As[16][132];
    __shared__ float Bs[16][132];

    const int bx = blockIdx.x, by = blockIdx.y;
    const int tid = threadIdx.x;
    const int tx = tid & 15, ty = tid >> 4;
    const float* Ab = A  + (size_t)by * 128 * K;
    const float* Bb = Bm + (size_t)bx * 128 * K;
    const int lrow = tid >> 2;
    const int lk = (tid & 3) * 4;

    float acc[8][8];
#pragma unroll
    for (int i = 0; i < 8; i++)
#pragma unroll
        for (int j = 0; j < 8; j++) acc[i][j] = 0.f;

    for (int k0 = 0; k0 < K; k0 += 16) {
#pragma unroll
        for (int r = 0; r < 2; r++) {
            const int row = lrow + r * 64;
            float4 a = *(const float4*)(Ab + (size_t)row * K + k0 + lk);
            As[lk + 0][row] = a.x; As[lk + 1][row] = a.y;
            As[lk + 2][row] = a.z; As[lk + 3][row] = a.w;
            float4 b = *(const float4*)(Bb + (size_t)row * K + k0 + lk);
            Bs[lk + 0][row] = b.x; Bs[lk + 1][row] = b.y;
            Bs[lk + 2][row] = b.z; Bs[lk + 3][row] = b.w;
        }
        __syncthreads();
#pragma unroll
        for (int kk = 0; kk < 16; kk++) {
            float4 a0 = *(const float4*)&As[kk][ty * 8];
            float4 a1 = *(const float4*)&As[kk][ty * 8 + 4];
            float4 b0 = *(const float4*)&Bs[kk][tx * 8];
            float4 b1 = *(const float4*)&Bs[kk][tx * 8 + 4];
            float av[8] = {a0.x, a0.y, a0.z, a0.w, a1.x, a1.y, a1.z, a1.w};
            float bv[8] = {b0.x, b0.y, b0.z, b0.w, b1.x, b1.y, b1.z, b1.w};
#pragma unroll
            for (int i = 0; i < 8; i++)
#pragma unroll
                for (int j = 0; j < 8; j++) acc[i][j] += av[i] * bv[j];
        }
        __syncthreads();
    }

    const size_t row0 = (size_t)by * 128 + ty * 8;
    const int col0 = bx * 128 + tx * 8;
#pragma unroll
    for (int i = 0; i < 8; i++) {
        const size_t off = (row0 + i) * (size_t)N + col0;
#pragma unroll
        for (int jj = 0; jj < 8; jj += 4) {
            float4 v;
            v.x = acc[i][jj + 0]; v.y = acc[i][jj + 1];
            v.z = acc[i][jj + 2]; v.w = acc[i][jj + 3];
            if (EPI == 1) {
                float4 r = *(const float4*)(res0 + off + jj);
                v.x += r.x; v.y += r.y; v.z += r.z; v.w += r.w;
            } else if (EPI == 2) {
                v.x = fmaxf(v.x, 0.f); v.x *= v.x;
                v.y = fmaxf(v.y, 0.f); v.y *= v.y;
                v.z = fmaxf(v.z, 0.f); v.z *= v.z;
                v.w = fmaxf(v.w, 0.f); v.w *= v.w;
            } else if (EPI == 3) {
                float4 r0 = *(const float4*)(res0 + off + jj);
                float4 r1 = *(const float4*)(res1 + off + jj);
                v.x = r0.x + r1.x / (1.f + __expf(-v.x));
                v.y = r0.y + r1.y / (1.f + __expf(-v.y));
                v.z = r0.z + r1.z / (1.f + __expf(-v.z));
                v.w = r0.w + r1.w / (1.f + __expf(-v.w));
            }
            *(float4*)(Cm + off + jj) = v;
        }
    }
}

// ---------------------------------------------------------------------------
// WKV recurrence (numerically-stable RWKV-v4) with fused sigmoid(r) gate.
// One thread per (batch, channel) lane: 16384 lanes, T=2048 sequential steps.
// ---------------------------------------------------------------------------
__global__ __launch_bounds__(128) void wkv_gate_kernel(
    const float* __restrict__ k, const float* __restrict__ v,
    const float* __restrict__ r,
    const float* __restrict__ w_decay, const float* __restrict__ u_first,
    float* __restrict__ out)
{
    const int idx = blockIdx.x * blockDim.x + threadIdx.x;  // 0 .. B*C-1
    const int c = idx % Cn;
    const int b = idx / Cn;
    const float w = -expf(w_decay[c]);
    const float u = u_first[c];

    float aa = 0.f, bb = 0.f, pp = -1e38f;
    size_t off = (size_t)b * Tn * Cn + c;
    for (int t = 0; t < Tn; t++, off += Cn) {
        const float kt = k[off];
        const float vt = v[off];
        const float rr = r[off];

        const float ww = u + kt;
        const float p  = fmaxf(pp, ww);
        const float e1 = __expf(pp - p);
        const float e2 = __expf(ww - p);
        const float y  = (e1 * aa + e2 * vt) / (e1 * bb + e2);
        out[off] = y / (1.f + __expf(-rr));   // sigmoid(r) * y

        const float ww2 = pp + w;
        const float p2  = fmaxf(ww2, kt);
        const float e1b = __expf(ww2 - p2);
        const float e2b = __expf(kt - p2);
        aa = e1b * aa + e2b * vt;
        bb = e1b * bb + e2b;
        pp = p2;
    }
}

// ---------------------------------------------------------------------------
// Launch
// ---------------------------------------------------------------------------
extern "C" void kernel_launch(void* const* d_in, const int* in_sizes, int n_in,
                              void* d_out, int out_size)
{
    (void)in_sizes; (void)n_in; (void)out_size;
    const float* x    = (const float*)d_in[0];
    const float* ln1w = (const float*)d_in[1];
    const float* ln1b = (const float*)d_in[2];
    const float* ln2w = (const float*)d_in[3];
    const float* ln2b = (const float*)d_in[4];
    const float* tdec = (const float*)d_in[5];
    const float* tfir = (const float*)d_in[6];
    const float* tmk  = (const float*)d_in[7];
    const float* tmv  = (const float*)d_in[8];
    const float* tmr  = (const float*)d_in[9];
    const float* Wk   = (const float*)d_in[10];
    const float* Wv   = (const float*)d_in[11];
    const float* Wr   = (const float*)d_in[12];
    const float* Wo   = (const float*)d_in[13];
    const float* cmk  = (const float*)d_in[14];
    const float* cmr  = (const float*)d_in[15];
    const float* Wck  = (const float*)d_in[16];
    const float* Wcv  = (const float*)d_in[17];
    const float* Wcr  = (const float*)d_in[18];
    float* out = (float*)d_out;

    float *b0, *b1, *b2, *b3, *b4, *b5, *b6, *hb;
    cudaGetSymbolAddress((void**)&b0, g_b0);
    cudaGetSymbolAddress((void**)&b1, g_b1);
    cudaGetSymbolAddress((void**)&b2, g_b2);
    cudaGetSymbolAddress((void**)&b3, g_b3);
    cudaGetSymbolAddress((void**)&b4, g_b4);
    cudaGetSymbolAddress((void**)&b5, g_b5);
    cudaGetSymbolAddress((void**)&b6, g_b6);
    cudaGetSymbolAddress((void**)&hb, g_h);

    const int mixBlocks = (int)(((size_t)Mn * Cn / 4) / 256);
    const dim3 gC(Cn / 128, Mn / 128);   // N=2048 GEMMs
    const dim3 gH(Hn / 128, Mn / 128);   // N=8192 GEMM

    // --- time-mix attention ---
    ln_kernel<<<Mn, 256>>>(x, ln1w, ln1b, b0);                      // xn
    mix3_kernel<<<mixBlocks, 256>>>(b0, tmk, tmv, tmr, b1, b2, b3); // xk,xv,xr
    gemm_nt<0><<<gC, 256>>>(b1, Wk, b4, Cn, Cn, nullptr, nullptr);  // k
    gemm_nt<0><<<gC, 256>>>(b2, Wv, b5, Cn, Cn, nullptr, nullptr);  // v
    gemm_nt<0><<<gC, 256>>>(b3, Wr, b6, Cn, Cn, nullptr, nullptr);  // r (pre-sigmoid)
    wkv_gate_kernel<<<(Bn * Cn) / 128, 128>>>(b4, b5, b6, tdec, tfir, b1); // g = sig(r)*wkv
    gemm_nt<1><<<gC, 256>>>(b1, Wo, b2, Cn, Cn, x, nullptr);        // x1 = x + g@Wo^T

    // --- channel mix ---
    ln_kernel<<<Mn, 256>>>(b2, ln2w, ln2b, b0);                     // xn2
    mix2_kernel<<<mixBlocks, 256>>>(b0, cmk, cmr, b3, b4);          // ck, cr
    gemm_nt<2><<<gH, 256>>>(b3, Wck, hb, Hn, Cn, nullptr, nullptr); // h = relu(ck@Wck^T)^2
    gemm_nt<0><<<gC, 256>>>(hb, Wcv, b5, Cn, Hn, nullptr, nullptr); // kv = h@Wcv^T
    gemm_nt<3><<<gC, 256>>>(b4, Wcr, out, Cn, Cn, b2, b5);          // out = x1 + sig(cr@Wcr^T)*kv
}

// round 3
// speedup vs baseline: 3.6413x; 3.6413x over previous
#include <cuda_runtime.h>
#include <cuda_bf16.h>
#include <math.h>
#include <stdint.h>

#define Bn 8
#define Tn 2048
#define Cn 2048
#define Hn 8192
#define Mn (Bn * Tn)   // 16384

typedef __nv_bfloat16 bf16;

// ---------------------------------------------------------------------------
// Scratch (device globals — allocation-free per harness rules)
// ---------------------------------------------------------------------------
__device__ float g_xn[(size_t)Mn * Cn];
__device__ float g_k [(size_t)Mn * Cn];
__device__ float g_v [(size_t)Mn * Cn];
__device__ float g_r [(size_t)Mn * Cn];
__device__ float g_x1[(size_t)Mn * Cn];
__device__ float g_kv[(size_t)Mn * Cn];
__device__ bf16  g_p0h[(size_t)Mn * Cn], g_p0l[(size_t)Mn * Cn];
__device__ bf16  g_p1h[(size_t)Mn * Cn], g_p1l[(size_t)Mn * Cn];
__device__ bf16  g_p2h[(size_t)Mn * Cn], g_p2l[(size_t)Mn * Cn];
__device__ bf16  g_hh [(size_t)Mn * Hn], g_hl [(size_t)Mn * Hn];
__device__ bf16  g_wh [(size_t)Hn * Cn], g_wl [(size_t)Hn * Cn];

// ---------------------------------------------------------------------------
// PTX helpers (baseline sm_103 — NO "a"-suffix features)
// ---------------------------------------------------------------------------
__device__ __forceinline__ uint32_t smem_u32(const void* p) {
    uint32_t a;
    asm("{ .reg .u64 t; cvta.to.shared.u64 t, %1; cvt.u32.u64 %0, t; }"
        : "=r"(a) : "l"(p));
    return a;
}

__device__ __forceinline__ void cp16(uint32_t s, const void* g) {
    asm volatile("cp.async.cg.shared.global [%0], [%1], 16;" :: "r"(s), "l"(g));
}
#define CP_COMMIT() asm volatile("cp.async.commit_group;" ::: "memory")

__device__ __forceinline__ void ldsm4(uint32_t& r0, uint32_t& r1,
                                      uint32_t& r2, uint32_t& r3, uint32_t a) {
    asm volatile("ldmatrix.sync.aligned.m8n8.x4.shared.b16 {%0,%1,%2,%3}, [%4];"
                 : "=r"(r0), "=r"(r1), "=r"(r2), "=r"(r3) : "r"(a));
}

__device__ __forceinline__ void mma16816(float* d, const uint32_t* a,
                                         const uint32_t* b) {
    asm volatile(
        "mma.sync.aligned.m16n8k16.row.col.f32.bf16.bf16.f32 "
        "{%0,%1,%2,%3}, {%4,%5,%6,%7}, {%8,%9}, {%0,%1,%2,%3};"
        : "+f"(d[0]), "+f"(d[1]), "+f"(d[2]), "+f"(d[3])
        : "r"(a[0]), "r"(a[1]), "r"(a[2]), "r"(a[3]), "r"(b[0]), "r"(b[1]));
}

// ---------------------------------------------------------------------------
// bf16 hi/lo split helpers
// ---------------------------------------------------------------------------
__device__ __forceinline__ uint32_t pack2f(float x, float y) {
    __nv_bfloat162 t = __floats2bfloat162_rn(x, y);
    return *reinterpret_cast<uint32_t*>(&t);
}

__device__ __forceinline__ void store_split4(float4 v, bf16* ph, bf16* pl, size_t idx) {
    float hx = __bfloat162float(__float2bfloat16(v.x));
    float hy = __bfloat162float(__float2bfloat16(v.y));
    float hz = __bfloat162float(__float2bfloat16(v.z));
    float hw = __bfloat162float(__float2bfloat16(v.w));
    uint2 H, L;
    H.x = pack2f(v.x, v.y); H.y = pack2f(v.z, v.w);
    L.x = pack2f(v.x - hx, v.y - hy); L.y = pack2f(v.z - hz, v.w - hw);
    *(uint2*)(ph + idx) = H;
    *(uint2*)(pl + idx) = L;
}

__device__ __forceinline__ void store_split2(float x, float y, bf16* ph, bf16* pl,
                                             size_t idx) {
    float hx = __bfloat162float(__float2bfloat16(x));
    float hy = __bfloat162float(__float2bfloat16(y));
    *(uint32_t*)(ph + idx) = pack2f(x, y);
    *(uint32_t*)(pl + idx) = pack2f(x - hx, y - hy);
}

// ---------------------------------------------------------------------------
// LayerNorm: one block per row
// ---------------------------------------------------------------------------
__global__ __launch_bounds__(256) void ln_kernel(
    const float* __restrict__ x, const float* __restrict__ w,
    const float* __restrict__ b, float* __restrict__ out)
{
    const int row = blockIdx.x;
    const int tid = threadIdx.x;
    const float* xr = x + (size_t)row * Cn;

    float4 f0 = ((const float4*)xr)[tid];
    float4 f1 = ((const float4*)xr)[tid + 256];
    float v[8] = {f0.x, f0.y, f0.z, f0.w, f1.x, f1.y, f1.z, f1.w};

    float s = 0.f, s2 = 0.f;
#pragma unroll
    for (int i = 0; i < 8; i++) { s += v[i]; s2 += v[i] * v[i]; }
#pragma unroll
    for (int o = 16; o > 0; o >>= 1) {
        s  += __shfl_xor_sync(0xFFFFFFFFu, s,  o);
        s2 += __shfl_xor_sync(0xFFFFFFFFu, s2, o);
    }
    __shared__ float sh[16];
    const int wid = tid >> 5, lane = tid & 31;
    if (lane == 0) { sh[wid] = s; sh[wid + 8] = s2; }
    __syncthreads();
    if (tid < 32) {
        float a  = (tid < 8) ? sh[tid]     : 0.f;
        float a2 = (tid < 8) ? sh[tid + 8] : 0.f;
#pragma unroll
        for (int o = 4; o > 0; o >>= 1) {
            a  += __shfl_xor_sync(0xFFFFFFFFu, a,  o);
            a2 += __shfl_xor_sync(0xFFFFFFFFu, a2, o);
        }
        if (tid == 0) { sh[0] = a; sh[1] = a2; }
    }
    __syncthreads();

    const float mu  = sh[0] * (1.f / Cn);
    const float var = sh[1] * (1.f / Cn) - mu * mu;
    const float inv = rsqrtf(var + 1e-5f);

    float* orow = out + (size_t)row * Cn;
    const int c0 = tid * 4, c1 = (tid + 256) * 4;
    float4 o0, o1;
    o0.x = (v[0] - mu) * inv * w[c0 + 0] + b[c0 + 0];
    o0.y = (v[1] - mu) * inv * w[c0 + 1] + b[c0 + 1];
    o0.z = (v[2] - mu) * inv * w[c0 + 2] + b[c0 + 2];
    o0.w = (v[3] - mu) * inv * w[c0 + 3] + b[c0 + 3];
    o1.x = (v[4] - mu) * inv * w[c1 + 0] + b[c1 + 0];
    o1.y = (v[5] - mu) * inv * w[c1 + 1] + b[c1 + 1];
    o1.z = (v[6] - mu) * inv * w[c1 + 2] + b[c1 + 2];
    o1.w = (v[7] - mu) * inv * w[c1 + 3] + b[c1 + 3];
    ((float4*)orow)[tid]       = o0;
    ((float4*)orow)[tid + 256] = o1;
}

// ---------------------------------------------------------------------------
// Time-shift mixes → bf16 hi/lo splits
// ---------------------------------------------------------------------------
__device__ __forceinline__ float4 lerp4(float4 cur, float4 prev, float4 m) {
    float4 r;
    r.x = cur.x * m.x + prev.x * (1.f - m.x);
    r.y = cur.y * m.y + prev.y * (1.f - m.y);
    r.z = cur.z * m.z + prev.z * (1.f - m.z);
    r.w = cur.w * m.w + prev.w * (1.f - m.w);
    return r;
}

__global__ __launch_bounds__(256) void mix3_split(
    const float* __restrict__ xn,
    const float* __restrict__ tk, const float* __restrict__ tv,
    const float* __restrict__ tr,
    bf16* kh, bf16* kl, bf16* vh, bf16* vl, bf16* rh, bf16* rl)
{
    const size_t i4 = (size_t)blockIdx.x * blockDim.x + threadIdx.x;
    const size_t idx = i4 * 4;
    const int c = (int)(idx % Cn);
    const int t = (int)((idx / Cn) % Tn);
    float4 cur = *(const float4*)(xn + idx);
    float4 prev = make_float4(0.f, 0.f, 0.f, 0.f);
    if (t > 0) prev = *(const float4*)(xn + idx - Cn);
    store_split4(lerp4(cur, prev, *(const float4*)(tk + c)), kh, kl, idx);
    store_split4(lerp4(cur, prev, *(const float4*)(tv + c)), vh, vl, idx);
    store_split4(lerp4(cur, prev, *(const float4*)(tr + c)), rh, rl, idx);
}

__global__ __launch_bounds__(256) void mix2_split(
    const float* __restrict__ xn,
    const float* __restrict__ tk, const float* __restrict__ tr,
    bf16* kh, bf16* kl, bf16* rh, bf16* rl)
{
    const size_t i4 = (size_t)blockIdx.x * blockDim.x + threadIdx.x;
    const size_t idx = i4 * 4;
    const int c = (int)(idx % Cn);
    const int t = (int)((idx / Cn) % Tn);
    float4 cur = *(const float4*)(xn + idx);
    float4 prev = make_float4(0.f, 0.f, 0.f, 0.f);
    if (t > 0) prev = *(const float4*)(xn + idx - Cn);
    store_split4(lerp4(cur, prev, *(const float4*)(tk + c)), kh, kl, idx);
    store_split4(lerp4(cur, prev, *(const float4*)(tr + c)), rh, rl, idx);
}

// Weight split: fp32 -> bf16 hi/lo
__global__ __launch_bounds__(256) void split_w(
    const float* __restrict__ w, bf16* __restrict__ hi, bf16* __restrict__ lo)
{
    const size_t i4 = (size_t)blockIdx.x * blockDim.x + threadIdx.x;
    const size_t idx = i4 * 4;
    float4 v = *(const float4*)(w + idx);
    store_split4(v, hi, lo, idx);
}

// ---------------------------------------------------------------------------
// WKV recurrence + sigmoid(r) gate → bf16 hi/lo split output
// ---------------------------------------------------------------------------
__global__ __launch_bounds__(128) void wkv_gate_kernel(
    const float* __restrict__ k, const float* __restrict__ v,
    const float* __restrict__ r,
    const float* __restrict__ w_decay, const float* __restrict__ u_first,
    bf16* __restrict__ gh, bf16* __restrict__ gl)
{
    const int idx = blockIdx.x * blockDim.x + threadIdx.x;
    const int c = idx % Cn;
    const int b = idx / Cn;
    const float w = -expf(w_decay[c]);
    const float u = u_first[c];

    float aa = 0.f, bb = 0.f, pp = -1e38f;
    size_t off = (size_t)b * Tn * Cn + c;
    for (int t = 0; t < Tn; t++, off += Cn) {
        const float kt = k[off];
        const float vt = v[off];
        const float rr = r[off];

        const float ww = u + kt;
        const float p  = fmaxf(pp, ww);
        const float e1 = __expf(pp - p);
        const float e2 = __expf(ww - p);
        const float y  = (e1 * aa + e2 * vt) / (e1 * bb + e2);
        const float gv = y / (1.f + __expf(-rr));
        bf16 h = __float2bfloat16(gv);
        gh[off] = h;
        gl[off] = __float2bfloat16(gv - __bfloat162float(h));

        const float ww2 = pp + w;
        const float p2  = fmaxf(ww2, kt);
        const float e1b = __expf(ww2 - p2);
        const float e2b = __expf(kt - p2);
        aa = e1b * aa + e2b * vt;
        bb = e1b * bb + e2b;
        pp = p2;
    }
}

// ---------------------------------------------------------------------------
// HMMA split-bf16 GEMM:  C[M,N] = A[M,K] @ B[N,K]^T, 3-product bf16
// CTA 128x128, BK=32, 8 warps (2x4), warp tile 64x32, mma.sync.m16n8k16.
// 4-stage cp.async pipeline; smem rows padded to 80B (conflict-free ldmatrix).
// EPI: 0 plain fp32; 1 +res0; 2 relu^2 -> bf16 hi/lo; 3 res0 + sigmoid*res1
// ---------------------------------------------------------------------------
static constexpr int ROWB    = 80;            // padded row bytes (32 bf16 = 64B + 16B pad)
static constexpr int TILE_B  = 128 * ROWB;    // 10240 B per tile
static constexpr int STAGE   = 4 * TILE_B;    // Ah, Al, Bh, Bl
static constexpr int NSTAGE  = 4;
static constexpr int SMEM_DYN = NSTAGE * STAGE;   // 163840 B

__device__ __forceinline__ void load_stage(
    uint32_t st, const bf16* Ah, const bf16* Al, const bf16* Bh, const bf16* Bl,
    int m0, int n0, int k0, int K, int tid)
{
#pragma unroll
    for (int q = 0; q < 2; q++) {
        const int idx = tid + q * 256;        // 0..511
        const int row = idx >> 2, kc = idx & 3;
        const uint32_t so = (uint32_t)(row * ROWB + kc * 16);
        const size_t ga = (size_t)(m0 + row) * K + k0 + kc * 8;
        cp16(st + so, Ah + ga);
        cp16(st + TILE_B + so, Al + ga);
        const size_t gb = (size_t)(n0 + row) * K + k0 + kc * 8;
        cp16(st + 2 * TILE_B + so, Bh + gb);
        cp16(st + 3 * TILE_B + so, Bl + gb);
    }
}

template <int EPI>
__global__ __launch_bounds__(256, 1) void gemm3bf(
    const bf16* __restrict__ Ah, const bf16* __restrict__ Al,
    const bf16* __restrict__ Bh, const bf16* __restrict__ Bl,
    float* __restrict__ Cm, bf16* __restrict__ Oh, bf16* __restrict__ Ol,
    int N, int K,
    const float* __restrict__ res0, const float* __restrict__ res1)
{
    extern __shared__ char dsm[];
    const uint32_t sb = smem_u32(dsm);
    const int tid = threadIdx.x, wid = tid >> 5, lane = tid & 31;
    const int m0 = blockIdx.y * 128, n0 = blockIdx.x * 128;
    const int wm = wid >> 2, wn = wid & 3;

    float acc[4][4][4];
#pragma unroll
    for (int a = 0; a < 4; a++)
#pragma unroll
        for (int b = 0; b < 4; b++)
#pragma unroll
            for (int c = 0; c < 4; c++) acc[a][b][c] = 0.f;

    const int nk = K >> 5;

    load_stage(sb + 0 * STAGE, Ah, Al, Bh, Bl, m0, n0, 0,  K, tid); CP_COMMIT();
    load_stage(sb + 1 * STAGE, Ah, Al, Bh, Bl, m0, n0, 32, K, tid); CP_COMMIT();
    load_stage(sb + 2 * STAGE, Ah, Al, Bh, Bl, m0, n0, 64, K, tid); CP_COMMIT();

    // per-thread ldmatrix row/col components
    const int a_row  = wm * 64 + (lane & 15);
    const int a_koff = (lane & 16) ? 8 : 0;
    const int b_row  = wn * 32 + (lane & 7) + ((lane & 16) ? 8 : 0);
    const int b_koff = (lane & 8) ? 8 : 0;

    for (int i = 0; i < nk; i++) {
        asm volatile("cp.async.wait_group 2;" ::: "memory");
        __syncthreads();
        if (i + 3 < nk)
            load_stage(sb + ((i + 3) & 3) * STAGE, Ah, Al, Bh, Bl,
                       m0, n0, (i + 3) * 32, K, tid);
        CP_COMMIT();

        const uint32_t st = sb + (i & 3) * STAGE;
#pragma unroll
        for (int k16 = 0; k16 < 2; k16++) {
            uint32_t ah[4][4], al[4][4];
            const uint32_t acol = (uint32_t)(k16 * 16 + a_koff) * 2;
#pragma unroll
            for (int mt = 0; mt < 4; mt++) {
                const uint32_t ad = st + (uint32_t)(a_row + mt * 16) * ROWB + acol;
                ldsm4(ah[mt][0], ah[mt][1], ah[mt][2], ah[mt][3], ad);
                ldsm4(al[mt][0], al[mt][1], al[mt][2], al[mt][3], ad + TILE_B);
            }
            uint32_t bh[4][2], bl[4][2];
            const uint32_t bcol = (uint32_t)(k16 * 16 + b_koff) * 2;
#pragma unroll
            for (int p = 0; p < 2; p++) {
                const uint32_t bd = st + 2 * TILE_B +
                                    (uint32_t)(b_row + p * 16) * ROWB + bcol;
                ldsm4(bh[2*p][0], bh[2*p][1], bh[2*p+1][0], bh[2*p+1][1], bd);
                ldsm4(bl[2*p][0], bl[2*p][1], bl[2*p+1][0], bl[2*p+1][1], bd + TILE_B);
            }
#pragma unroll
            for (int mt = 0; mt < 4; mt++)
#pragma unroll
                for (int nt = 0; nt < 4; nt++) {
                    mma16816(acc[mt][nt], ah[mt], bh[nt]);
                    mma16816(acc[mt][nt], ah[mt], bl[nt]);
                    mma16816(acc[mt][nt], al[mt], bh[nt]);
                }
        }
    }
    asm volatile("cp.async.wait_group 0;" ::: "memory");

    // Epilogue: registers -> global
    const int row_base = m0 + wm * 64 + (lane >> 2);
    const int col_base = n0 + wn * 32 + (lane & 3) * 2;
#pragma unroll
    for (int mt = 0; mt < 4; mt++) {
#pragma unroll
        for (int h = 0; h < 2; h++) {
            const int row = row_base + mt * 16 + h * 8;
#pragma unroll
            for (int nt = 0; nt < 4; nt++) {
                float vx = acc[mt][nt][2 * h + 0];
                float vy = acc[mt][nt][2 * h + 1];
                const size_t off = (size_t)row * N + col_base + nt * 8;
                if (EPI == 0) {
                    *(float2*)(Cm + off) = make_float2(vx, vy);
                } else if (EPI == 1) {
                    float2 r = *(const float2*)(res0 + off);
                    *(float2*)(Cm + off) = make_float2(vx + r.x, vy + r.y);
                } else if (EPI == 2) {
                    vx = fmaxf(vx, 0.f); vx *= vx;
                    vy = fmaxf(vy, 0.f); vy *= vy;
                    store_split2(vx, vy, Oh, Ol, off);
                } else {
                    float2 r0 = *(const float2*)(res0 + off);
                    float2 r1 = *(const float2*)(res1 + off);
                    vx = r0.x + r1.x / (1.f + __expf(-vx));
                    vy = r0.y + r1.y / (1.f + __expf(-vy));
                    *(float2*)(Cm + off) = make_float2(vx, vy);
                }
            }
        }
    }
}

// ---------------------------------------------------------------------------
// Launch
// ---------------------------------------------------------------------------
extern "C" void kernel_launch(void* const* d_in, const int* in_sizes, int n_in,
                              void* d_out, int out_size)
{
    (void)in_sizes; (void)n_in; (void)out_size;
    const float* x    = (const float*)d_in[0];
    const float* ln1w = (const float*)d_in[1];
    const float* ln1b = (const float*)d_in[2];
    const float* ln2w = (const float*)d_in[3];
    const float* ln2b = (const float*)d_in[4];
    const float* tdec = (const float*)d_in[5];
    const float* tfir = (const float*)d_in[6];
    const float* tmk  = (const float*)d_in[7];
    const float* tmv  = (const float*)d_in[8];
    const float* tmr  = (const float*)d_in[9];
    const float* Wk   = (const float*)d_in[10];
    const float* Wv   = (const float*)d_in[11];
    const float* Wr   = (const float*)d_in[12];
    const float* Wo   = (const float*)d_in[13];
    const float* cmk  = (const float*)d_in[14];
    const float* cmr  = (const float*)d_in[15];
    const float* Wck  = (const float*)d_in[16];
    const float* Wcv  = (const float*)d_in[17];
    const float* Wcr  = (const float*)d_in[18];
    float* out = (float*)d_out;

    float *xn, *kf, *vf, *rf, *x1, *kv;
    bf16 *p0h, *p0l, *p1h, *p1l, *p2h, *p2l, *hh, *hl, *wh, *wl;
    cudaGetSymbolAddress((void**)&xn, g_xn);
    cudaGetSymbolAddress((void**)&kf, g_k);
    cudaGetSymbolAddress((void**)&vf, g_v);
    cudaGetSymbolAddress((void**)&rf, g_r);
    cudaGetSymbolAddress((void**)&x1, g_x1);
    cudaGetSymbolAddress((void**)&kv, g_kv);
    cudaGetSymbolAddress((void**)&p0h, g_p0h);
    cudaGetSymbolAddress((void**)&p0l, g_p0l);
    cudaGetSymbolAddress((void**)&p1h, g_p1h);
    cudaGetSymbolAddress((void**)&p1l, g_p1l);
    cudaGetSymbolAddress((void**)&p2h, g_p2h);
    cudaGetSymbolAddress((void**)&p2l, g_p2l);
    cudaGetSymbolAddress((void**)&hh, g_hh);
    cudaGetSymbolAddress((void**)&hl, g_hl);
    cudaGetSymbolAddress((void**)&wh, g_wh);
    cudaGetSymbolAddress((void**)&wl, g_wl);

    cudaFuncSetAttribute(gemm3bf<0>, cudaFuncAttributeMaxDynamicSharedMemorySize, SMEM_DYN);
    cudaFuncSetAttribute(gemm3bf<1>, cudaFuncAttributeMaxDynamicSharedMemorySize, SMEM_DYN);
    cudaFuncSetAttribute(gemm3bf<2>, cudaFuncAttributeMaxDynamicSharedMemorySize, SMEM_DYN);
    cudaFuncSetAttribute(gemm3bf<3>, cudaFuncAttributeMaxDynamicSharedMemorySize, SMEM_DYN);

    const int mixBlocks = (int)(((size_t)Mn * Cn / 4) / 256);
    const int wCC = (Cn * Cn / 4) / 256;
    const int wHC = (Hn * Cn / 4) / 256;
    const dim3 gC(Cn / 128, Mn / 128);   // (16, 128)
    const dim3 gH(Hn / 128, Mn / 128);   // (64, 128)

    // --- time-mix attention ---
    ln_kernel<<<Mn, 256>>>(x, ln1w, ln1b, xn);
    mix3_split<<<mixBlocks, 256>>>(xn, tmk, tmv, tmr, p0h, p0l, p1h, p1l, p2h, p2l);

    split_w<<<wCC, 256>>>(Wk, wh, wl);
    gemm3bf<0><<<gC, 256, SMEM_DYN>>>(p0h, p0l, wh, wl, kf, nullptr, nullptr, Cn, Cn, nullptr, nullptr);
    split_w<<<wCC, 256>>>(Wv, wh, wl);
    gemm3bf<0><<<gC, 256, SMEM_DYN>>>(p1h, p1l, wh, wl, vf, nullptr, nullptr, Cn, Cn, nullptr, nullptr);
    split_w<<<wCC, 256>>>(Wr, wh, wl);
    gemm3bf<0><<<gC, 256, SMEM_DYN>>>(p2h, p2l, wh, wl, rf, nullptr, nullptr, Cn, Cn, nullptr, nullptr);

    wkv_gate_kernel<<<(Bn * Cn) / 128, 128>>>(kf, vf, rf, tdec, tfir, p0h, p0l);

    split_w<<<wCC, 256>>>(Wo, wh, wl);
    gemm3bf<1><<<gC, 256, SMEM_DYN>>>(p0h, p0l, wh, wl, x1, nullptr, nullptr, Cn, Cn, x, nullptr);

    // --- channel mix ---
    ln_kernel<<<Mn, 256>>>(x1, ln2w, ln2b, xn);
    mix2_split<<<mixBlocks, 256>>>(xn, cmk, cmr, p1h, p1l, p2h, p2l);

    split_w<<<wHC, 256>>>(Wck, wh, wl);
    gemm3bf<2><<<gH, 256, SMEM_DYN>>>(p1h, p1l, wh, wl, nullptr, hh, hl, Hn, Cn, nullptr, nullptr);
    split_w<<<wHC, 256>>>(Wcv, wh, wl);
    gemm3bf<0><<<gC, 256, SMEM_DYN>>>(hh, hl, wh, wl, kv, nullptr, nullptr, Cn, Hn, nullptr, nullptr);
    split_w<<<wCC, 256>>>(Wcr, wh, wl);
    gemm3bf<3><<<gC, 256, SMEM_DYN>>>(p2h, p2l, wh, wl, out, nullptr, nullptr, Cn, Cn, x1, kv);
}

// round 4
// speedup vs baseline: 4.0852x; 1.1219x over previous
#include <cuda_runtime.h>
#include <cuda_bf16.h>
#include <math.h>
#include <stdint.h>

#define Bn 8
#define Tn 2048
#define Cn 2048
#define Hn 8192
#define Mn (Bn * Tn)   // 16384

typedef __nv_bfloat16 bf16;

// ---------------------------------------------------------------------------
// Scratch (device globals — allocation-free per harness rules)
// ---------------------------------------------------------------------------
__device__ float g_xn[(size_t)Mn * Cn];
__device__ float g_k [(size_t)Mn * Cn];
__device__ float g_v [(size_t)Mn * Cn];
__device__ float g_r [(size_t)Mn * Cn];
__device__ float g_x1[(size_t)Mn * Cn];
__device__ float g_kv[(size_t)Mn * Cn];
__device__ bf16  g_p0h[(size_t)Mn * Cn], g_p0l[(size_t)Mn * Cn];
__device__ bf16  g_p1h[(size_t)Mn * Cn], g_p1l[(size_t)Mn * Cn];
__device__ bf16  g_p2h[(size_t)Mn * Cn], g_p2l[(size_t)Mn * Cn];
__device__ bf16  g_hh [(size_t)Mn * Hn], g_hl [(size_t)Mn * Hn];
__device__ bf16  g_wh [(size_t)Hn * Cn], g_wl [(size_t)Hn * Cn];

// ---------------------------------------------------------------------------
// PTX helpers (baseline sm_103 — NO "a"-suffix features)
// ---------------------------------------------------------------------------
__device__ __forceinline__ uint32_t smem_u32(const void* p) {
    uint32_t a;
    asm("{ .reg .u64 t; cvta.to.shared.u64 t, %1; cvt.u32.u64 %0, t; }"
        : "=r"(a) : "l"(p));
    return a;
}

__device__ __forceinline__ void cp16(uint32_t s, const void* g) {
    asm volatile("cp.async.cg.shared.global [%0], [%1], 16;" :: "r"(s), "l"(g));
}
#define CP_COMMIT() asm volatile("cp.async.commit_group;" ::: "memory")

__device__ __forceinline__ void ldsm4(uint32_t& r0, uint32_t& r1,
                                      uint32_t& r2, uint32_t& r3, uint32_t a) {
    asm volatile("ldmatrix.sync.aligned.m8n8.x4.shared.b16 {%0,%1,%2,%3}, [%4];"
                 : "=r"(r0), "=r"(r1), "=r"(r2), "=r"(r3) : "r"(a));
}

__device__ __forceinline__ void mma16816(float* d, const uint32_t* a,
                                         const uint32_t* b) {
    asm volatile(
        "mma.sync.aligned.m16n8k16.row.col.f32.bf16.bf16.f32 "
        "{%0,%1,%2,%3}, {%4,%5,%6,%7}, {%8,%9}, {%0,%1,%2,%3};"
        : "+f"(d[0]), "+f"(d[1]), "+f"(d[2]), "+f"(d[3])
        : "r"(a[0]), "r"(a[1]), "r"(a[2]), "r"(a[3]), "r"(b[0]), "r"(b[1]));
}

// ---------------------------------------------------------------------------
// bf16 hi/lo split helpers
// ---------------------------------------------------------------------------
__device__ __forceinline__ uint32_t pack2f(float x, float y) {
    __nv_bfloat162 t = __floats2bfloat162_rn(x, y);
    return *reinterpret_cast<uint32_t*>(&t);
}

__device__ __forceinline__ void store_split4(float4 v, bf16* ph, bf16* pl, size_t idx) {
    float hx = __bfloat162float(__float2bfloat16(v.x));
    float hy = __bfloat162float(__float2bfloat16(v.y));
    float hz = __bfloat162float(__float2bfloat16(v.z));
    float hw = __bfloat162float(__float2bfloat16(v.w));
    uint2 H, L;
    H.x = pack2f(v.x, v.y); H.y = pack2f(v.z, v.w);
    L.x = pack2f(v.x - hx, v.y - hy); L.y = pack2f(v.z - hz, v.w - hw);
    *(uint2*)(ph + idx) = H;
    *(uint2*)(pl + idx) = L;
}

__device__ __forceinline__ void store_split2(float x, float y, bf16* ph, bf16* pl,
                                             size_t idx) {
    float hx = __bfloat162float(__float2bfloat16(x));
    float hy = __bfloat162float(__float2bfloat16(y));
    *(uint32_t*)(ph + idx) = pack2f(x, y);
    *(uint32_t*)(pl + idx) = pack2f(x - hx, y - hy);
}

// ---------------------------------------------------------------------------
// LayerNorm: one block per row
// ---------------------------------------------------------------------------
__global__ __launch_bounds__(256) void ln_kernel(
    const float* __restrict__ x, const float* __restrict__ w,
    const float* __restrict__ b, float* __restrict__ out)
{
    const int row = blockIdx.x;
    const int tid = threadIdx.x;
    const float* xr = x + (size_t)row * Cn;

    float4 f0 = ((const float4*)xr)[tid];
    float4 f1 = ((const float4*)xr)[tid + 256];
    float v[8] = {f0.x, f0.y, f0.z, f0.w, f1.x, f1.y, f1.z, f1.w};

    float s = 0.f, s2 = 0.f;
#pragma unroll
    for (int i = 0; i < 8; i++) { s += v[i]; s2 += v[i] * v[i]; }
#pragma unroll
    for (int o = 16; o > 0; o >>= 1) {
        s  += __shfl_xor_sync(0xFFFFFFFFu, s,  o);
        s2 += __shfl_xor_sync(0xFFFFFFFFu, s2, o);
    }
    __shared__ float sh[16];
    const int wid = tid >> 5, lane = tid & 31;
    if (lane == 0) { sh[wid] = s; sh[wid + 8] = s2; }
    __syncthreads();
    if (tid < 32) {
        float a  = (tid < 8) ? sh[tid]     : 0.f;
        float a2 = (tid < 8) ? sh[tid + 8] : 0.f;
#pragma unroll
        for (int o = 4; o > 0; o >>= 1) {
            a  += __shfl_xor_sync(0xFFFFFFFFu, a,  o);
            a2 += __shfl_xor_sync(0xFFFFFFFFu, a2, o);
        }
        if (tid == 0) { sh[0] = a; sh[1] = a2; }
    }
    __syncthreads();

    const float mu  = sh[0] * (1.f / Cn);
    const float var = sh[1] * (1.f / Cn) - mu * mu;
    const float inv = rsqrtf(var + 1e-5f);

    float* orow = out + (size_t)row * Cn;
    const int c0 = tid * 4, c1 = (tid + 256) * 4;
    float4 o0, o1;
    o0.x = (v[0] - mu) * inv * w[c0 + 0] + b[c0 + 0];
    o0.y = (v[1] - mu) * inv * w[c0 + 1] + b[c0 + 1];
    o0.z = (v[2] - mu) * inv * w[c0 + 2] + b[c0 + 2];
    o0.w = (v[3] - mu) * inv * w[c0 + 3] + b[c0 + 3];
    o1.x = (v[4] - mu) * inv * w[c1 + 0] + b[c1 + 0];
    o1.y = (v[5] - mu) * inv * w[c1 + 1] + b[c1 + 1];
    o1.z = (v[6] - mu) * inv * w[c1 + 2] + b[c1 + 2];
    o1.w = (v[7] - mu) * inv * w[c1 + 3] + b[c1 + 3];
    ((float4*)orow)[tid]       = o0;
    ((float4*)orow)[tid + 256] = o1;
}

// ---------------------------------------------------------------------------
// Time-shift mixes → bf16 hi/lo splits
// ---------------------------------------------------------------------------
__device__ __forceinline__ float4 lerp4(float4 cur, float4 prev, float4 m) {
    float4 r;
    r.x = cur.x * m.x + prev.x * (1.f - m.x);
    r.y = cur.y * m.y + prev.y * (1.f - m.y);
    r.z = cur.z * m.z + prev.z * (1.f - m.z);
    r.w = cur.w * m.w + prev.w * (1.f - m.w);
    return r;
}

__global__ __launch_bounds__(256) void mix3_split(
    const float* __restrict__ xn,
    const float* __restrict__ tk, const float* __restrict__ tv,
    const float* __restrict__ tr,
    bf16* kh, bf16* kl, bf16* vh, bf16* vl, bf16* rh, bf16* rl)
{
    const size_t i4 = (size_t)blockIdx.x * blockDim.x + threadIdx.x;
    const size_t idx = i4 * 4;
    const int c = (int)(idx % Cn);
    const int t = (int)((idx / Cn) % Tn);
    float4 cur = *(const float4*)(xn + idx);
    float4 prev = make_float4(0.f, 0.f, 0.f, 0.f);
    if (t > 0) prev = *(const float4*)(xn + idx - Cn);
    store_split4(lerp4(cur, prev, *(const float4*)(tk + c)), kh, kl, idx);
    store_split4(lerp4(cur, prev, *(const float4*)(tv + c)), vh, vl, idx);
    store_split4(lerp4(cur, prev, *(const float4*)(tr + c)), rh, rl, idx);
}

__global__ __launch_bounds__(256) void mix2_split(
    const float* __restrict__ xn,
    const float* __restrict__ tk, const float* __restrict__ tr,
    bf16* kh, bf16* kl, bf16* rh, bf16* rl)
{
    const size_t i4 = (size_t)blockIdx.x * blockDim.x + threadIdx.x;
    const size_t idx = i4 * 4;
    const int c = (int)(idx % Cn);
    const int t = (int)((idx / Cn) % Tn);
    float4 cur = *(const float4*)(xn + idx);
    float4 prev = make_float4(0.f, 0.f, 0.f, 0.f);
    if (t > 0) prev = *(const float4*)(xn + idx - Cn);
    store_split4(lerp4(cur, prev, *(const float4*)(tk + c)), kh, kl, idx);
    store_split4(lerp4(cur, prev, *(const float4*)(tr + c)), rh, rl, idx);
}

// Weight split: fp32 -> bf16 hi/lo
__global__ __launch_bounds__(256) void split_w(
    const float* __restrict__ w, bf16* __restrict__ hi, bf16* __restrict__ lo)
{
    const size_t i4 = (size_t)blockIdx.x * blockDim.x + threadIdx.x;
    const size_t idx = i4 * 4;
    float4 v = *(const float4*)(w + idx);
    store_split4(v, hi, lo, idx);
}

// ---------------------------------------------------------------------------
// WKV recurrence + sigmoid(r) gate → bf16 hi/lo split output
// ---------------------------------------------------------------------------
__global__ __launch_bounds__(64) void wkv_gate_kernel(
    const float* __restrict__ k, const float* __restrict__ v,
    const float* __restrict__ r,
    const float* __restrict__ w_decay, const float* __restrict__ u_first,
    bf16* __restrict__ gh, bf16* __restrict__ gl)
{
    const int idx = blockIdx.x * blockDim.x + threadIdx.x;
    const int c = idx % Cn;
    const int b = idx / Cn;
    const float w = -expf(w_decay[c]);
    const float u = u_first[c];

    float aa = 0.f, bb = 0.f, pp = -1e38f;
    size_t off = (size_t)b * Tn * Cn + c;
    for (int t = 0; t < Tn; t++, off += Cn) {
        const float kt = k[off];
        const float vt = v[off];
        const float rr = r[off];

        const float ww = u + kt;
        const float p  = fmaxf(pp, ww);
        const float e1 = __expf(pp - p);
        const float e2 = __expf(ww - p);
        const float y  = (e1 * aa + e2 * vt) / (e1 * bb + e2);
        const float gv = y / (1.f + __expf(-rr));
        bf16 h = __float2bfloat16(gv);
        gh[off] = h;
        gl[off] = __float2bfloat16(gv - __bfloat162float(h));

        const float ww2 = pp + w;
        const float p2  = fmaxf(ww2, kt);
        const float e1b = __expf(ww2 - p2);
        const float e2b = __expf(kt - p2);
        aa = e1b * aa + e2b * vt;
        bb = e1b * bb + e2b;
        pp = p2;
    }
}

// ---------------------------------------------------------------------------
// HMMA split-bf16 GEMM:  C[M,N] = A[M,K] @ B[N,K]^T, 3-product bf16
// CTA 128x256, BK=32, 16 warps (2x8), warp tile 64x32, mma.sync.m16n8k16.
// 3-stage cp.async pipeline; smem rows padded to 80B (conflict-free ldmatrix).
// EPI: 0 plain fp32; 1 +res0; 2 relu^2 -> bf16 hi/lo; 3 res0 + sigmoid*res1
// ---------------------------------------------------------------------------
static constexpr int ROWB   = 80;             // 32 bf16 = 64B + 16B pad
static constexpr int A_T    = 128 * ROWB;     // 10240
static constexpr int B_T    = 256 * ROWB;     // 20480
static constexpr int STAGE  = 2 * A_T + 2 * B_T;  // 61440 (Ah, Al, Bh, Bl)
static constexpr int NSTAGE = 3;
static constexpr int SMEM_DYN = NSTAGE * STAGE;   // 184320

__device__ __forceinline__ void load_stage(
    uint32_t st, const bf16* Ah, const bf16* Al, const bf16* Bh, const bf16* Bl,
    int m0, int n0, int k0, int K, int tid)
{
    {
        const int row = tid >> 2, kc = tid & 3;          // 128 rows x 4 chunks
        const uint32_t so = (uint32_t)(row * ROWB + kc * 16);
        const size_t ga = (size_t)(m0 + row) * K + k0 + kc * 8;
        cp16(st + so, Ah + ga);
        cp16(st + A_T + so, Al + ga);
    }
#pragma unroll
    for (int q = 0; q < 2; q++) {
        const int idx = tid + q * 512;                   // 256 rows x 4 chunks
        const int row = idx >> 2, kc = idx & 3;
        const uint32_t so = (uint32_t)(row * ROWB + kc * 16);
        const size_t gb = (size_t)(n0 + row) * K + k0 + kc * 8;
        cp16(st + 2 * A_T + so, Bh + gb);
        cp16(st + 2 * A_T + B_T + so, Bl + gb);
    }
}

template <int EPI>
__global__ __launch_bounds__(512, 1) void gemm3bf(
    const bf16* __restrict__ Ah, const bf16* __restrict__ Al,
    const bf16* __restrict__ Bh, const bf16* __restrict__ Bl,
    float* __restrict__ Cm, bf16* __restrict__ Oh, bf16* __restrict__ Ol,
    int N, int K,
    const float* __restrict__ res0, const float* __restrict__ res1)
{
    extern __shared__ char dsm[];
    const uint32_t sb = smem_u32(dsm);
    const int tid = threadIdx.x, wid = tid >> 5, lane = tid & 31;
    const int m0 = blockIdx.y * 128, n0 = blockIdx.x * 256;
    const int wm = wid >> 3, wn = wid & 7;   // 2 x 8 warps, warp tile 64x32

    float acc[4][4][4];
#pragma unroll
    for (int a = 0; a < 4; a++)
#pragma unroll
        for (int b = 0; b < 4; b++)
#pragma unroll
            for (int c = 0; c < 4; c++) acc[a][b][c] = 0.f;

    const int nk = K >> 5;

    load_stage(sb + 0 * STAGE, Ah, Al, Bh, Bl, m0, n0, 0,  K, tid); CP_COMMIT();
    load_stage(sb + 1 * STAGE, Ah, Al, Bh, Bl, m0, n0, 32, K, tid); CP_COMMIT();

    const int a_row  = wm * 64 + (lane & 15);
    const int a_koff = (lane & 16) ? 8 : 0;
    const int b_row  = wn * 32 + (lane & 7) + ((lane & 16) ? 8 : 0);
    const int b_koff = (lane & 8) ? 8 : 0;

    int sidx = 0;  // i % 3
    for (int i = 0; i < nk; i++) {
        if (i + 1 < nk) asm volatile("cp.async.wait_group 1;" ::: "memory");
        else            asm volatile("cp.async.wait_group 0;" ::: "memory");
        __syncthreads();

        if (i + 2 < nk) {
            int ns = sidx + 2; if (ns >= 3) ns -= 3;
            load_stage(sb + ns * STAGE, Ah, Al, Bh, Bl, m0, n0, (i + 2) * 32, K, tid);
            CP_COMMIT();
        }

        const uint32_t st = sb + sidx * STAGE;
        if (++sidx == 3) sidx = 0;
#pragma unroll
        for (int k16 = 0; k16 < 2; k16++) {
            uint32_t ah[4][4], al[4][4];
            const uint32_t acol = (uint32_t)(k16 * 16 + a_koff) * 2;
#pragma unroll
            for (int mt = 0; mt < 4; mt++) {
                const uint32_t ad = st + (uint32_t)(a_row + mt * 16) * ROWB + acol;
                ldsm4(ah[mt][0], ah[mt][1], ah[mt][2], ah[mt][3], ad);
                ldsm4(al[mt][0], al[mt][1], al[mt][2], al[mt][3], ad + A_T);
            }
            uint32_t bh[4][2], bl[4][2];
            const uint32_t bcol = (uint32_t)(k16 * 16 + b_koff) * 2;
#pragma unroll
            for (int p = 0; p < 2; p++) {
                const uint32_t bd = st + 2 * A_T +
                                    (uint32_t)(b_row + p * 16) * ROWB + bcol;
                ldsm4(bh[2*p][0], bh[2*p][1], bh[2*p+1][0], bh[2*p+1][1], bd);
                ldsm4(bl[2*p][0], bl[2*p][1], bl[2*p+1][0], bl[2*p+1][1], bd + B_T);
            }
#pragma unroll
            for (int mt = 0; mt < 4; mt++)
#pragma unroll
                for (int nt = 0; nt < 4; nt++) {
                    mma16816(acc[mt][nt], ah[mt], bh[nt]);
                    mma16816(acc[mt][nt], ah[mt], bl[nt]);
                    mma16816(acc[mt][nt], al[mt], bh[nt]);
                }
        }
    }

    // Epilogue: registers -> global
    const int row_base = m0 + wm * 64 + (lane >> 2);
    const int col_base = n0 + wn * 32 + (lane & 3) * 2;
#pragma unroll
    for (int mt = 0; mt < 4; mt++) {
#pragma unroll
        for (int h = 0; h < 2; h++) {
            const int row = row_base + mt * 16 + h * 8;
#pragma unroll
            for (int nt = 0; nt < 4; nt++) {
                float vx = acc[mt][nt][2 * h + 0];
                float vy = acc[mt][nt][2 * h + 1];
                const size_t off = (size_t)row * N + col_base + nt * 8;
                if (EPI == 0) {
                    *(float2*)(Cm + off) = make_float2(vx, vy);
                } else if (EPI == 1) {
                    float2 r = *(const float2*)(res0 + off);
                    *(float2*)(Cm + off) = make_float2(vx + r.x, vy + r.y);
                } else if (EPI == 2) {
                    vx = fmaxf(vx, 0.f); vx *= vx;
                    vy = fmaxf(vy, 0.f); vy *= vy;
                    store_split2(vx, vy, Oh, Ol, off);
                } else {
                    float2 r0 = *(const float2*)(res0 + off);
                    float2 r1 = *(const float2*)(res1 + off);
                    vx = r0.x + r1.x / (1.f + __expf(-vx));
                    vy = r0.y + r1.y / (1.f + __expf(-vy));
                    *(float2*)(Cm + off) = make_float2(vx, vy);
                }
            }
        }
    }
}

// ---------------------------------------------------------------------------
// Launch
// ---------------------------------------------------------------------------
extern "C" void kernel_launch(void* const* d_in, const int* in_sizes, int n_in,
                              void* d_out, int out_size)
{
    (void)in_sizes; (void)n_in; (void)out_size;
    const float* x    = (const float*)d_in[0];
    const float* ln1w = (const float*)d_in[1];
    const float* ln1b = (const float*)d_in[2];
    const float* ln2w = (const float*)d_in[3];
    const float* ln2b = (const float*)d_in[4];
    const float* tdec = (const float*)d_in[5];
    const float* tfir = (const float*)d_in[6];
    const float* tmk  = (const float*)d_in[7];
    const float* tmv  = (const float*)d_in[8];
    const float* tmr  = (const float*)d_in[9];
    const float* Wk   = (const float*)d_in[10];
    const float* Wv   = (const float*)d_in[11];
    const float* Wr   = (const float*)d_in[12];
    const float* Wo   = (const float*)d_in[13];
    const float* cmk  = (const float*)d_in[14];
    const float* cmr  = (const float*)d_in[15];
    const float* Wck  = (const float*)d_in[16];
    const float* Wcv  = (const float*)d_in[17];
    const float* Wcr  = (const float*)d_in[18];
    float* out = (float*)d_out;

    float *xn, *kf, *vf, *rf, *x1, *kv;
    bf16 *p0h, *p0l, *p1h, *p1l, *p2h, *p2l, *hh, *hl, *wh, *wl;
    cudaGetSymbolAddress((void**)&xn, g_xn);
    cudaGetSymbolAddress((void**)&kf, g_k);
    cudaGetSymbolAddress((void**)&vf, g_v);
    cudaGetSymbolAddress((void**)&rf, g_r);
    cudaGetSymbolAddress((void**)&x1, g_x1);
    cudaGetSymbolAddress((void**)&kv, g_kv);
    cudaGetSymbolAddress((void**)&p0h, g_p0h);
    cudaGetSymbolAddress((void**)&p0l, g_p0l);
    cudaGetSymbolAddress((void**)&p1h, g_p1h);
    cudaGetSymbolAddress((void**)&p1l, g_p1l);
    cudaGetSymbolAddress((void**)&p2h, g_p2h);
    cudaGetSymbolAddress((void**)&p2l, g_p2l);
    cudaGetSymbolAddress((void**)&hh, g_hh);
    cudaGetSymbolAddress((void**)&hl, g_hl);
    cudaGetSymbolAddress((void**)&wh, g_wh);
    cudaGetSymbolAddress((void**)&wl, g_wl);

    cudaFuncSetAttribute(gemm3bf<0>, cudaFuncAttributeMaxDynamicSharedMemorySize, SMEM_DYN);
    cudaFuncSetAttribute(gemm3bf<1>, cudaFuncAttributeMaxDynamicSharedMemorySize, SMEM_DYN);
    cudaFuncSetAttribute(gemm3bf<2>, cudaFuncAttributeMaxDynamicSharedMemorySize, SMEM_DYN);
    cudaFuncSetAttribute(gemm3bf<3>, cudaFuncAttributeMaxDynamicSharedMemorySize, SMEM_DYN);

    const int mixBlocks = (int)(((size_t)Mn * Cn / 4) / 256);
    const int wCC = (Cn * Cn / 4) / 256;
    const int wHC = (Hn * Cn / 4) / 256;
    const dim3 gC(Cn / 256, Mn / 128);   // (8, 128)
    const dim3 gH(Hn / 256, Mn / 128);   // (32, 128)

    // --- time-mix attention ---
    ln_kernel<<<Mn, 256>>>(x, ln1w, ln1b, xn);
    mix3_split<<<mixBlocks, 256>>>(xn, tmk, tmv, tmr, p0h, p0l, p1h, p1l, p2h, p2l);

    split_w<<<wCC, 256>>>(Wk, wh, wl);
    gemm3bf<0><<<gC, 512, SMEM_DYN>>>(p0h, p0l, wh, wl, kf, nullptr, nullptr, Cn, Cn, nullptr, nullptr);
    split_w<<<wCC, 256>>>(Wv, wh, wl);
    gemm3bf<0><<<gC, 512, SMEM_DYN>>>(p1h, p1l, wh, wl, vf, nullptr, nullptr, Cn, Cn, nullptr, nullptr);
    split_w<<<wCC, 256>>>(Wr, wh, wl);
    gemm3bf<0><<<gC, 512, SMEM_DYN>>>(p2h, p2l, wh, wl, rf, nullptr, nullptr, Cn, Cn, nullptr, nullptr);

    wkv_gate_kernel<<<(Bn * Cn) / 64, 64>>>(kf, vf, rf, tdec, tfir, p0h, p0l);

    split_w<<<wCC, 256>>>(Wo, wh, wl);
    gemm3bf<1><<<gC, 512, SMEM_DYN>>>(p0h, p0l, wh, wl, x1, nullptr, nullptr, Cn, Cn, x, nullptr);

    // --- channel mix ---
    ln_kernel<<<Mn, 256>>>(x1, ln2w, ln2b, xn);
    mix2_split<<<mixBlocks, 256>>>(xn, cmk, cmr, p1h, p1l, p2h, p2l);

    split_w<<<wHC, 256>>>(Wck, wh, wl);
    gemm3bf<2><<<gH, 512, SMEM_DYN>>>(p1h, p1l, wh, wl, nullptr, hh, hl, Hn, Cn, nullptr, nullptr);
    split_w<<<wHC, 256>>>(Wcv, wh, wl);
    gemm3bf<0><<<gC, 512, SMEM_DYN>>>(hh, hl, wh, wl, kv, nullptr, nullptr, Cn, Hn, nullptr, nullptr);
    split_w<<<wCC, 256>>>(Wcr, wh, wl);
    gemm3bf<3><<<gC, 512, SMEM_DYN>>>(p2h, p2l, wh, wl, out, nullptr, nullptr, Cn, Cn, x1, kv);
}

// round 5
// speedup vs baseline: 5.4522x; 1.3346x over previous
#include <cuda_runtime.h>
#include <cuda_fp16.h>
#include <math.h>
#include <stdint.h>

#define Bn 8
#define Tn 2048
#define Cn 2048
#define Hn 8192
#define Mn (Bn * Tn)   // 16384

// ---------------------------------------------------------------------------
// Scratch (device globals — allocation-free per harness rules)
// ---------------------------------------------------------------------------
__device__ float g_xn[(size_t)Mn * Cn];
__device__ float g_k [(size_t)Mn * Cn];
__device__ float g_v [(size_t)Mn * Cn];
__device__ float g_r [(size_t)Mn * Cn];
__device__ float g_x1[(size_t)Mn * Cn];
__device__ float g_kv[(size_t)Mn * Cn];
__device__ __half g_a0[(size_t)Mn * Cn];
__device__ __half g_a1[(size_t)Mn * Cn];
__device__ __half g_a2[(size_t)Mn * Cn];
__device__ __half g_h [(size_t)Mn * Hn];
__device__ __half g_wh[(size_t)Hn * Cn], g_wl[(size_t)Hn * Cn];

// ---------------------------------------------------------------------------
// PTX helpers (baseline sm_103 — NO "a"-suffix features)
// ---------------------------------------------------------------------------
__device__ __forceinline__ uint32_t smem_u32(const void* p) {
    uint32_t a;
    asm("{ .reg .u64 t; cvta.to.shared.u64 t, %1; cvt.u32.u64 %0, t; }"
        : "=r"(a) : "l"(p));
    return a;
}

__device__ __forceinline__ void cp16(uint32_t s, const void* g) {
    asm volatile("cp.async.cg.shared.global [%0], [%1], 16;" :: "r"(s), "l"(g));
}
#define CP_COMMIT() asm volatile("cp.async.commit_group;" ::: "memory")

__device__ __forceinline__ void ldsm4(uint32_t& r0, uint32_t& r1,
                                      uint32_t& r2, uint32_t& r3, uint32_t a) {
    asm volatile("ldmatrix.sync.aligned.m8n8.x4.shared.b16 {%0,%1,%2,%3}, [%4];"
                 : "=r"(r0), "=r"(r1), "=r"(r2), "=r"(r3) : "r"(a));
}

__device__ __forceinline__ void mma16816(float* d, const uint32_t* a,
                                         const uint32_t* b) {
    asm volatile(
        "mma.sync.aligned.m16n8k16.row.col.f32.f16.f16.f32 "
        "{%0,%1,%2,%3}, {%4,%5,%6,%7}, {%8,%9}, {%0,%1,%2,%3};"
        : "+f"(d[0]), "+f"(d[1]), "+f"(d[2]), "+f"(d[3])
        : "r"(a[0]), "r"(a[1]), "r"(a[2]), "r"(a[3]), "r"(b[0]), "r"(b[1]));
}

// ---------------------------------------------------------------------------
// fp16 pack helpers
// ---------------------------------------------------------------------------
__device__ __forceinline__ uint32_t pack2h(float x, float y) {
    __half2 t = __floats2half2_rn(x, y);
    return *reinterpret_cast<uint32_t*>(&t);
}

__device__ __forceinline__ void store_h4(float4 v, __half* p, size_t idx) {
    uint2 u;
    u.x = pack2h(v.x, v.y);
    u.y = pack2h(v.z, v.w);
    *(uint2*)(p + idx) = u;
}

// weight split: w = wh + wl (fp16 hi/lo)
__device__ __forceinline__ void store_splitw4(float4 v, __half* ph, __half* pl,
                                              size_t idx) {
    float hx = __half2float(__float2half_rn(v.x));
    float hy = __half2float(__float2half_rn(v.y));
    float hz = __half2float(__float2half_rn(v.z));
    float hw = __half2float(__float2half_rn(v.w));
    uint2 H, L;
    H.x = pack2h(v.x, v.y); H.y = pack2h(v.z, v.w);
    L.x = pack2h(v.x - hx, v.y - hy); L.y = pack2h(v.z - hz, v.w - hw);
    *(uint2*)(ph + idx) = H;
    *(uint2*)(pl + idx) = L;
}

// ---------------------------------------------------------------------------
// LayerNorm: one block per row
// ---------------------------------------------------------------------------
__global__ __launch_bounds__(256) void ln_kernel(
    const float* __restrict__ x, const float* __restrict__ w,
    const float* __restrict__ b, float* __restrict__ out)
{
    const int row = blockIdx.x;
    const int tid = threadIdx.x;
    const float* xr = x + (size_t)row * Cn;

    float4 f0 = ((const float4*)xr)[tid];
    float4 f1 = ((const float4*)xr)[tid + 256];
    float v[8] = {f0.x, f0.y, f0.z, f0.w, f1.x, f1.y, f1.z, f1.w};

    float s = 0.f, s2 = 0.f;
#pragma unroll
    for (int i = 0; i < 8; i++) { s += v[i]; s2 += v[i] * v[i]; }
#pragma unroll
    for (int o = 16; o > 0; o >>= 1) {
        s  += __shfl_xor_sync(0xFFFFFFFFu, s,  o);
        s2 += __shfl_xor_sync(0xFFFFFFFFu, s2, o);
    }
    __shared__ float sh[16];
    const int wid = tid >> 5, lane = tid & 31;
    if (lane == 0) { sh[wid] = s; sh[wid + 8] = s2; }
    __syncthreads();
    if (tid < 32) {
        float a  = (tid < 8) ? sh[tid]     : 0.f;
        float a2 = (tid < 8) ? sh[tid + 8] : 0.f;
#pragma unroll
        for (int o = 4; o > 0; o >>= 1) {
            a  += __shfl_xor_sync(0xFFFFFFFFu, a,  o);
            a2 += __shfl_xor_sync(0xFFFFFFFFu, a2, o);
        }
        if (tid == 0) { sh[0] = a; sh[1] = a2; }
    }
    __syncthreads();

    const float mu  = sh[0] * (1.f / Cn);
    const float var = sh[1] * (1.f / Cn) - mu * mu;
    const float inv = rsqrtf(var + 1e-5f);

    float* orow = out + (size_t)row * Cn;
    const int c0 = tid * 4, c1 = (tid + 256) * 4;
    float4 o0, o1;
    o0.x = (v[0] - mu) * inv * w[c0 + 0] + b[c0 + 0];
    o0.y = (v[1] - mu) * inv * w[c0 + 1] + b[c0 + 1];
    o0.z = (v[2] - mu) * inv * w[c0 + 2] + b[c0 + 2];
    o0.w = (v[3] - mu) * inv * w[c0 + 3] + b[c0 + 3];
    o1.x = (v[4] - mu) * inv * w[c1 + 0] + b[c1 + 0];
    o1.y = (v[5] - mu) * inv * w[c1 + 1] + b[c1 + 1];
    o1.z = (v[6] - mu) * inv * w[c1 + 2] + b[c1 + 2];
    o1.w = (v[7] - mu) * inv * w[c1 + 3] + b[c1 + 3];
    ((float4*)orow)[tid]       = o0;
    ((float4*)orow)[tid + 256] = o1;
}

// ---------------------------------------------------------------------------
// Time-shift mixes → fp16
// ---------------------------------------------------------------------------
__device__ __forceinline__ float4 lerp4(float4 cur, float4 prev, float4 m) {
    float4 r;
    r.x = cur.x * m.x + prev.x * (1.f - m.x);
    r.y = cur.y * m.y + prev.y * (1.f - m.y);
    r.z = cur.z * m.z + prev.z * (1.f - m.z);
    r.w = cur.w * m.w + prev.w * (1.f - m.w);
    return r;
}

__global__ __launch_bounds__(256) void mix3_h(
    const float* __restrict__ xn,
    const float* __restrict__ tk, const float* __restrict__ tv,
    const float* __restrict__ tr,
    __half* xk, __half* xv, __half* xr)
{
    const size_t i4 = (size_t)blockIdx.x * blockDim.x + threadIdx.x;
    const size_t idx = i4 * 4;
    const int c = (int)(idx % Cn);
    const int t = (int)((idx / Cn) % Tn);
    float4 cur = *(const float4*)(xn + idx);
    float4 prev = make_float4(0.f, 0.f, 0.f, 0.f);
    if (t > 0) prev = *(const float4*)(xn + idx - Cn);
    store_h4(lerp4(cur, prev, *(const float4*)(tk + c)), xk, idx);
    store_h4(lerp4(cur, prev, *(const float4*)(tv + c)), xv, idx);
    store_h4(lerp4(cur, prev, *(const float4*)(tr + c)), xr, idx);
}

__global__ __launch_bounds__(256) void mix2_h(
    const float* __restrict__ xn,
    const float* __restrict__ tk, const float* __restrict__ tr,
    __half* ck, __half* cr)
{
    const size_t i4 = (size_t)blockIdx.x * blockDim.x + threadIdx.x;
    const size_t idx = i4 * 4;
    const int c = (int)(idx % Cn);
    const int t = (int)((idx / Cn) % Tn);
    float4 cur = *(const float4*)(xn + idx);
    float4 prev = make_float4(0.f, 0.f, 0.f, 0.f);
    if (t > 0) prev = *(const float4*)(xn + idx - Cn);
    store_h4(lerp4(cur, prev, *(const float4*)(tk + c)), ck, idx);
    store_h4(lerp4(cur, prev, *(const float4*)(tr + c)), cr, idx);
}

// Weight split: fp32 -> fp16 hi/lo
__global__ __launch_bounds__(256) void split_w(
    const float* __restrict__ w, __half* __restrict__ hi, __half* __restrict__ lo)
{
    const size_t i4 = (size_t)blockIdx.x * blockDim.x + threadIdx.x;
    const size_t idx = i4 * 4;
    float4 v = *(const float4*)(w + idx);
    store_splitw4(v, hi, lo, idx);
}

// ---------------------------------------------------------------------------
// WKV recurrence + sigmoid(r) gate → fp16 output
// ---------------------------------------------------------------------------
__global__ __launch_bounds__(64) void wkv_gate_kernel(
    const float* __restrict__ k, const float* __restrict__ v,
    const float* __restrict__ r,
    const float* __restrict__ w_decay, const float* __restrict__ u_first,
    __half* __restrict__ g)
{
    const int idx = blockIdx.x * blockDim.x + threadIdx.x;
    const int c = idx % Cn;
    const int b = idx / Cn;
    const float w = -expf(w_decay[c]);
    const float u = u_first[c];

    float aa = 0.f, bb = 0.f, pp = -1e38f;
    size_t off = (size_t)b * Tn * Cn + c;
    for (int t = 0; t < Tn; t++, off += Cn) {
        const float kt = k[off];
        const float vt = v[off];
        const float rr = r[off];

        const float ww = u + kt;
        const float p  = fmaxf(pp, ww);
        const float e1 = __expf(pp - p);
        const float e2 = __expf(ww - p);
        const float y  = (e1 * aa + e2 * vt) / (e1 * bb + e2);
        g[off] = __float2half_rn(y / (1.f + __expf(-rr)));

        const float ww2 = pp + w;
        const float p2  = fmaxf(ww2, kt);
        const float e1b = __expf(ww2 - p2);
        const float e2b = __expf(kt - p2);
        aa = e1b * aa + e2b * vt;
        bb = e1b * bb + e2b;
        pp = p2;
    }
}

// ---------------------------------------------------------------------------
// HMMA fp16 2-product GEMM:  C[M,N] = A[M,K] @ (Bh+Bl)[N,K]^T
// A plain fp16; B split hi/lo fp16.  CTA 128x256, BK=32, 16 warps (2x8),
// warp tile 64x32, mma.sync.m16n8k16, 3-stage cp.async pipeline,
// 80B-padded smem rows (conflict-free ldmatrix).
// EPI: 0 plain fp32; 1 +res0; 2 relu^2 -> fp16; 3 res0 + sigmoid*res1
// ---------------------------------------------------------------------------
static constexpr int ROWB   = 80;                 // 32 fp16 = 64B + 16B pad
static constexpr int A_T    = 128 * ROWB;         // 10240
static constexpr int B_T    = 256 * ROWB;         // 20480
static constexpr int STAGE  = A_T + 2 * B_T;      // 51200 (A, Bh, Bl)
static constexpr int NSTAGE = 3;
static constexpr int SMEM_DYN = NSTAGE * STAGE;   // 153600

__device__ __forceinline__ void load_stage(
    uint32_t st, const __half* A, const __half* Bh, const __half* Bl,
    int m0, int n0, int k0, int K, int tid)
{
    {
        const int row = tid >> 2, kc = tid & 3;          // 128 rows x 4 chunks
        const uint32_t so = (uint32_t)(row * ROWB + kc * 16);
        cp16(st + so, A + (size_t)(m0 + row) * K + k0 + kc * 8);
    }
#pragma unroll
    for (int q = 0; q < 2; q++) {
        const int idx = tid + q * 512;                   // 256 rows x 4 chunks
        const int row = idx >> 2, kc = idx & 3;
        const uint32_t so = (uint32_t)(row * ROWB + kc * 16);
        const size_t gb = (size_t)(n0 + row) * K + k0 + kc * 8;
        cp16(st + A_T + so, Bh + gb);
        cp16(st + A_T + B_T + so, Bl + gb);
    }
}

template <int EPI>
__global__ __launch_bounds__(512, 1) void gemm2h(
    const __half* __restrict__ A,
    const __half* __restrict__ Bh, const __half* __restrict__ Bl,
    float* __restrict__ Cm, __half* __restrict__ Oh,
    int N, int K,
    const float* __restrict__ res0, const float* __restrict__ res1)
{
    extern __shared__ char dsm[];
    const uint32_t sb = smem_u32(dsm);
    const int tid = threadIdx.x, wid = tid >> 5, lane = tid & 31;
    const int m0 = blockIdx.y * 128, n0 = blockIdx.x * 256;
    const int wm = wid >> 3, wn = wid & 7;   // 2 x 8 warps, warp tile 64x32

    float acc[4][4][4];
#pragma unroll
    for (int a = 0; a < 4; a++)
#pragma unroll
        for (int b = 0; b < 4; b++)
#pragma unroll
            for (int c = 0; c < 4; c++) acc[a][b][c] = 0.f;

    const int nk = K >> 5;

    load_stage(sb + 0 * STAGE, A, Bh, Bl, m0, n0, 0,  K, tid); CP_COMMIT();
    load_stage(sb + 1 * STAGE, A, Bh, Bl, m0, n0, 32, K, tid); CP_COMMIT();

    const int a_row  = wm * 64 + (lane & 15);
    const int a_koff = (lane & 16) ? 8 : 0;
    const int b_row  = wn * 32 + (lane & 7) + ((lane & 16) ? 8 : 0);
    const int b_koff = (lane & 8) ? 8 : 0;

    int sidx = 0;
    for (int i = 0; i < nk; i++) {
        if (i + 1 < nk) asm volatile("cp.async.wait_group 1;" ::: "memory");
        else            asm volatile("cp.async.wait_group 0;" ::: "memory");
        __syncthreads();

        if (i + 2 < nk) {
            int ns = sidx + 2; if (ns >= 3) ns -= 3;
            load_stage(sb + ns * STAGE, A, Bh, Bl, m0, n0, (i + 2) * 32, K, tid);
            CP_COMMIT();
        }

        const uint32_t st = sb + sidx * STAGE;
        if (++sidx == 3) sidx = 0;
#pragma unroll
        for (int k16 = 0; k16 < 2; k16++) {
            uint32_t ah[4][4];
            const uint32_t acol = (uint32_t)(k16 * 16 + a_koff) * 2;
#pragma unroll
            for (int mt = 0; mt < 4; mt++) {
                const uint32_t ad = st + (uint32_t)(a_row + mt * 16) * ROWB + acol;
                ldsm4(ah[mt][0], ah[mt][1], ah[mt][2], ah[mt][3], ad);
            }
            uint32_t bh[4][2], bl[4][2];
            const uint32_t bcol = (uint32_t)(k16 * 16 + b_koff) * 2;
#pragma unroll
            for (int p = 0; p < 2; p++) {
                const uint32_t bd = st + A_T +
                                    (uint32_t)(b_row + p * 16) * ROWB + bcol;
                ldsm4(bh[2*p][0], bh[2*p][1], bh[2*p+1][0], bh[2*p+1][1], bd);
                ldsm4(bl[2*p][0], bl[2*p][1], bl[2*p+1][0], bl[2*p+1][1], bd + B_T);
            }
#pragma unroll
            for (int mt = 0; mt < 4; mt++)
#pragma unroll
                for (int nt = 0; nt < 4; nt++) {
                    mma16816(acc[mt][nt], ah[mt], bh[nt]);
                    mma16816(acc[mt][nt], ah[mt], bl[nt]);
                }
        }
    }

    // Epilogue: registers -> global
    const int row_base = m0 + wm * 64 + (lane >> 2);
    const int col_base = n0 + wn * 32 + (lane & 3) * 2;
#pragma unroll
    for (int mt = 0; mt < 4; mt++) {
#pragma unroll
        for (int h = 0; h < 2; h++) {
            const int row = row_base + mt * 16 + h * 8;
#pragma unroll
            for (int nt = 0; nt < 4; nt++) {
                float vx = acc[mt][nt][2 * h + 0];
                float vy = acc[mt][nt][2 * h + 1];
                const size_t off = (size_t)row * N + col_base + nt * 8;
                if (EPI == 0) {
                    *(float2*)(Cm + off) = make_float2(vx, vy);
                } else if (EPI == 1) {
                    float2 r = *(const float2*)(res0 + off);
                    *(float2*)(Cm + off) = make_float2(vx + r.x, vy + r.y);
                } else if (EPI == 2) {
                    vx = fmaxf(vx, 0.f); vx *= vx;
                    vy = fmaxf(vy, 0.f); vy *= vy;
                    *(uint32_t*)(Oh + off) = pack2h(vx, vy);
                } else {
                    float2 r0 = *(const float2*)(res0 + off);
                    float2 r1 = *(const float2*)(res1 + off);
                    vx = r0.x + r1.x / (1.f + __expf(-vx));
                    vy = r0.y + r1.y / (1.f + __expf(-vy));
                    *(float2*)(Cm + off) = make_float2(vx, vy);
                }
            }
        }
    }
}

// ---------------------------------------------------------------------------
// Launch
// ---------------------------------------------------------------------------
extern "C" void kernel_launch(void* const* d_in, const int* in_sizes, int n_in,
                              void* d_out, int out_size)
{
    (void)in_sizes; (void)n_in; (void)out_size;
    const float* x    = (const float*)d_in[0];
    const float* ln1w = (const float*)d_in[1];
    const float* ln1b = (const float*)d_in[2];
    const float* ln2w = (const float*)d_in[3];
    const float* ln2b = (const float*)d_in[4];
    const float* tdec = (const float*)d_in[5];
    const float* tfir = (const float*)d_in[6];
    const float* tmk  = (const float*)d_in[7];
    const float* tmv  = (const float*)d_in[8];
    const float* tmr  = (const float*)d_in[9];
    const float* Wk   = (const float*)d_in[10];
    const float* Wv   = (const float*)d_in[11];
    const float* Wr   = (const float*)d_in[12];
    const float* Wo   = (const float*)d_in[13];
    const float* cmk  = (const float*)d_in[14];
    const float* cmr  = (const float*)d_in[15];
    const float* Wck  = (const float*)d_in[16];
    const float* Wcv  = (const float*)d_in[17];
    const float* Wcr  = (const float*)d_in[18];
    float* out = (float*)d_out;

    float *xn, *kf, *vf, *rf, *x1, *kv;
    __half *a0, *a1, *a2, *hb, *wh, *wl;
    cudaGetSymbolAddress((void**)&xn, g_xn);
    cudaGetSymbolAddress((void**)&kf, g_k);
    cudaGetSymbolAddress((void**)&vf, g_v);
    cudaGetSymbolAddress((void**)&rf, g_r);
    cudaGetSymbolAddress((void**)&x1, g_x1);
    cudaGetSymbolAddress((void**)&kv, g_kv);
    cudaGetSymbolAddress((void**)&a0, g_a0);
    cudaGetSymbolAddress((void**)&a1, g_a1);
    cudaGetSymbolAddress((void**)&a2, g_a2);
    cudaGetSymbolAddress((void**)&hb, g_h);
    cudaGetSymbolAddress((void**)&wh, g_wh);
    cudaGetSymbolAddress((void**)&wl, g_wl);

    cudaFuncSetAttribute(gemm2h<0>, cudaFuncAttributeMaxDynamicSharedMemorySize, SMEM_DYN);
    cudaFuncSetAttribute(gemm2h<1>, cudaFuncAttributeMaxDynamicSharedMemorySize, SMEM_DYN);
    cudaFuncSetAttribute(gemm2h<2>, cudaFuncAttributeMaxDynamicSharedMemorySize, SMEM_DYN);
    cudaFuncSetAttribute(gemm2h<3>, cudaFuncAttributeMaxDynamicSharedMemorySize, SMEM_DYN);

    const int mixBlocks = (int)(((size_t)Mn * Cn / 4) / 256);
    const int wCC = (Cn * Cn / 4) / 256;
    const int wHC = (Hn * Cn / 4) / 256;
    const dim3 gC(Cn / 256, Mn / 128);   // (8, 128)
    const dim3 gH(Hn / 256, Mn / 128);   // (32, 128)

    // --- time-mix attention ---
    ln_kernel<<<Mn, 256>>>(x, ln1w, ln1b, xn);
    mix3_h<<<mixBlocks, 256>>>(xn, tmk, tmv, tmr, a0, a1, a2);

    split_w<<<wCC, 256>>>(Wk, wh, wl);
    gemm2h<0><<<gC, 512, SMEM_DYN>>>(a0, wh, wl, kf, nullptr, Cn, Cn, nullptr, nullptr);
    split_w<<<wCC, 256>>>(Wv, wh, wl);
    gemm2h<0><<<gC, 512, SMEM_DYN>>>(a1, wh, wl, vf, nullptr, Cn, Cn, nullptr, nullptr);
    split_w<<<wCC, 256>>>(Wr, wh, wl);
    gemm2h<0><<<gC, 512, SMEM_DYN>>>(a2, wh, wl, rf, nullptr, Cn, Cn, nullptr, nullptr);

    wkv_gate_kernel<<<(Bn * Cn) / 64, 64>>>(kf, vf, rf, tdec, tfir, a0);

    split_w<<<wCC, 256>>>(Wo, wh, wl);
    gemm2h<1><<<gC, 512, SMEM_DYN>>>(a0, wh, wl, x1, nullptr, Cn, Cn, x, nullptr);

    // --- channel mix ---
    ln_kernel<<<Mn, 256>>>(x1, ln2w, ln2b, xn);
    mix2_h<<<mixBlocks, 256>>>(xn, cmk, cmr, a1, a2);

    split_w<<<wHC, 256>>>(Wck, wh, wl);
    gemm2h<2><<<gH, 512, SMEM_DYN>>>(a1, wh, wl, nullptr, hb, Hn, Cn, nullptr, nullptr);
    split_w<<<wHC, 256>>>(Wcv, wh, wl);
    gemm2h<0><<<gC, 512, SMEM_DYN>>>(hb, wh, wl, kv, nullptr, Cn, Hn, nullptr, nullptr);
    split_w<<<wCC, 256>>>(Wcr, wh, wl);
    gemm2h<3><<<gC, 512, SMEM_DYN>>>(a2, wh, wl, out, nullptr, Cn, Cn, x1, kv);
}

// round 6
// speedup vs baseline: 9.5238x; 1.7468x over previous
#include <cuda_runtime.h>
#include <cuda_fp16.h>
#include <math.h>
#include <stdint.h>

#define Bn 8
#define Tn 2048
#define Cn 2048
#define Hn 8192
#define Mn (Bn * Tn)   // 16384

// ---------------------------------------------------------------------------
// Scratch (device globals — allocation-free per harness rules)
// ---------------------------------------------------------------------------
__device__ float g_xn[(size_t)Mn * Cn];
__device__ float g_k [(size_t)Mn * Cn];
__device__ float g_v [(size_t)Mn * Cn];
__device__ float g_r [(size_t)Mn * Cn];
__device__ float g_x1[(size_t)Mn * Cn];
__device__ float g_kv[(size_t)Mn * Cn];
__device__ __half g_a0[(size_t)Mn * Cn];
__device__ __half g_a1[(size_t)Mn * Cn];
__device__ __half g_a2[(size_t)Mn * Cn];
__device__ __half g_h [(size_t)Mn * Hn];
__device__ __half g_w [(size_t)Hn * Cn];

// ---------------------------------------------------------------------------
// PTX helpers (baseline sm_103 — NO "a"-suffix features)
// ---------------------------------------------------------------------------
__device__ __forceinline__ uint32_t smem_u32(const void* p) {
    uint32_t a;
    asm("{ .reg .u64 t; cvta.to.shared.u64 t, %1; cvt.u32.u64 %0, t; }"
        : "=r"(a) : "l"(p));
    return a;
}

__device__ __forceinline__ void cp16(uint32_t s, const void* g) {
    asm volatile("cp.async.cg.shared.global [%0], [%1], 16;" :: "r"(s), "l"(g));
}
#define CP_COMMIT() asm volatile("cp.async.commit_group;" ::: "memory")

__device__ __forceinline__ void ldsm4(uint32_t& r0, uint32_t& r1,
                                      uint32_t& r2, uint32_t& r3, uint32_t a) {
    asm volatile("ldmatrix.sync.aligned.m8n8.x4.shared.b16 {%0,%1,%2,%3}, [%4];"
                 : "=r"(r0), "=r"(r1), "=r"(r2), "=r"(r3) : "r"(a));
}

__device__ __forceinline__ void mma16816(float* d, const uint32_t* a,
                                         const uint32_t* b) {
    asm volatile(
        "mma.sync.aligned.m16n8k16.row.col.f32.f16.f16.f32 "
        "{%0,%1,%2,%3}, {%4,%5,%6,%7}, {%8,%9}, {%0,%1,%2,%3};"
        : "+f"(d[0]), "+f"(d[1]), "+f"(d[2]), "+f"(d[3])
        : "r"(a[0]), "r"(a[1]), "r"(a[2]), "r"(a[3]), "r"(b[0]), "r"(b[1]));
}

// ---------------------------------------------------------------------------
// fp16 pack helpers
// ---------------------------------------------------------------------------
__device__ __forceinline__ uint32_t pack2h(float x, float y) {
    __half2 t = __floats2half2_rn(x, y);
    return *reinterpret_cast<uint32_t*>(&t);
}

__device__ __forceinline__ void store_h4(float4 v, __half* p, size_t idx) {
    uint2 u;
    u.x = pack2h(v.x, v.y);
    u.y = pack2h(v.z, v.w);
    *(uint2*)(p + idx) = u;
}

// ---------------------------------------------------------------------------
// LayerNorm: one block per row
// ---------------------------------------------------------------------------
__global__ __launch_bounds__(256) void ln_kernel(
    const float* __restrict__ x, const float* __restrict__ w,
    const float* __restrict__ b, float* __restrict__ out)
{
    const int row = blockIdx.x;
    const int tid = threadIdx.x;
    const float* xr = x + (size_t)row * Cn;

    float4 f0 = ((const float4*)xr)[tid];
    float4 f1 = ((const float4*)xr)[tid + 256];
    float v[8] = {f0.x, f0.y, f0.z, f0.w, f1.x, f1.y, f1.z, f1.w};

    float s = 0.f, s2 = 0.f;
#pragma unroll
    for (int i = 0; i < 8; i++) { s += v[i]; s2 += v[i] * v[i]; }
#pragma unroll
    for (int o = 16; o > 0; o >>= 1) {
        s  += __shfl_xor_sync(0xFFFFFFFFu, s,  o);
        s2 += __shfl_xor_sync(0xFFFFFFFFu, s2, o);
    }
    __shared__ float sh[16];
    const int wid = tid >> 5, lane = tid & 31;
    if (lane == 0) { sh[wid] = s; sh[wid + 8] = s2; }
    __syncthreads();
    if (tid < 32) {
        float a  = (tid < 8) ? sh[tid]     : 0.f;
        float a2 = (tid < 8) ? sh[tid + 8] : 0.f;
#pragma unroll
        for (int o = 4; o > 0; o >>= 1) {
            a  += __shfl_xor_sync(0xFFFFFFFFu, a,  o);
            a2 += __shfl_xor_sync(0xFFFFFFFFu, a2, o);
        }
        if (tid == 0) { sh[0] = a; sh[1] = a2; }
    }
    __syncthreads();

    const float mu  = sh[0] * (1.f / Cn);
    const float var = sh[1] * (1.f / Cn) - mu * mu;
    const float inv = rsqrtf(var + 1e-5f);

    float* orow = out + (size_t)row * Cn;
    const int c0 = tid * 4, c1 = (tid + 256) * 4;
    float4 o0, o1;
    o0.x = (v[0] - mu) * inv * w[c0 + 0] + b[c0 + 0];
    o0.y = (v[1] - mu) * inv * w[c0 + 1] + b[c0 + 1];
    o0.z = (v[2] - mu) * inv * w[c0 + 2] + b[c0 + 2];
    o0.w = (v[3] - mu) * inv * w[c0 + 3] + b[c0 + 3];
    o1.x = (v[4] - mu) * inv * w[c1 + 0] + b[c1 + 0];
    o1.y = (v[5] - mu) * inv * w[c1 + 1] + b[c1 + 1];
    o1.z = (v[6] - mu) * inv * w[c1 + 2] + b[c1 + 2];
    o1.w = (v[7] - mu) * inv * w[c1 + 3] + b[c1 + 3];
    ((float4*)orow)[tid]       = o0;
    ((float4*)orow)[tid + 256] = o1;
}

// ---------------------------------------------------------------------------
// Time-shift mixes → fp16
// ---------------------------------------------------------------------------
__device__ __forceinline__ float4 lerp4(float4 cur, float4 prev, float4 m) {
    float4 r;
    r.x = cur.x * m.x + prev.x * (1.f - m.x);
    r.y = cur.y * m.y + prev.y * (1.f - m.y);
    r.z = cur.z * m.z + prev.z * (1.f - m.z);
    r.w = cur.w * m.w + prev.w * (1.f - m.w);
    return r;
}

__global__ __launch_bounds__(256) void mix3_h(
    const float* __restrict__ xn,
    const float* __restrict__ tk, const float* __restrict__ tv,
    const float* __restrict__ tr,
    __half* xk, __half* xv, __half* xr)
{
    const size_t i4 = (size_t)blockIdx.x * blockDim.x + threadIdx.x;
    const size_t idx = i4 * 4;
    const int c = (int)(idx % Cn);
    const int t = (int)((idx / Cn) % Tn);
    float4 cur = *(const float4*)(xn + idx);
    float4 prev = make_float4(0.f, 0.f, 0.f, 0.f);
    if (t > 0) prev = *(const float4*)(xn + idx - Cn);
    store_h4(lerp4(cur, prev, *(const float4*)(tk + c)), xk, idx);
    store_h4(lerp4(cur, prev, *(const float4*)(tv + c)), xv, idx);
    store_h4(lerp4(cur, prev, *(const float4*)(tr + c)), xr, idx);
}

__global__ __launch_bounds__(256) void mix2_h(
    const float* __restrict__ xn,
    const float* __restrict__ tk, const float* __restrict__ tr,
    __half* ck, __half* cr)
{
    const size_t i4 = (size_t)blockIdx.x * blockDim.x + threadIdx.x;
    const size_t idx = i4 * 4;
    const int c = (int)(idx % Cn);
    const int t = (int)((idx / Cn) % Tn);
    float4 cur = *(const float4*)(xn + idx);
    float4 prev = make_float4(0.f, 0.f, 0.f, 0.f);
    if (t > 0) prev = *(const float4*)(xn + idx - Cn);
    store_h4(lerp4(cur, prev, *(const float4*)(tk + c)), ck, idx);
    store_h4(lerp4(cur, prev, *(const float4*)(tr + c)), cr, idx);
}

// Weight convert: fp32 -> fp16
__global__ __launch_bounds__(256) void conv_w(
    const float* __restrict__ w, __half* __restrict__ h)
{
    const size_t i4 = (size_t)blockIdx.x * blockDim.x + threadIdx.x;
    const size_t idx = i4 * 4;
    float4 v = *(const float4*)(w + idx);
    store_h4(v, h, idx);
}

// ---------------------------------------------------------------------------
// WKV recurrence + sigmoid(r) gate → fp16 output
// ---------------------------------------------------------------------------
__global__ __launch_bounds__(64) void wkv_gate_kernel(
    const float* __restrict__ k, const float* __restrict__ v,
    const float* __restrict__ r,
    const float* __restrict__ w_decay, const float* __restrict__ u_first,
    __half* __restrict__ g)
{
    const int idx = blockIdx.x * blockDim.x + threadIdx.x;
    const int c = idx % Cn;
    const int b = idx / Cn;
    const float w = -expf(w_decay[c]);
    const float u = u_first[c];

    float aa = 0.f, bb = 0.f, pp = -1e38f;
    size_t off = (size_t)b * Tn * Cn + c;
    for (int t = 0; t < Tn; t++, off += Cn) {
        const float kt = k[off];
        const float vt = v[off];
        const float rr = r[off];

        const float ww = u + kt;
        const float p  = fmaxf(pp, ww);
        const float e1 = __expf(pp - p);
        const float e2 = __expf(ww - p);
        const float y  = (e1 * aa + e2 * vt) / (e1 * bb + e2);
        g[off] = __float2half_rn(y / (1.f + __expf(-rr)));

        const float ww2 = pp + w;
        const float p2  = fmaxf(ww2, kt);
        const float e1b = __expf(ww2 - p2);
        const float e2b = __expf(kt - p2);
        aa = e1b * aa + e2b * vt;
        bb = e1b * bb + e2b;
        pp = p2;
    }
}

// ---------------------------------------------------------------------------
// HMMA fp16 GEMM:  C[M,N] = A[M,K] @ B[N,K]^T   (single product)
// CTA 128x256, BK=64, 16 warps (2x8), warp tile 64x32, mma.sync.m16n8k16,
// 3-stage cp.async pipeline; smem rows padded to 144B (conflict-free ldmatrix).
// EPI: 0 plain fp32; 1 +res0; 2 relu^2 -> fp16; 3 res0 + sigmoid*res1
// ---------------------------------------------------------------------------
static constexpr int ROWB   = 144;                // 64 fp16 = 128B + 16B pad
static constexpr int A_T    = 128 * ROWB;         // 18432
static constexpr int B_T    = 256 * ROWB;         // 36864
static constexpr int STAGE  = A_T + B_T;          // 55296
static constexpr int NSTAGE = 3;
static constexpr int SMEM_DYN = NSTAGE * STAGE;   // 165888

__device__ __forceinline__ void load_stage(
    uint32_t st, const __half* A, const __half* B,
    int m0, int n0, int k0, int K, int tid)
{
#pragma unroll
    for (int q = 0; q < 2; q++) {
        const int c = tid + q * 512;                 // 1024: 128 rows x 8 chunks
        const int row = c >> 3, kc = c & 7;
        cp16(st + (uint32_t)(row * ROWB + kc * 16),
             A + (size_t)(m0 + row) * K + k0 + kc * 8);
    }
#pragma unroll
    for (int q = 0; q < 4; q++) {
        const int c = tid + q * 512;                 // 2048: 256 rows x 8 chunks
        const int row = c >> 3, kc = c & 7;
        cp16(st + A_T + (uint32_t)(row * ROWB + kc * 16),
             B + (size_t)(n0 + row) * K + k0 + kc * 8);
    }
}

template <int EPI>
__global__ __launch_bounds__(512, 1) void gemm1h(
    const __half* __restrict__ A, const __half* __restrict__ B,
    float* __restrict__ Cm, __half* __restrict__ Oh,
    int N, int K,
    const float* __restrict__ res0, const float* __restrict__ res1)
{
    extern __shared__ char dsm[];
    const uint32_t sb = smem_u32(dsm);
    const int tid = threadIdx.x, wid = tid >> 5, lane = tid & 31;
    const int m0 = blockIdx.y * 128, n0 = blockIdx.x * 256;
    const int wm = wid >> 3, wn = wid & 7;   // 2 x 8 warps, warp tile 64x32

    float acc[4][4][4];
#pragma unroll
    for (int a = 0; a < 4; a++)
#pragma unroll
        for (int b = 0; b < 4; b++)
#pragma unroll
            for (int c = 0; c < 4; c++) acc[a][b][c] = 0.f;

    const int nk = K >> 6;

    load_stage(sb + 0 * STAGE, A, B, m0, n0, 0,  K, tid); CP_COMMIT();
    load_stage(sb + 1 * STAGE, A, B, m0, n0, 64, K, tid); CP_COMMIT();

    const int a_row  = wm * 64 + (lane & 15);
    const int a_koff = (lane & 16) ? 8 : 0;
    const int b_row  = wn * 32 + (lane & 7) + ((lane & 16) ? 8 : 0);
    const int b_koff = (lane & 8) ? 8 : 0;

    int sidx = 0;
    for (int i = 0; i < nk; i++) {
        if (i + 1 < nk) asm volatile("cp.async.wait_group 1;" ::: "memory");
        else            asm volatile("cp.async.wait_group 0;" ::: "memory");
        __syncthreads();

        if (i + 2 < nk) {
            int ns = sidx + 2; if (ns >= 3) ns -= 3;
            load_stage(sb + ns * STAGE, A, B, m0, n0, (i + 2) * 64, K, tid);
            CP_COMMIT();
        }

        const uint32_t st = sb + sidx * STAGE;
        if (++sidx == 3) sidx = 0;
#pragma unroll
        for (int k16 = 0; k16 < 4; k16++) {
            uint32_t ah[4][4];
            const uint32_t acol = (uint32_t)(k16 * 16 + a_koff) * 2;
#pragma unroll
            for (int mt = 0; mt < 4; mt++) {
                const uint32_t ad = st + (uint32_t)(a_row + mt * 16) * ROWB + acol;
                ldsm4(ah[mt][0], ah[mt][1], ah[mt][2], ah[mt][3], ad);
            }
            uint32_t bh[4][2];
            const uint32_t bcol = (uint32_t)(k16 * 16 + b_koff) * 2;
#pragma unroll
            for (int p = 0; p < 2; p++) {
                const uint32_t bd = st + A_T +
                                    (uint32_t)(b_row + p * 16) * ROWB + bcol;
                ldsm4(bh[2*p][0], bh[2*p][1], bh[2*p+1][0], bh[2*p+1][1], bd);
            }
#pragma unroll
            for (int mt = 0; mt < 4; mt++)
#pragma unroll
                for (int nt = 0; nt < 4; nt++)
                    mma16816(acc[mt][nt], ah[mt], bh[nt]);
        }
    }

    // Epilogue: registers -> global
    const int row_base = m0 + wm * 64 + (lane >> 2);
    const int col_base = n0 + wn * 32 + (lane & 3) * 2;
#pragma unroll
    for (int mt = 0; mt < 4; mt++) {
#pragma unroll
        for (int h = 0; h < 2; h++) {
            const int row = row_base + mt * 16 + h * 8;
#pragma unroll
            for (int nt = 0; nt < 4; nt++) {
                float vx = acc[mt][nt][2 * h + 0];
                float vy = acc[mt][nt][2 * h + 1];
                const size_t off = (size_t)row * N + col_base + nt * 8;
                if (EPI == 0) {
                    *(float2*)(Cm + off) = make_float2(vx, vy);
                } else if (EPI == 1) {
                    float2 r = *(const float2*)(res0 + off);
                    *(float2*)(Cm + off) = make_float2(vx + r.x, vy + r.y);
                } else if (EPI == 2) {
                    vx = fmaxf(vx, 0.f); vx *= vx;
                    vy = fmaxf(vy, 0.f); vy *= vy;
                    *(uint32_t*)(Oh + off) = pack2h(vx, vy);
                } else {
                    float2 r0 = *(const float2*)(res0 + off);
                    float2 r1 = *(const float2*)(res1 + off);
                    vx = r0.x + r1.x / (1.f + __expf(-vx));
                    vy = r0.y + r1.y / (1.f + __expf(-vy));
                    *(float2*)(Cm + off) = make_float2(vx, vy);
                }
            }
        }
    }
}

// ---------------------------------------------------------------------------
// Launch
// ---------------------------------------------------------------------------
extern "C" void kernel_launch(void* const* d_in, const int* in_sizes, int n_in,
                              void* d_out, int out_size)
{
    (void)in_sizes; (void)n_in; (void)out_size;
    const float* x    = (const float*)d_in[0];
    const float* ln1w = (const float*)d_in[1];
    const float* ln1b = (const float*)d_in[2];
    const float* ln2w = (const float*)d_in[3];
    const float* ln2b = (const float*)d_in[4];
    const float* tdec = (const float*)d_in[5];
    const float* tfir = (const float*)d_in[6];
    const float* tmk  = (const float*)d_in[7];
    const float* tmv  = (const float*)d_in[8];
    const float* tmr  = (const float*)d_in[9];
    const float* Wk   = (const float*)d_in[10];
    const float* Wv   = (const float*)d_in[11];
    const float* Wr   = (const float*)d_in[12];
    const float* Wo   = (const float*)d_in[13];
    const float* cmk  = (const float*)d_in[14];
    const float* cmr  = (const float*)d_in[15];
    const float* Wck  = (const float*)d_in[16];
    const float* Wcv  = (const float*)d_in[17];
    const float* Wcr  = (const float*)d_in[18];
    float* out = (float*)d_out;

    float *xn, *kf, *vf, *rf, *x1, *kv;
    __half *a0, *a1, *a2, *hb, *wh;
    cudaGetSymbolAddress((void**)&xn, g_xn);
    cudaGetSymbolAddress((void**)&kf, g_k);
    cudaGetSymbolAddress((void**)&vf, g_v);
    cudaGetSymbolAddress((void**)&rf, g_r);
    cudaGetSymbolAddress((void**)&x1, g_x1);
    cudaGetSymbolAddress((void**)&kv, g_kv);
    cudaGetSymbolAddress((void**)&a0, g_a0);
    cudaGetSymbolAddress((void**)&a1, g_a1);
    cudaGetSymbolAddress((void**)&a2, g_a2);
    cudaGetSymbolAddress((void**)&hb, g_h);
    cudaGetSymbolAddress((void**)&wh, g_w);

    cudaFuncSetAttribute(gemm1h<0>, cudaFuncAttributeMaxDynamicSharedMemorySize, SMEM_DYN);
    cudaFuncSetAttribute(gemm1h<1>, cudaFuncAttributeMaxDynamicSharedMemorySize, SMEM_DYN);
    cudaFuncSetAttribute(gemm1h<2>, cudaFuncAttributeMaxDynamicSharedMemorySize, SMEM_DYN);
    cudaFuncSetAttribute(gemm1h<3>, cudaFuncAttributeMaxDynamicSharedMemorySize, SMEM_DYN);

    const int mixBlocks = (int)(((size_t)Mn * Cn / 4) / 256);
    const int wCC = (Cn * Cn / 4) / 256;
    const int wHC = (Hn * Cn / 4) / 256;
    const dim3 gC(Cn / 256, Mn / 128);   // (8, 128)
    const dim3 gH(Hn / 256, Mn / 128);   // (32, 128)

    // --- time-mix attention ---
    ln_kernel<<<Mn, 256>>>(x, ln1w, ln1b, xn);
    mix3_h<<<mixBlocks, 256>>>(xn, tmk, tmv, tmr, a0, a1, a2);

    conv_w<<<wCC, 256>>>(Wk, wh);
    gemm1h<0><<<gC, 512, SMEM_DYN>>>(a0, wh, kf, nullptr, Cn, Cn, nullptr, nullptr);
    conv_w<<<wCC, 256>>>(Wv, wh);
    gemm1h<0><<<gC, 512, SMEM_DYN>>>(a1, wh, vf, nullptr, Cn, Cn, nullptr, nullptr);
    conv_w<<<wCC, 256>>>(Wr, wh);
    gemm1h<0><<<gC, 512, SMEM_DYN>>>(a2, wh, rf, nullptr, Cn, Cn, nullptr, nullptr);

    wkv_gate_kernel<<<(Bn * Cn) / 64, 64>>>(kf, vf, rf, tdec, tfir, a0);

    conv_w<<<wCC, 256>>>(Wo, wh);
    gemm1h<1><<<gC, 512, SMEM_DYN>>>(a0, wh, x1, nullptr, Cn, Cn, x, nullptr);

    // --- channel mix ---
    ln_kernel<<<Mn, 256>>>(x1, ln2w, ln2b, xn);
    mix2_h<<<mixBlocks, 256>>>(xn, cmk, cmr, a1, a2);

    conv_w<<<wHC, 256>>>(Wck, wh);
    gemm1h<2><<<gH, 512, SMEM_DYN>>>(a1, wh, nullptr, hb, Hn, Cn, nullptr, nullptr);
    conv_w<<<wHC, 256>>>(Wcv, wh);
    gemm1h<0><<<gC, 512, SMEM_DYN>>>(hb, wh, kv, nullptr, Cn, Hn, nullptr, nullptr);
    conv_w<<<wCC, 256>>>(Wcr, wh);
    gemm1h<3><<<gC, 512, SMEM_DYN>>>(a2, wh, out, nullptr, Cn, Cn, x1, kv);
}

// round 7
// speedup vs baseline: 11.0664x; 1.1620x over previous
#include <cuda_runtime.h>
#include <cuda_fp16.h>
#include <math.h>
#include <stdint.h>

#define Bn 8
#define Tn 2048
#define Cn 2048
#define Hn 8192
#define Mn (Bn * Tn)   // 16384

// Packed-tile geometry: rows padded to 72 halfs (144B) for conflict-free ldsm.
#define PADH 72
#define A_TILE_H (128 * PADH)       // 9216 halfs  = 18432 B  (128 rows x 64 k)
#define B_TILE_H (256 * PADH)       // 18432 halfs = 36864 B  (256 rows x 64 k)

// ---------------------------------------------------------------------------
// Scratch (device globals — allocation-free per harness rules)
// ---------------------------------------------------------------------------
__device__ float g_xn[(size_t)Mn * Cn];
__device__ float g_k [(size_t)Mn * Cn];
__device__ float g_v [(size_t)Mn * Cn];
__device__ float g_r [(size_t)Mn * Cn];
__device__ float g_x1[(size_t)Mn * Cn];
__device__ float g_kv[(size_t)Mn * Cn];
// packed fp16 activation buffers (A operands), 72/64 padding factor
__device__ __align__(128) __half g_a0[(size_t)Mn * Cn / 64 * PADH];
__device__ __align__(128) __half g_a1[(size_t)Mn * Cn / 64 * PADH];
__device__ __align__(128) __half g_a2[(size_t)Mn * Cn / 64 * PADH];
__device__ __align__(128) __half g_h [(size_t)Mn * Hn / 64 * PADH];
// packed fp16 weight buffer (B operand), max Hn*Cn elements
__device__ __align__(128) __half g_w [(size_t)Hn * Cn / 64 * PADH];

// ---------------------------------------------------------------------------
// Packed-offset helpers (half-element index)
// A layout: [m/128][k/64] tiles of 128x72;  B layout: [n/256][k/64] tiles 256x72
// ---------------------------------------------------------------------------
__device__ __forceinline__ size_t apack_off(int m, int k, int K) {
    return ((size_t)(m >> 7) * (K >> 6) + (k >> 6)) * A_TILE_H
           + (size_t)(m & 127) * PADH + (k & 63);
}
__device__ __forceinline__ size_t bpack_off(int n, int k, int K) {
    return ((size_t)(n >> 8) * (K >> 6) + (k >> 6)) * B_TILE_H
           + (size_t)(n & 255) * PADH + (k & 63);
}

// ---------------------------------------------------------------------------
// PTX helpers (baseline sm_103 — NO "a"-suffix features)
// ---------------------------------------------------------------------------
__device__ __forceinline__ uint32_t smem_u32(const void* p) {
    uint32_t a;
    asm("{ .reg .u64 t; cvta.to.shared.u64 t, %1; cvt.u32.u64 %0, t; }"
        : "=r"(a) : "l"(p));
    return a;
}

#define MBAR_INIT(mb, cnt) \
    asm volatile("mbarrier.init.shared.b64 [%0], %1;" :: "r"(mb), "r"((uint32_t)(cnt)) : "memory")

#define MBAR_EXPECT_TX(mb, bytes) \
    asm volatile("mbarrier.arrive.expect_tx.shared.b64 _, [%0], %1;" \
                 :: "r"(mb), "r"((uint32_t)(bytes)) : "memory")

#define MBAR_WAIT(mb, ph) do {                                            \
    uint32_t _m = (mb); uint32_t _p = (uint32_t)(ph); uint32_t _d;        \
    asm volatile("{ .reg .pred p;"                                        \
        " mbarrier.try_wait.parity.acquire.cta.shared::cta.b64 p, [%1], %2;" \
        " selp.b32 %0, 1, 0, p; }"                                        \
        : "=r"(_d) : "r"(_m), "r"(_p) : "memory");                        \
    if (!_d) {                                                            \
        asm volatile("{ .reg .pred P1;"                                   \
            " WL_%=:"                                                     \
            " mbarrier.try_wait.parity.acquire.cta.shared::cta.b64 P1, [%0], %1, 0x989680;" \
            " @P1 bra.uni WD_%=;"                                         \
            " bra.uni WL_%=;"                                             \
            " WD_%=: }" :: "r"(_m), "r"(_p) : "memory");                  \
    }                                                                     \
} while (0)

#define BULK_G2S(dst, src, sz, mb) \
    asm volatile("cp.async.bulk.shared::cluster.global.mbarrier::complete_tx::bytes " \
                 "[%0], [%1], %2, [%3];" \
                 :: "r"(dst), "l"(src), "r"((uint32_t)(sz)), "r"(mb) : "memory")

__device__ __forceinline__ void ldsm4(uint32_t& r0, uint32_t& r1,
                                      uint32_t& r2, uint32_t& r3, uint32_t a) {
    asm volatile("ldmatrix.sync.aligned.m8n8.x4.shared.b16 {%0,%1,%2,%3}, [%4];"
                 : "=r"(r0), "=r"(r1), "=r"(r2), "=r"(r3) : "r"(a));
}

__device__ __forceinline__ void mma16816(float* d, const uint32_t* a,
                                         const uint32_t* b) {
    asm volatile(
        "mma.sync.aligned.m16n8k16.row.col.f32.f16.f16.f32 "
        "{%0,%1,%2,%3}, {%4,%5,%6,%7}, {%8,%9}, {%0,%1,%2,%3};"
        : "+f"(d[0]), "+f"(d[1]), "+f"(d[2]), "+f"(d[3])
        : "r"(a[0]), "r"(a[1]), "r"(a[2]), "r"(a[3]), "r"(b[0]), "r"(b[1]));
}

// ---------------------------------------------------------------------------
// fp16 pack helpers
// ---------------------------------------------------------------------------
__device__ __forceinline__ uint32_t pack2h(float x, float y) {
    __half2 t = __floats2half2_rn(x, y);
    return *reinterpret_cast<uint32_t*>(&t);
}

__device__ __forceinline__ void store_h4(float4 v, __half* p, size_t idx) {
    uint2 u;
    u.x = pack2h(v.x, v.y);
    u.y = pack2h(v.z, v.w);
    *(uint2*)(p + idx) = u;
}

// ---------------------------------------------------------------------------
// LayerNorm: one block per row
// ---------------------------------------------------------------------------
__global__ __launch_bounds__(256) void ln_kernel(
    const float* __restrict__ x, const float* __restrict__ w,
    const float* __restrict__ b, float* __restrict__ out)
{
    const int row = blockIdx.x;
    const int tid = threadIdx.x;
    const float* xr = x + (size_t)row * Cn;

    float4 f0 = ((const float4*)xr)[tid];
    float4 f1 = ((const float4*)xr)[tid + 256];
    float v[8] = {f0.x, f0.y, f0.z, f0.w, f1.x, f1.y, f1.z, f1.w};

    float s = 0.f, s2 = 0.f;
#pragma unroll
    for (int i = 0; i < 8; i++) { s += v[i]; s2 += v[i] * v[i]; }
#pragma unroll
    for (int o = 16; o > 0; o >>= 1) {
        s  += __shfl_xor_sync(0xFFFFFFFFu, s,  o);
        s2 += __shfl_xor_sync(0xFFFFFFFFu, s2, o);
    }
    __shared__ float sh[16];
    const int wid = tid >> 5, lane = tid & 31;
    if (lane == 0) { sh[wid] = s; sh[wid + 8] = s2; }
    __syncthreads();
    if (tid < 32) {
        float a  = (tid < 8) ? sh[tid]     : 0.f;
        float a2 = (tid < 8) ? sh[tid + 8] : 0.f;
#pragma unroll
        for (int o = 4; o > 0; o >>= 1) {
            a  += __shfl_xor_sync(0xFFFFFFFFu, a,  o);
            a2 += __shfl_xor_sync(0xFFFFFFFFu, a2, o);
        }
        if (tid == 0) { sh[0] = a; sh[1] = a2; }
    }
    __syncthreads();

    const float mu  = sh[0] * (1.f / Cn);
    const float var = sh[1] * (1.f / Cn) - mu * mu;
    const float inv = rsqrtf(var + 1e-5f);

    float* orow = out + (size_t)row * Cn;
    const int c0 = tid * 4, c1 = (tid + 256) * 4;
    float4 o0, o1;
    o0.x = (v[0] - mu) * inv * w[c0 + 0] + b[c0 + 0];
    o0.y = (v[1] - mu) * inv * w[c0 + 1] + b[c0 + 1];
    o0.z = (v[2] - mu) * inv * w[c0 + 2] + b[c0 + 2];
    o0.w = (v[3] - mu) * inv * w[c0 + 3] + b[c0 + 3];
    o1.x = (v[4] - mu) * inv * w[c1 + 0] + b[c1 + 0];
    o1.y = (v[5] - mu) * inv * w[c1 + 1] + b[c1 + 1];
    o1.z = (v[6] - mu) * inv * w[c1 + 2] + b[c1 + 2];
    o1.w = (v[7] - mu) * inv * w[c1 + 3] + b[c1 + 3];
    ((float4*)orow)[tid]       = o0;
    ((float4*)orow)[tid + 256] = o1;
}

// ---------------------------------------------------------------------------
// Time-shift mixes → packed fp16
// ---------------------------------------------------------------------------
__device__ __forceinline__ float4 lerp4(float4 cur, float4 prev, float4 m) {
    float4 r;
    r.x = cur.x * m.x + prev.x * (1.f - m.x);
    r.y = cur.y * m.y + prev.y * (1.f - m.y);
    r.z = cur.z * m.z + prev.z * (1.f - m.z);
    r.w = cur.w * m.w + prev.w * (1.f - m.w);
    return r;
}

__global__ __launch_bounds__(256) void mix3_h(
    const float* __restrict__ xn,
    const float* __restrict__ tk, const float* __restrict__ tv,
    const float* __restrict__ tr,
    __half* xk, __half* xv, __half* xr)
{
    const size_t i4 = (size_t)blockIdx.x * blockDim.x + threadIdx.x;
    const size_t idx = i4 * 4;
    const int c = (int)(idx % Cn);
    const int m = (int)(idx / Cn);
    const int t = m % Tn;
    float4 cur = *(const float4*)(xn + idx);
    float4 prev = make_float4(0.f, 0.f, 0.f, 0.f);
    if (t > 0) prev = *(const float4*)(xn + idx - Cn);
    const size_t po = apack_off(m, c, Cn);
    store_h4(lerp4(cur, prev, *(const float4*)(tk + c)), xk, po);
    store_h4(lerp4(cur, prev, *(const float4*)(tv + c)), xv, po);
    store_h4(lerp4(cur, prev, *(const float4*)(tr + c)), xr, po);
}

__global__ __launch_bounds__(256) void mix2_h(
    const float* __restrict__ xn,
    const float* __restrict__ tk, const float* __restrict__ tr,
    __half* ck, __half* cr)
{
    const size_t i4 = (size_t)blockIdx.x * blockDim.x + threadIdx.x;
    const size_t idx = i4 * 4;
    const int c = (int)(idx % Cn);
    const int m = (int)(idx / Cn);
    const int t = m % Tn;
    float4 cur = *(const float4*)(xn + idx);
    float4 prev = make_float4(0.f, 0.f, 0.f, 0.f);
    if (t > 0) prev = *(const float4*)(xn + idx - Cn);
    const size_t po = apack_off(m, c, Cn);
    store_h4(lerp4(cur, prev, *(const float4*)(tk + c)), ck, po);
    store_h4(lerp4(cur, prev, *(const float4*)(tr + c)), cr, po);
}

// Weight convert fp32 -> packed fp16 B layout. K = inner dim of W[N,K].
__global__ __launch_bounds__(256) void conv_w(
    const float* __restrict__ w, __half* __restrict__ h, int K)
{
    const size_t i4 = (size_t)blockIdx.x * blockDim.x + threadIdx.x;
    const size_t idx = i4 * 4;
    const int n = (int)(idx / K);
    const int k = (int)(idx % K);
    float4 v = *(const float4*)(w + idx);
    store_h4(v, h, bpack_off(n, k, K));
}

// ---------------------------------------------------------------------------
// WKV recurrence + sigmoid(r) gate → packed fp16 output
// ---------------------------------------------------------------------------
__global__ __launch_bounds__(64) void wkv_gate_kernel(
    const float* __restrict__ k, const float* __restrict__ v,
    const float* __restrict__ r,
    const float* __restrict__ w_decay, const float* __restrict__ u_first,
    __half* __restrict__ g)
{
    const int idx = blockIdx.x * blockDim.x + threadIdx.x;
    const int c = idx % Cn;
    const int b = idx / Cn;
    const float w = -expf(w_decay[c]);
    const float u = u_first[c];

    float aa = 0.f, bb = 0.f, pp = -1e38f;
    size_t off = (size_t)b * Tn * Cn + c;
    int m = b * Tn;
    for (int t = 0; t < Tn; t++, off += Cn, m++) {
        const float kt = k[off];
        const float vt = v[off];
        const float rr = r[off];

        const float ww = u + kt;
        const float p  = fmaxf(pp, ww);
        const float e1 = __expf(pp - p);
        const float e2 = __expf(ww - p);
        const float y  = (e1 * aa + e2 * vt) / (e1 * bb + e2);
        g[apack_off(m, c, Cn)] = __float2half_rn(y / (1.f + __expf(-rr)));

        const float ww2 = pp + w;
        const float p2  = fmaxf(ww2, kt);
        const float e1b = __expf(ww2 - p2);
        const float e2b = __expf(kt - p2);
        aa = e1b * aa + e2b * vt;
        bb = e1b * bb + e2b;
        pp = p2;
    }
}

// ---------------------------------------------------------------------------
// HMMA fp16 GEMM over packed tiles:  C[M,N] = A[M,K] @ B[N,K]^T
// CTA 128x256, 8 warps (2x4) of 64x64, BK=64, 3-stage cp.async.bulk+mbarrier.
// EPI: 0 plain fp32; 1 +res0; 2 relu^2 -> packed fp16; 3 res0 + sigmoid*res1
// ---------------------------------------------------------------------------
static constexpr int A_T = A_TILE_H * 2;      // 18432 B
static constexpr int B_T = B_TILE_H * 2;      // 36864 B
static constexpr int STAGE = A_T + B_T;       // 55296 B
static constexpr int SMEM_DYN = 3 * STAGE;    // 165888 B

template <int EPI>
__global__ __launch_bounds__(256, 1) void gemmp(
    const __half* __restrict__ Ap, const __half* __restrict__ Bp,
    float* __restrict__ Cm, __half* __restrict__ Ohp,
    int N, int K,
    const float* __restrict__ res0, const float* __restrict__ res1)
{
    extern __shared__ __align__(128) char dsm[];
    __shared__ __align__(8) uint64_t s_mbar[3];

    const uint32_t sb = smem_u32(dsm);
    const uint32_t mb = smem_u32(s_mbar);
    const int tid = threadIdx.x, wid = tid >> 5, lane = tid & 31;
    const int m0 = blockIdx.y * 128, n0 = blockIdx.x * 256;
    const int wm = wid >> 2, wn = wid & 3;   // 2 x 4 warps of 64x64

    const int nk = K >> 6;
    const __half* gA = Ap + (size_t)blockIdx.y * nk * A_TILE_H;
    const __half* gB = Bp + (size_t)blockIdx.x * nk * B_TILE_H;

    if (tid == 0) {
        MBAR_INIT(mb + 0, 1);
        MBAR_INIT(mb + 8, 1);
        MBAR_INIT(mb + 16, 1);
    }
    __syncthreads();

    if (tid == 0) {
#pragma unroll
        for (int s = 0; s < 2; s++) {
            MBAR_EXPECT_TX(mb + s * 8, STAGE);
            BULK_G2S(sb + s * STAGE,        gA + (size_t)s * A_TILE_H, A_T, mb + s * 8);
            BULK_G2S(sb + s * STAGE + A_T,  gB + (size_t)s * B_TILE_H, B_T, mb + s * 8);
        }
    }

    float acc[4][8][4];
#pragma unroll
    for (int a = 0; a < 4; a++)
#pragma unroll
        for (int b = 0; b < 8; b++)
#pragma unroll
            for (int c = 0; c < 4; c++) acc[a][b][c] = 0.f;

    const int a_row  = wm * 64 + (lane & 15);
    const int a_koff = (lane & 16) ? 8 : 0;
    const int b_row  = wn * 64 + (lane & 7) + ((lane & 16) ? 8 : 0);
    const int b_koff = (lane & 8) ? 8 : 0;

    int s = 0;
    uint32_t par = 0;
    for (int i = 0; i < nk; i++) {
        MBAR_WAIT(mb + s * 8, (par >> s) & 1u);
        par ^= (1u << s);
        __syncthreads();

        if (tid == 0 && i + 2 < nk) {
            int ns = s + 2; if (ns >= 3) ns -= 3;
            MBAR_EXPECT_TX(mb + ns * 8, STAGE);
            BULK_G2S(sb + ns * STAGE,       gA + (size_t)(i + 2) * A_TILE_H, A_T, mb + ns * 8);
            BULK_G2S(sb + ns * STAGE + A_T, gB + (size_t)(i + 2) * B_TILE_H, B_T, mb + ns * 8);
        }

        const uint32_t st = sb + s * STAGE;
        if (++s == 3) s = 0;
#pragma unroll
        for (int k16 = 0; k16 < 4; k16++) {
            uint32_t ah[4][4];
            const uint32_t acol = (uint32_t)(k16 * 16 + a_koff) * 2;
#pragma unroll
            for (int mt = 0; mt < 4; mt++) {
                const uint32_t ad = st + (uint32_t)(a_row + mt * 16) * (PADH * 2) + acol;
                ldsm4(ah[mt][0], ah[mt][1], ah[mt][2], ah[mt][3], ad);
            }
            uint32_t bh[8][2];
            const uint32_t bcol = (uint32_t)(k16 * 16 + b_koff) * 2;
#pragma unroll
            for (int p = 0; p < 4; p++) {
                const uint32_t bd = st + A_T +
                                    (uint32_t)(b_row + p * 16) * (PADH * 2) + bcol;
                ldsm4(bh[2*p][0], bh[2*p][1], bh[2*p+1][0], bh[2*p+1][1], bd);
            }
#pragma unroll
            for (int mt = 0; mt < 4; mt++)
#pragma unroll
                for (int nt = 0; nt < 8; nt++)
                    mma16816(acc[mt][nt], ah[mt], bh[nt]);
        }
    }

    // Epilogue: registers -> global
    const int row_base = m0 + wm * 64 + (lane >> 2);
    const int col_base = n0 + wn * 64 + (lane & 3) * 2;
#pragma unroll
    for (int mt = 0; mt < 4; mt++) {
#pragma unroll
        for (int h = 0; h < 2; h++) {
            const int row = row_base + mt * 16 + h * 8;
#pragma unroll
            for (int nt = 0; nt < 8; nt++) {
                float vx = acc[mt][nt][2 * h + 0];
                float vy = acc[mt][nt][2 * h + 1];
                const int col = col_base + nt * 8;
                const size_t off = (size_t)row * N + col;
                if (EPI == 0) {
                    *(float2*)(Cm + off) = make_float2(vx, vy);
                } else if (EPI == 1) {
                    float2 r = *(const float2*)(res0 + off);
                    *(float2*)(Cm + off) = make_float2(vx + r.x, vy + r.y);
                } else if (EPI == 2) {
                    vx = fmaxf(vx, 0.f); vx *= vx;
                    vy = fmaxf(vy, 0.f); vy *= vy;
                    *(uint32_t*)(Ohp + apack_off(row, col, N)) = pack2h(vx, vy);
                } else {
                    float2 r0 = *(const float2*)(res0 + off);
                    float2 r1 = *(const float2*)(res1 + off);
                    vx = r0.x + r1.x / (1.f + __expf(-vx));
                    vy = r0.y + r1.y / (1.f + __expf(-vy));
                    *(float2*)(Cm + off) = make_float2(vx, vy);
                }
            }
        }
    }
}

// ---------------------------------------------------------------------------
// Launch
// ---------------------------------------------------------------------------
extern "C" void kernel_launch(void* const* d_in, const int* in_sizes, int n_in,
                              void* d_out, int out_size)
{
    (void)in_sizes; (void)n_in; (void)out_size;
    const float* x    = (const float*)d_in[0];
    const float* ln1w = (const float*)d_in[1];
    const float* ln1b = (const float*)d_in[2];
    const float* ln2w = (const float*)d_in[3];
    const float* ln2b = (const float*)d_in[4];
    const float* tdec = (const float*)d_in[5];
    const float* tfir = (const float*)d_in[6];
    const float* tmk  = (const float*)d_in[7];
    const float* tmv  = (const float*)d_in[8];
    const float* tmr  = (const float*)d_in[9];
    const float* Wk   = (const float*)d_in[10];
    const float* Wv   = (const float*)d_in[11];
    const float* Wr   = (const float*)d_in[12];
    const float* Wo   = (const float*)d_in[13];
    const float* cmk  = (const float*)d_in[14];
    const float* cmr  = (const float*)d_in[15];
    const float* Wck  = (const float*)d_in[16];
    const float* Wcv  = (const float*)d_in[17];
    const float* Wcr  = (const float*)d_in[18];
    float* out = (float*)d_out;

    float *xn, *kf, *vf, *rf, *x1, *kv;
    __half *a0, *a1, *a2, *hb, *wp;
    cudaGetSymbolAddress((void**)&xn, g_xn);
    cudaGetSymbolAddress((void**)&kf, g_k);
    cudaGetSymbolAddress((void**)&vf, g_v);
    cudaGetSymbolAddress((void**)&rf, g_r);
    cudaGetSymbolAddress((void**)&x1, g_x1);
    cudaGetSymbolAddress((void**)&kv, g_kv);
    cudaGetSymbolAddress((void**)&a0, g_a0);
    cudaGetSymbolAddress((void**)&a1, g_a1);
    cudaGetSymbolAddress((void**)&a2, g_a2);
    cudaGetSymbolAddress((void**)&hb, g_h);
    cudaGetSymbolAddress((void**)&wp, g_w);

    cudaFuncSetAttribute(gemmp<0>, cudaFuncAttributeMaxDynamicSharedMemorySize, SMEM_DYN);
    cudaFuncSetAttribute(gemmp<1>, cudaFuncAttributeMaxDynamicSharedMemorySize, SMEM_DYN);
    cudaFuncSetAttribute(gemmp<2>, cudaFuncAttributeMaxDynamicSharedMemorySize, SMEM_DYN);
    cudaFuncSetAttribute(gemmp<3>, cudaFuncAttributeMaxDynamicSharedMemorySize, SMEM_DYN);

    const int mixBlocks = (int)(((size_t)Mn * Cn / 4) / 256);
    const int wCC = (Cn * Cn / 4) / 256;
    const int wHC = (Hn * Cn / 4) / 256;
    const dim3 gC(Cn / 256, Mn / 128);   // (8, 128)
    const dim3 gH(Hn / 256, Mn / 128);   // (32, 128)

    // --- time-mix attention ---
    ln_kernel<<<Mn, 256>>>(x, ln1w, ln1b, xn);
    mix3_h<<<mixBlocks, 256>>>(xn, tmk, tmv, tmr, a0, a1, a2);

    conv_w<<<wCC, 256>>>(Wk, wp, Cn);
    gemmp<0><<<gC, 256, SMEM_DYN>>>(a0, wp, kf, nullptr, Cn, Cn, nullptr, nullptr);
    conv_w<<<wCC, 256>>>(Wv, wp, Cn);
    gemmp<0><<<gC, 256, SMEM_DYN>>>(a1, wp, vf, nullptr, Cn, Cn, nullptr, nullptr);
    conv_w<<<wCC, 256>>>(Wr, wp, Cn);
    gemmp<0><<<gC, 256, SMEM_DYN>>>(a2, wp, rf, nullptr, Cn, Cn, nullptr, nullptr);

    wkv_gate_kernel<<<(Bn * Cn) / 64, 64>>>(kf, vf, rf, tdec, tfir, a0);

    conv_w<<<wCC, 256>>>(Wo, wp, Cn);
    gemmp<1><<<gC, 256, SMEM_DYN>>>(a0, wp, x1, nullptr, Cn, Cn, x, nullptr);

    // --- channel mix ---
    ln_kernel<<<Mn, 256>>>(x1, ln2w, ln2b, xn);
    mix2_h<<<mixBlocks, 256>>>(xn, cmk, cmr, a1, a2);

    conv_w<<<wHC, 256>>>(Wck, wp, Cn);
    gemmp<2><<<gH, 256, SMEM_DYN>>>(a1, wp, nullptr, hb, Hn, Cn, nullptr, nullptr);
    conv_w<<<wHC, 256>>>(Wcv, wp, Hn);
    gemmp<0><<<gC, 256, SMEM_DYN>>>(hb, wp, kv, nullptr, Cn, Hn, nullptr, nullptr);
    conv_w<<<wCC, 256>>>(Wcr, wp, Cn);
    gemmp<3><<<gC, 256, SMEM_DYN>>>(a2, wp, out, nullptr, Cn, Cn, x1, kv);
}

// round 8
// speedup vs baseline: 11.6350x; 1.0514x over previous
#include <cuda_runtime.h>
#include <cuda_fp16.h>
#include <math.h>
#include <stdint.h>

#define Bn 8
#define Tn 2048
#define Cn 2048
#define Hn 8192
#define Mn (Bn * Tn)   // 16384

// Packed-tile geometry: rows padded to 72 halfs (144B) for conflict-free ldsm.
#define PADH 72
#define A_TILE_H (128 * PADH)       // halfs per 128x64 A tile
#define B_TILE_H (256 * PADH)       // halfs per 256x64 B tile

// ---------------------------------------------------------------------------
// Scratch (device globals — allocation-free per harness rules)
// ---------------------------------------------------------------------------
__device__ float g_k [(size_t)Mn * Cn];
__device__ float g_v [(size_t)Mn * Cn];
__device__ float g_x1[(size_t)Mn * Cn];
__device__ float g_kv[(size_t)Mn * Cn];
__device__ __align__(128) __half g_a0[(size_t)Mn * Cn / 64 * PADH];
__device__ __align__(128) __half g_a1[(size_t)Mn * Cn / 64 * PADH];
__device__ __align__(128) __half g_a2[(size_t)Mn * Cn / 64 * PADH];
__device__ __align__(128) __half g_h [(size_t)Mn * Hn / 64 * PADH];
__device__ __align__(128) __half g_w [(size_t)Hn * Cn / 64 * PADH];

// ---------------------------------------------------------------------------
// Packed-offset helpers (half-element index)
// ---------------------------------------------------------------------------
__device__ __forceinline__ size_t apack_off(int m, int k, int K) {
    return ((size_t)(m >> 7) * (K >> 6) + (k >> 6)) * A_TILE_H
           + (size_t)(m & 127) * PADH + (k & 63);
}
__device__ __forceinline__ size_t bpack_off(int n, int k, int K) {
    return ((size_t)(n >> 8) * (K >> 6) + (k >> 6)) * B_TILE_H
           + (size_t)(n & 255) * PADH + (k & 63);
}

// ---------------------------------------------------------------------------
// PTX helpers (baseline sm_103 — NO "a"-suffix features)
// ---------------------------------------------------------------------------
__device__ __forceinline__ uint32_t smem_u32(const void* p) {
    uint32_t a;
    asm("{ .reg .u64 t; cvta.to.shared.u64 t, %1; cvt.u32.u64 %0, t; }"
        : "=r"(a) : "l"(p));
    return a;
}

#define MBAR_INIT(mb, cnt) \
    asm volatile("mbarrier.init.shared.b64 [%0], %1;" :: "r"(mb), "r"((uint32_t)(cnt)) : "memory")

#define MBAR_EXPECT_TX(mb, bytes) \
    asm volatile("mbarrier.arrive.expect_tx.shared.b64 _, [%0], %1;" \
                 :: "r"(mb), "r"((uint32_t)(bytes)) : "memory")

#define MBAR_WAIT(mb, ph) do {                                            \
    uint32_t _m = (mb); uint32_t _p = (uint32_t)(ph); uint32_t _d;        \
    asm volatile("{ .reg .pred p;"                                        \
        " mbarrier.try_wait.parity.acquire.cta.shared::cta.b64 p, [%1], %2;" \
        " selp.b32 %0, 1, 0, p; }"                                        \
        : "=r"(_d) : "r"(_m), "r"(_p) : "memory");                        \
    if (!_d) {                                                            \
        asm volatile("{ .reg .pred P1;"                                   \
            " WL_%=:"                                                     \
            " mbarrier.try_wait.parity.acquire.cta.shared::cta.b64 P1, [%0], %1, 0x989680;" \
            " @P1 bra.uni WD_%=;"                                         \
            " bra.uni WL_%=;"                                             \
            " WD_%=: }" :: "r"(_m), "r"(_p) : "memory");                  \
    }                                                                     \
} while (0)

#define BULK_G2S(dst, src, sz, mb) \
    asm volatile("cp.async.bulk.shared::cluster.global.mbarrier::complete_tx::bytes " \
                 "[%0], [%1], %2, [%3];" \
                 :: "r"(dst), "l"(src), "r"((uint32_t)(sz)), "r"(mb) : "memory")

__device__ __forceinline__ void ldsm4(uint32_t& r0, uint32_t& r1,
                                      uint32_t& r2, uint32_t& r3, uint32_t a) {
    asm volatile("ldmatrix.sync.aligned.m8n8.x4.shared.b16 {%0,%1,%2,%3}, [%4];"
                 : "=r"(r0), "=r"(r1), "=r"(r2), "=r"(r3) : "r"(a));
}

__device__ __forceinline__ void mma16816(float* d, const uint32_t* a,
                                         const uint32_t* b) {
    asm volatile(
        "mma.sync.aligned.m16n8k16.row.col.f32.f16.f16.f32 "
        "{%0,%1,%2,%3}, {%4,%5,%6,%7}, {%8,%9}, {%0,%1,%2,%3};"
        : "+f"(d[0]), "+f"(d[1]), "+f"(d[2]), "+f"(d[3])
        : "r"(a[0]), "r"(a[1]), "r"(a[2]), "r"(a[3]), "r"(b[0]), "r"(b[1]));
}

// ---------------------------------------------------------------------------
// fp16 pack helpers
// ---------------------------------------------------------------------------
__device__ __forceinline__ uint32_t pack2h(float x, float y) {
    __half2 t = __floats2half2_rn(x, y);
    return *reinterpret_cast<uint32_t*>(&t);
}

__device__ __forceinline__ void store_h4(float4 v, __half* p, size_t idx) {
    uint2 u;
    u.x = pack2h(v.x, v.y);
    u.y = pack2h(v.z, v.w);
    *(uint2*)(p + idx) = u;
}

__device__ __forceinline__ float4 lerp4(float4 cur, float4 prev, float4 m) {
    float4 r;
    r.x = cur.x * m.x + prev.x * (1.f - m.x);
    r.y = cur.y * m.y + prev.y * (1.f - m.y);
    r.z = cur.z * m.z + prev.z * (1.f - m.z);
    r.w = cur.w * m.w + prev.w * (1.f - m.w);
    return r;
}

// ---------------------------------------------------------------------------
// Fused LayerNorm + time-shift mix → packed fp16.
// Each block handles row m: computes LN stats for row m AND row m-1,
// then mixes; t==0 mixes with zero.
// ---------------------------------------------------------------------------
template <int NOUT>
__global__ __launch_bounds__(256) void ln_mix(
    const float* __restrict__ x, const float* __restrict__ w,
    const float* __restrict__ b,
    const float* __restrict__ m0p, const float* __restrict__ m1p,
    const float* __restrict__ m2p,
    __half* __restrict__ o0, __half* __restrict__ o1, __half* __restrict__ o2)
{
    const int row = blockIdx.x;
    const int t = row % Tn;
    const int tid = threadIdx.x;
    const float* xr = x + (size_t)row * Cn;

    float4 f0 = ((const float4*)xr)[tid];
    float4 f1 = ((const float4*)xr)[tid + 256];
    float v[8] = {f0.x, f0.y, f0.z, f0.w, f1.x, f1.y, f1.z, f1.w};
    float p[8] = {0.f, 0.f, 0.f, 0.f, 0.f, 0.f, 0.f, 0.f};
    if (t > 0) {
        const float* pr = xr - Cn;
        float4 g0 = ((const float4*)pr)[tid];
        float4 g1 = ((const float4*)pr)[tid + 256];
        p[0]=g0.x; p[1]=g0.y; p[2]=g0.z; p[3]=g0.w;
        p[4]=g1.x; p[5]=g1.y; p[6]=g1.z; p[7]=g1.w;
    }

    float sc = 0.f, sc2 = 0.f, sp = 0.f, sp2 = 0.f;
#pragma unroll
    for (int i = 0; i < 8; i++) {
        sc += v[i]; sc2 += v[i] * v[i];
        sp += p[i]; sp2 += p[i] * p[i];
    }
#pragma unroll
    for (int o = 16; o > 0; o >>= 1) {
        sc  += __shfl_xor_sync(0xFFFFFFFFu, sc,  o);
        sc2 += __shfl_xor_sync(0xFFFFFFFFu, sc2, o);
        sp  += __shfl_xor_sync(0xFFFFFFFFu, sp,  o);
        sp2 += __shfl_xor_sync(0xFFFFFFFFu, sp2, o);
    }
    __shared__ float sh[32];
    const int wid = tid >> 5, lane = tid & 31;
    if (lane == 0) {
        sh[wid] = sc; sh[wid + 8] = sc2; sh[wid + 16] = sp; sh[wid + 24] = sp2;
    }
    __syncthreads();
    if (tid < 32) {
        const int g = tid >> 3, l = tid & 7;   // 4 groups of 8
        float a = sh[g * 8 + l];
#pragma unroll
        for (int o = 4; o > 0; o >>= 1)
            a += __shfl_xor_sync(0xFFFFFFFFu, a, o);
        if (l == 0) sh[g] = a;
    }
    __syncthreads();

    const float mu_c  = sh[0] * (1.f / Cn);
    const float inv_c = rsqrtf(sh[1] * (1.f / Cn) - mu_c * mu_c + 1e-5f);
    const float mu_p  = sh[2] * (1.f / Cn);
    const float inv_p = rsqrtf(sh[3] * (1.f / Cn) - mu_p * mu_p + 1e-5f);

#pragma unroll
    for (int j = 0; j < 2; j++) {
        const int c = (tid + j * 256) * 4;
        float4 xn4, xx4;
        const float* vv = v + j * 4;
        const float* pp = p + j * 4;
        xn4.x = (vv[0] - mu_c) * inv_c * w[c + 0] + b[c + 0];
        xn4.y = (vv[1] - mu_c) * inv_c * w[c + 1] + b[c + 1];
        xn4.z = (vv[2] - mu_c) * inv_c * w[c + 2] + b[c + 2];
        xn4.w = (vv[3] - mu_c) * inv_c * w[c + 3] + b[c + 3];
        if (t > 0) {
            xx4.x = (pp[0] - mu_p) * inv_p * w[c + 0] + b[c + 0];
            xx4.y = (pp[1] - mu_p) * inv_p * w[c + 1] + b[c + 1];
            xx4.z = (pp[2] - mu_p) * inv_p * w[c + 2] + b[c + 2];
            xx4.w = (pp[3] - mu_p) * inv_p * w[c + 3] + b[c + 3];
        } else {
            xx4 = make_float4(0.f, 0.f, 0.f, 0.f);
        }
        const size_t po = apack_off(row, c, Cn);
        store_h4(lerp4(xn4, xx4, *(const float4*)(m0p + c)), o0, po);
        store_h4(lerp4(xn4, xx4, *(const float4*)(m1p + c)), o1, po);
        if (NOUT == 3)
            store_h4(lerp4(xn4, xx4, *(const float4*)(m2p + c)), o2, po);
    }
}

// Weight convert fp32 -> packed fp16 B layout. K = inner dim of W[N,K].
__global__ __launch_bounds__(256) void conv_w(
    const float* __restrict__ w, __half* __restrict__ h, int K)
{
    const size_t i4 = (size_t)blockIdx.x * blockDim.x + threadIdx.x;
    const size_t idx = i4 * 4;
    const int n = (int)(idx / K);
    const int k = (int)(idx % K);
    float4 v = *(const float4*)(w + idx);
    store_h4(v, h, bpack_off(n, k, K));
}

// ---------------------------------------------------------------------------
// WKV recurrence + sigmoid(r) gate; r packed fp16 in, g packed fp16 out.
// ---------------------------------------------------------------------------
__global__ __launch_bounds__(64) void wkv_gate_kernel(
    const float* __restrict__ k, const float* __restrict__ v,
    const __half* __restrict__ rp,
    const float* __restrict__ w_decay, const float* __restrict__ u_first,
    __half* __restrict__ g)
{
    const int idx = blockIdx.x * blockDim.x + threadIdx.x;
    const int c = idx % Cn;
    const int b = idx / Cn;
    const float w = -expf(w_decay[c]);
    const float u = u_first[c];

    float aa = 0.f, bb = 0.f, pp = -1e38f;
    size_t off = (size_t)b * Tn * Cn + c;
    int m = b * Tn;
    for (int t = 0; t < Tn; t++, off += Cn, m++) {
        const float kt = k[off];
        const float vt = v[off];
        const size_t po = apack_off(m, c, Cn);
        const float rr = __half2float(rp[po]);

        const float ww = u + kt;
        const float pmx = fmaxf(pp, ww);
        const float e1 = __expf(pp - pmx);
        const float e2 = __expf(ww - pmx);
        const float y  = (e1 * aa + e2 * vt) / (e1 * bb + e2);
        g[po] = __float2half_rn(y / (1.f + __expf(-rr)));

        const float ww2 = pp + w;
        const float p2  = fmaxf(ww2, kt);
        const float e1b = __expf(ww2 - p2);
        const float e2b = __expf(kt - p2);
        aa = e1b * aa + e2b * vt;
        bb = e1b * bb + e2b;
        pp = p2;
    }
}

// ---------------------------------------------------------------------------
// HMMA fp16 GEMM over packed tiles:  C[M,N] = A[M,K] @ B[N,K]^T
// CTA 128x256, 8 warps (2x4) of 64x64, BK=128, 2-stage cp.async.bulk+mbarrier.
// EPI: 0 fp32; 1 +res0; 2 relu^2 -> packed fp16; 3 res0 + sigmoid*res1;
//      4 packed fp16 (plain)
// ---------------------------------------------------------------------------
static constexpr int AT64 = A_TILE_H * 2;     // 18432 B (one 64-k A tile)
static constexpr int BT64 = B_TILE_H * 2;     // 36864 B (one 64-k B tile)
static constexpr int STAGE = 2 * (AT64 + BT64);   // 110592 B (BK=128)
static constexpr int SMEM_DYN = 2 * STAGE;        // 221184 B

template <int EPI>
__global__ __launch_bounds__(256, 1) void gemmp(
    const __half* __restrict__ Ap, const __half* __restrict__ Bp,
    float* __restrict__ Cm, __half* __restrict__ Ohp,
    int N, int K,
    const float* __restrict__ res0, const float* __restrict__ res1)
{
    extern __shared__ __align__(128) char dsm[];
    __shared__ __align__(8) uint64_t s_mbar[2];

    const uint32_t sb = smem_u32(dsm);
    const uint32_t mb = smem_u32(s_mbar);
    const int tid = threadIdx.x, wid = tid >> 5, lane = tid & 31;
    const int m0 = blockIdx.y * 128, n0 = blockIdx.x * 256;
    const int wm = wid >> 2, wn = wid & 3;   // 2 x 4 warps of 64x64

    const int nk = K >> 7;                   // BK = 128
    const __half* gA = Ap + (size_t)blockIdx.y * (K >> 6) * A_TILE_H;
    const __half* gB = Bp + (size_t)blockIdx.x * (K >> 6) * B_TILE_H;

    if (tid == 0) {
        MBAR_INIT(mb + 0, 1);
        MBAR_INIT(mb + 8, 1);
    }
    __syncthreads();

    if (tid == 0) {
#pragma unroll
        for (int s = 0; s < 2; s++) {
            MBAR_EXPECT_TX(mb + s * 8, STAGE);
            BULK_G2S(sb + s * STAGE,
                     gA + (size_t)s * 2 * A_TILE_H, 2 * AT64, mb + s * 8);
            BULK_G2S(sb + s * STAGE + 2 * AT64,
                     gB + (size_t)s * 2 * B_TILE_H, 2 * BT64, mb + s * 8);
        }
    }

    float acc[4][8][4];
#pragma unroll
    for (int a = 0; a < 4; a++)
#pragma unroll
        for (int b = 0; b < 8; b++)
#pragma unroll
            for (int c = 0; c < 4; c++) acc[a][b][c] = 0.f;

    const int a_row  = wm * 64 + (lane & 15);
    const int a_koff = (lane & 16) ? 8 : 0;
    const int b_row  = wn * 64 + (lane & 7) + ((lane & 16) ? 8 : 0);
    const int b_koff = (lane & 8) ? 8 : 0;

    int s = 0;
    uint32_t par = 0;
    for (int i = 0; i < nk; i++) {
        MBAR_WAIT(mb + s * 8, (par >> s) & 1u);
        par ^= (1u << s);

        const uint32_t st = sb + s * STAGE;
#pragma unroll
        for (int half = 0; half < 2; half++) {
            const uint32_t abase = st + half * AT64;
            const uint32_t bbase = st + 2 * AT64 + half * BT64;
#pragma unroll
            for (int k16 = 0; k16 < 4; k16++) {
                uint32_t ah[4][4];
                const uint32_t acol = (uint32_t)(k16 * 16 + a_koff) * 2;
#pragma unroll
                for (int mt = 0; mt < 4; mt++) {
                    const uint32_t ad = abase +
                        (uint32_t)(a_row + mt * 16) * (PADH * 2) + acol;
                    ldsm4(ah[mt][0], ah[mt][1], ah[mt][2], ah[mt][3], ad);
                }
                uint32_t bh[8][2];
                const uint32_t bcol = (uint32_t)(k16 * 16 + b_koff) * 2;
#pragma unroll
                for (int pq = 0; pq < 4; pq++) {
                    const uint32_t bd = bbase +
                        (uint32_t)(b_row + pq * 16) * (PADH * 2) + bcol;
                    ldsm4(bh[2*pq][0], bh[2*pq][1], bh[2*pq+1][0], bh[2*pq+1][1], bd);
                }
#pragma unroll
                for (int mt = 0; mt < 4; mt++)
#pragma unroll
                    for (int nt = 0; nt < 8; nt++)
                        mma16816(acc[mt][nt], ah[mt], bh[nt]);
            }
        }

        __syncthreads();
        if (tid == 0 && i + 2 < nk) {
            MBAR_EXPECT_TX(mb + s * 8, STAGE);
            BULK_G2S(sb + s * STAGE,
                     gA + (size_t)(i + 2) * 2 * A_TILE_H, 2 * AT64, mb + s * 8);
            BULK_G2S(sb + s * STAGE + 2 * AT64,
                     gB + (size_t)(i + 2) * 2 * B_TILE_H, 2 * BT64, mb + s * 8);
        }
        s ^= 1;
    }

    // Epilogue: registers -> global
    const int row_base = m0 + wm * 64 + (lane >> 2);
    const int col_base = n0 + wn * 64 + (lane & 3) * 2;
#pragma unroll
    for (int mt = 0; mt < 4; mt++) {
#pragma unroll
        for (int h = 0; h < 2; h++) {
            const int row = row_base + mt * 16 + h * 8;
#pragma unroll
            for (int nt = 0; nt < 8; nt++) {
                float vx = acc[mt][nt][2 * h + 0];
                float vy = acc[mt][nt][2 * h + 1];
                const int col = col_base + nt * 8;
                const size_t off = (size_t)row * N + col;
                if (EPI == 0) {
                    *(float2*)(Cm + off) = make_float2(vx, vy);
                } else if (EPI == 1) {
                    float2 r = *(const float2*)(res0 + off);
                    *(float2*)(Cm + off) = make_float2(vx + r.x, vy + r.y);
                } else if (EPI == 2) {
                    vx = fmaxf(vx, 0.f); vx *= vx;
                    vy = fmaxf(vy, 0.f); vy *= vy;
                    *(uint32_t*)(Ohp + apack_off(row, col, N)) = pack2h(vx, vy);
                } else if (EPI == 4) {
                    *(uint32_t*)(Ohp + apack_off(row, col, N)) = pack2h(vx, vy);
                } else {
                    float2 r0 = *(const float2*)(res0 + off);
                    float2 r1 = *(const float2*)(res1 + off);
                    vx = r0.x + r1.x / (1.f + __expf(-vx));
                    vy = r0.y + r1.y / (1.f + __expf(-vy));
                    *(float2*)(Cm + off) = make_float2(vx, vy);
                }
            }
        }
    }
}

// ---------------------------------------------------------------------------
// Launch
// ---------------------------------------------------------------------------
extern "C" void kernel_launch(void* const* d_in, const int* in_sizes, int n_in,
                              void* d_out, int out_size)
{
    (void)in_sizes; (void)n_in; (void)out_size;
    const float* x    = (const float*)d_in[0];
    const float* ln1w = (const float*)d_in[1];
    const float* ln1b = (const float*)d_in[2];
    const float* ln2w = (const float*)d_in[3];
    const float* ln2b = (const float*)d_in[4];
    const float* tdec = (const float*)d_in[5];
    const float* tfir = (const float*)d_in[6];
    const float* tmk  = (const float*)d_in[7];
    const float* tmv  = (const float*)d_in[8];
    const float* tmr  = (const float*)d_in[9];
    const float* Wk   = (const float*)d_in[10];
    const float* Wv   = (const float*)d_in[11];
    const float* Wr   = (const float*)d_in[12];
    const float* Wo   = (const float*)d_in[13];
    const float* cmk  = (const float*)d_in[14];
    const float* cmr  = (const float*)d_in[15];
    const float* Wck  = (const float*)d_in[16];
    const float* Wcv  = (const float*)d_in[17];
    const float* Wcr  = (const float*)d_in[18];
    float* out = (float*)d_out;

    float *kf, *vf, *x1, *kv;
    __half *a0, *a1, *a2, *hb, *wp;
    cudaGetSymbolAddress((void**)&kf, g_k);
    cudaGetSymbolAddress((void**)&vf, g_v);
    cudaGetSymbolAddress((void**)&x1, g_x1);
    cudaGetSymbolAddress((void**)&kv, g_kv);
    cudaGetSymbolAddress((void**)&a0, g_a0);
    cudaGetSymbolAddress((void**)&a1, g_a1);
    cudaGetSymbolAddress((void**)&a2, g_a2);
    cudaGetSymbolAddress((void**)&hb, g_h);
    cudaGetSymbolAddress((void**)&wp, g_w);

    cudaFuncSetAttribute(gemmp<0>, cudaFuncAttributeMaxDynamicSharedMemorySize, SMEM_DYN);
    cudaFuncSetAttribute(gemmp<1>, cudaFuncAttributeMaxDynamicSharedMemorySize, SMEM_DYN);
    cudaFuncSetAttribute(gemmp<2>, cudaFuncAttributeMaxDynamicSharedMemorySize, SMEM_DYN);
    cudaFuncSetAttribute(gemmp<3>, cudaFuncAttributeMaxDynamicSharedMemorySize, SMEM_DYN);
    cudaFuncSetAttribute(gemmp<4>, cudaFuncAttributeMaxDynamicSharedMemorySize, SMEM_DYN);

    const int wCC = (Cn * Cn / 4) / 256;
    const int wHC = (Hn * Cn / 4) / 256;
    const dim3 gC(Cn / 256, Mn / 128);   // (8, 128)
    const dim3 gH(Hn / 256, Mn / 128);   // (32, 128)

    // --- time-mix attention ---
    ln_mix<3><<<Mn, 256>>>(x, ln1w, ln1b, tmk, tmv, tmr, a0, a1, a2);

    conv_w<<<wCC, 256>>>(Wk, wp, Cn);
    gemmp<0><<<gC, 256, SMEM_DYN>>>(a0, wp, kf, nullptr, Cn, Cn, nullptr, nullptr);
    conv_w<<<wCC, 256>>>(Wv, wp, Cn);
    gemmp<0><<<gC, 256, SMEM_DYN>>>(a1, wp, vf, nullptr, Cn, Cn, nullptr, nullptr);
    conv_w<<<wCC, 256>>>(Wr, wp, Cn);
    gemmp<4><<<gC, 256, SMEM_DYN>>>(a2, wp, nullptr, a0, Cn, Cn, nullptr, nullptr);

    wkv_gate_kernel<<<(Bn * Cn) / 64, 64>>>(kf, vf, a0, tdec, tfir, a1);

    conv_w<<<wCC, 256>>>(Wo, wp, Cn);
    gemmp<1><<<gC, 256, SMEM_DYN>>>(a1, wp, x1, nullptr, Cn, Cn, x, nullptr);

    // --- channel mix ---
    ln_mix<2><<<Mn, 256>>>(x1, ln2w, ln2b, cmk, cmr, nullptr, a0, a2, nullptr);

    conv_w<<<wHC, 256>>>(Wck, wp, Cn);
    gemmp<2><<<gH, 256, SMEM_DYN>>>(a0, wp, nullptr, hb, Hn, Cn, nullptr, nullptr);
    conv_w<<<wHC, 256>>>(Wcv, wp, Hn);
    gemmp<0><<<gC, 256, SMEM_DYN>>>(hb, wp, kv, nullptr, Cn, Hn, nullptr, nullptr);
    conv_w<<<wCC, 256>>>(Wcr, wp, Cn);
    gemmp<3><<<gC, 256, SMEM_DYN>>>(a2, wp, out, nullptr, Cn, Cn, x1, kv);
}

// round 10
// speedup vs baseline: 13.9403x; 1.1981x over previous
#include <cuda_runtime.h>
#include <cuda_fp16.h>
#include <math.h>
#include <stdint.h>

#define Bn 8
#define Tn 2048
#define Cn 2048
#define Hn 8192
#define Mn (Bn * Tn)   // 16384

// Packed-tile geometry: rows padded to 72 halfs (144B) for conflict-free ldsm.
#define PADH 72
#define A_TILE_H (128 * PADH)       // halfs per 128x64 A tile
#define B_TILE_H (256 * PADH)       // halfs per 256x64 B tile

// ---------------------------------------------------------------------------
// Scratch (device globals — allocation-free per harness rules)
// ---------------------------------------------------------------------------
__device__ float g_k [(size_t)Mn * Cn];
__device__ float g_v [(size_t)Mn * Cn];
__device__ float g_x1[(size_t)Mn * Cn];
__device__ float g_kv[(size_t)Mn * Cn];
__device__ __align__(128) __half g_a0[(size_t)Mn * Cn / 64 * PADH];
__device__ __align__(128) __half g_a1[(size_t)Mn * Cn / 64 * PADH];
__device__ __align__(128) __half g_a2[(size_t)Mn * Cn / 64 * PADH];
__device__ __align__(128) __half g_h [(size_t)Mn * Hn / 64 * PADH];
__device__ __align__(128) __half g_w [(size_t)Hn * Cn / 64 * PADH];

// ---------------------------------------------------------------------------
// Packed-offset helpers (half-element index)
// ---------------------------------------------------------------------------
__device__ __forceinline__ size_t apack_off(int m, int k, int K) {
    return ((size_t)(m >> 7) * (K >> 6) + (k >> 6)) * A_TILE_H
           + (size_t)(m & 127) * PADH + (k & 63);
}
__device__ __forceinline__ size_t bpack_off(int n, int k, int K) {
    return ((size_t)(n >> 8) * (K >> 6) + (k >> 6)) * B_TILE_H
           + (size_t)(n & 255) * PADH + (k & 63);
}

// ---------------------------------------------------------------------------
// PTX helpers (baseline sm_103 — NO "a"-suffix features)
// ---------------------------------------------------------------------------
__device__ __forceinline__ uint32_t smem_u32(const void* p) {
    uint32_t a;
    asm("{ .reg .u64 t; cvta.to.shared.u64 t, %1; cvt.u32.u64 %0, t; }"
        : "=r"(a) : "l"(p));
    return a;
}

#define MBAR_INIT(mb, cnt) \
    asm volatile("mbarrier.init.shared.b64 [%0], %1;" :: "r"(mb), "r"((uint32_t)(cnt)) : "memory")

#define MBAR_EXPECT_TX(mb, bytes) \
    asm volatile("mbarrier.arrive.expect_tx.shared.b64 _, [%0], %1;" \
                 :: "r"(mb), "r"((uint32_t)(bytes)) : "memory")

#define MBAR_WAIT(mb, ph) do {                                            \
    uint32_t _m = (mb); uint32_t _p = (uint32_t)(ph); uint32_t _d;        \
    asm volatile("{ .reg .pred p;"                                        \
        " mbarrier.try_wait.parity.acquire.cta.shared::cta.b64 p, [%1], %2;" \
        " selp.b32 %0, 1, 0, p; }"                                        \
        : "=r"(_d) : "r"(_m), "r"(_p) : "memory");                        \
    if (!_d) {                                                            \
        asm volatile("{ .reg .pred P1;"                                   \
            " WL_%=:"                                                     \
            " mbarrier.try_wait.parity.acquire.cta.shared::cta.b64 P1, [%0], %1, 0x989680;" \
            " @P1 bra.uni WD_%=;"                                         \
            " bra.uni WL_%=;"                                             \
            " WD_%=: }" :: "r"(_m), "r"(_p) : "memory");                  \
    }                                                                     \
} while (0)

#define BULK_G2S(dst, src, sz, mb) \
    asm volatile("cp.async.bulk.shared::cluster.global.mbarrier::complete_tx::bytes " \
                 "[%0], [%1], %2, [%3];" \
                 :: "r"(dst), "l"(src), "r"((uint32_t)(sz)), "r"(mb) : "memory")

__device__ __forceinline__ void ldsm4(uint32_t& r0, uint32_t& r1,
                                      uint32_t& r2, uint32_t& r3, uint32_t a) {
    asm volatile("ldmatrix.sync.aligned.m8n8.x4.shared.b16 {%0,%1,%2,%3}, [%4];"
                 : "=r"(r0), "=r"(r1), "=r"(r2), "=r"(r3) : "r"(a));
}

__device__ __forceinline__ void mma16816(float* d, const uint32_t* a,
                                         const uint32_t* b) {
    asm volatile(
        "mma.sync.aligned.m16n8k16.row.col.f32.f16.f16.f32 "
        "{%0,%1,%2,%3}, {%4,%5,%6,%7}, {%8,%9}, {%0,%1,%2,%3};"
        : "+f"(d[0]), "+f"(d[1]), "+f"(d[2]), "+f"(d[3])
        : "r"(a[0]), "r"(a[1]), "r"(a[2]), "r"(a[3]), "r"(b[0]), "r"(b[1]));
}

// ---------------------------------------------------------------------------
// fp16 pack helpers
// ---------------------------------------------------------------------------
__device__ __forceinline__ uint32_t pack2h(float x, float y) {
    __half2 t = __floats2half2_rn(x, y);
    return *reinterpret_cast<uint32_t*>(&t);
}

__device__ __forceinline__ void store_h4(float4 v, __half* p, size_t idx) {
    uint2 u;
    u.x = pack2h(v.x, v.y);
    u.y = pack2h(v.z, v.w);
    *(uint2*)(p + idx) = u;
}

__device__ __forceinline__ float4 lerp4(float4 cur, float4 prev, float4 m) {
    float4 r;
    r.x = cur.x * m.x + prev.x * (1.f - m.x);
    r.y = cur.y * m.y + prev.y * (1.f - m.y);
    r.z = cur.z * m.z + prev.z * (1.f - m.z);
    r.w = cur.w * m.w + prev.w * (1.f - m.w);
    return r;
}

// ---------------------------------------------------------------------------
// Fused LayerNorm + time-shift mix → packed fp16.
// ---------------------------------------------------------------------------
template <int NOUT>
__global__ __launch_bounds__(256) void ln_mix(
    const float* __restrict__ x, const float* __restrict__ w,
    const float* __restrict__ b,
    const float* __restrict__ m0p, const float* __restrict__ m1p,
    const float* __restrict__ m2p,
    __half* __restrict__ o0, __half* __restrict__ o1, __half* __restrict__ o2)
{
    const int row = blockIdx.x;
    const int t = row % Tn;
    const int tid = threadIdx.x;
    const float* xr = x + (size_t)row * Cn;

    float4 f0 = ((const float4*)xr)[tid];
    float4 f1 = ((const float4*)xr)[tid + 256];
    float v[8] = {f0.x, f0.y, f0.z, f0.w, f1.x, f1.y, f1.z, f1.w};
    float p[8] = {0.f, 0.f, 0.f, 0.f, 0.f, 0.f, 0.f, 0.f};
    if (t > 0) {
        const float* pr = xr - Cn;
        float4 g0 = ((const float4*)pr)[tid];
        float4 g1 = ((const float4*)pr)[tid + 256];
        p[0]=g0.x; p[1]=g0.y; p[2]=g0.z; p[3]=g0.w;
        p[4]=g1.x; p[5]=g1.y; p[6]=g1.z; p[7]=g1.w;
    }

    float sc = 0.f, sc2 = 0.f, sp = 0.f, sp2 = 0.f;
#pragma unroll
    for (int i = 0; i < 8; i++) {
        sc += v[i]; sc2 += v[i] * v[i];
        sp += p[i]; sp2 += p[i] * p[i];
    }
#pragma unroll
    for (int o = 16; o > 0; o >>= 1) {
        sc  += __shfl_xor_sync(0xFFFFFFFFu, sc,  o);
        sc2 += __shfl_xor_sync(0xFFFFFFFFu, sc2, o);
        sp  += __shfl_xor_sync(0xFFFFFFFFu, sp,  o);
        sp2 += __shfl_xor_sync(0xFFFFFFFFu, sp2, o);
    }
    __shared__ float sh[32];
    const int wid = tid >> 5, lane = tid & 31;
    if (lane == 0) {
        sh[wid] = sc; sh[wid + 8] = sc2; sh[wid + 16] = sp; sh[wid + 24] = sp2;
    }
    __syncthreads();
    if (tid < 32) {
        const int g = tid >> 3, l = tid & 7;   // 4 groups of 8
        float a = sh[g * 8 + l];
#pragma unroll
        for (int o = 4; o > 0; o >>= 1)
            a += __shfl_xor_sync(0xFFFFFFFFu, a, o);
        if (l == 0) sh[g] = a;
    }
    __syncthreads();

    const float mu_c  = sh[0] * (1.f / Cn);
    const float inv_c = rsqrtf(sh[1] * (1.f / Cn) - mu_c * mu_c + 1e-5f);
    const float mu_p  = sh[2] * (1.f / Cn);
    const float inv_p = rsqrtf(sh[3] * (1.f / Cn) - mu_p * mu_p + 1e-5f);

#pragma unroll
    for (int j = 0; j < 2; j++) {
        const int c = (tid + j * 256) * 4;
        float4 xn4, xx4;
        const float* vv = v + j * 4;
        const float* pp = p + j * 4;
        xn4.x = (vv[0] - mu_c) * inv_c * w[c + 0] + b[c + 0];
        xn4.y = (vv[1] - mu_c) * inv_c * w[c + 1] + b[c + 1];
        xn4.z = (vv[2] - mu_c) * inv_c * w[c + 2] + b[c + 2];
        xn4.w = (vv[3] - mu_c) * inv_c * w[c + 3] + b[c + 3];
        if (t > 0) {
            xx4.x = (pp[0] - mu_p) * inv_p * w[c + 0] + b[c + 0];
            xx4.y = (pp[1] - mu_p) * inv_p * w[c + 1] + b[c + 1];
            xx4.z = (pp[2] - mu_p) * inv_p * w[c + 2] + b[c + 2];
            xx4.w = (pp[3] - mu_p) * inv_p * w[c + 3] + b[c + 3];
        } else {
            xx4 = make_float4(0.f, 0.f, 0.f, 0.f);
        }
        const size_t po = apack_off(row, c, Cn);
        store_h4(lerp4(xn4, xx4, *(const float4*)(m0p + c)), o0, po);
        store_h4(lerp4(xn4, xx4, *(const float4*)(m1p + c)), o1, po);
        if (NOUT == 3)
            store_h4(lerp4(xn4, xx4, *(const float4*)(m2p + c)), o2, po);
    }
}

// Weight convert fp32 -> packed fp16 B layout. K = inner dim of W[N,K].
__global__ __launch_bounds__(256) void conv_w(
    const float* __restrict__ w, __half* __restrict__ h, int K)
{
    const size_t i4 = (size_t)blockIdx.x * blockDim.x + threadIdx.x;
    const size_t idx = i4 * 4;
    const int n = (int)(idx / K);
    const int k = (int)(idx % K);
    float4 v = *(const float4*)(w + idx);
    store_h4(v, h, bpack_off(n, k, K));
}

// ---------------------------------------------------------------------------
// WKV recurrence + sigmoid(r) gate. Block-level ping-pong prefetch (depth 8):
// the NEXT 8-step batch of k/v/r loads is issued into a separate register set
// before consuming the current batch, hiding DRAM latency behind the serial
// exp-chain. Single block-level bound guard; no per-step guards; no in-place
// overwrite of live slots. r packed fp16 in, g packed fp16 out.
// ---------------------------------------------------------------------------
#define WKV_PF 8

__global__ __launch_bounds__(64) void wkv_gate_kernel(
    const float* __restrict__ k, const float* __restrict__ v,
    const __half* __restrict__ rp,
    const float* __restrict__ w_decay, const float* __restrict__ u_first,
    __half* __restrict__ g)
{
    const int idx = blockIdx.x * blockDim.x + threadIdx.x;
    const int c = idx % Cn;
    const int b = idx / Cn;
    const float w = -expf(w_decay[c]);
    const float u = u_first[c];

    const size_t off0 = (size_t)b * Tn * Cn + c;
    const int m0 = b * Tn;

    float kA[WKV_PF], vA[WKV_PF], rA[WKV_PF];
    float kB[WKV_PF], vB[WKV_PF], rB[WKV_PF];

    // load batch 0
#pragma unroll
    for (int j = 0; j < WKV_PF; j++) {
        kA[j] = k[off0 + (size_t)j * Cn];
        vA[j] = v[off0 + (size_t)j * Cn];
        rA[j] = __half2float(rp[apack_off(m0 + j, c, Cn)]);
    }

    float aa = 0.f, bb = 0.f, pp = -1e38f;
    for (int t0 = 0; t0 < Tn; t0 += WKV_PF) {
        const bool more = (t0 + WKV_PF) < Tn;
        if (more) {
            const size_t offn = off0 + (size_t)(t0 + WKV_PF) * Cn;
            const int mn = m0 + t0 + WKV_PF;
#pragma unroll
            for (int j = 0; j < WKV_PF; j++) {
                kB[j] = k[offn + (size_t)j * Cn];
                vB[j] = v[offn + (size_t)j * Cn];
                rB[j] = __half2float(rp[apack_off(mn + j, c, Cn)]);
            }
        }

#pragma unroll
        for (int j = 0; j < WKV_PF; j++) {
            const float kt = kA[j];
            const float vt = vA[j];
            const float rr = rA[j];

            const float ww = u + kt;
            const float pmx = fmaxf(pp, ww);
            const float e1 = __expf(pp - pmx);
            const float e2 = __expf(ww - pmx);
            const float y  = __fdividef(e1 * aa + e2 * vt, e1 * bb + e2);
            const float sg = __fdividef(1.f, 1.f + __expf(-rr));
            g[apack_off(m0 + t0 + j, c, Cn)] = __float2half_rn(y * sg);

            const float ww2 = pp + w;
            const float p2  = fmaxf(ww2, kt);
            const float e1b = __expf(ww2 - p2);
            const float e2b = __expf(kt - p2);
            aa = e1b * aa + e2b * vt;
            bb = e1b * bb + e2b;
            pp = p2;
        }

        if (more) {
#pragma unroll
            for (int j = 0; j < WKV_PF; j++) {
                kA[j] = kB[j];
                vA[j] = vB[j];
                rA[j] = rB[j];
            }
        }
    }
}

// ---------------------------------------------------------------------------
// HMMA fp16 GEMM over packed tiles:  C[M,N] = A[M,K] @ B[N,K]^T
// CTA 128x256, 8 warps (2x4) of 64x64, BK=128, 2-stage cp.async.bulk+mbarrier.
// EPI: 0 fp32; 1 +res0; 2 relu^2 -> packed fp16; 3 res0 + sigmoid*res1;
//      4 packed fp16 (plain)
// ---------------------------------------------------------------------------
static constexpr int AT64 = A_TILE_H * 2;     // 18432 B (one 64-k A tile)
static constexpr int BT64 = B_TILE_H * 2;     // 36864 B (one 64-k B tile)
static constexpr int STAGE = 2 * (AT64 + BT64);   // 110592 B (BK=128)
static constexpr int SMEM_DYN = 2 * STAGE;        // 221184 B

template <int EPI>
__global__ __launch_bounds__(256, 1) void gemmp(
    const __half* __restrict__ Ap, const __half* __restrict__ Bp,
    float* __restrict__ Cm, __half* __restrict__ Ohp,
    int N, int K,
    const float* __restrict__ res0, const float* __restrict__ res1)
{
    extern __shared__ __align__(128) char dsm[];
    __shared__ __align__(8) uint64_t s_mbar[2];

    const uint32_t sb = smem_u32(dsm);
    const uint32_t mb = smem_u32(s_mbar);
    const int tid = threadIdx.x, wid = tid >> 5, lane = tid & 31;
    const int m0 = blockIdx.y * 128, n0 = blockIdx.x * 256;
    const int wm = wid >> 2, wn = wid & 3;   // 2 x 4 warps of 64x64

    const int nk = K >> 7;                   // BK = 128
    const __half* gA = Ap + (size_t)blockIdx.y * (K >> 6) * A_TILE_H;
    const __half* gB = Bp + (size_t)blockIdx.x * (K >> 6) * B_TILE_H;

    if (tid == 0) {
        MBAR_INIT(mb + 0, 1);
        MBAR_INIT(mb + 8, 1);
    }
    __syncthreads();

    if (tid == 0) {
#pragma unroll
        for (int s = 0; s < 2; s++) {
            MBAR_EXPECT_TX(mb + s * 8, STAGE);
            BULK_G2S(sb + s * STAGE,
                     gA + (size_t)s * 2 * A_TILE_H, 2 * AT64, mb + s * 8);
            BULK_G2S(sb + s * STAGE + 2 * AT64,
                     gB + (size_t)s * 2 * B_TILE_H, 2 * BT64, mb + s * 8);
        }
    }

    float acc[4][8][4];
#pragma unroll
    for (int a = 0; a < 4; a++)
#pragma unroll
        for (int b = 0; b < 8; b++)
#pragma unroll
            for (int c = 0; c < 4; c++) acc[a][b][c] = 0.f;

    const int a_row  = wm * 64 + (lane & 15);
    const int a_koff = (lane & 16) ? 8 : 0;
    const int b_row  = wn * 64 + (lane & 7) + ((lane & 16) ? 8 : 0);
    const int b_koff = (lane & 8) ? 8 : 0;

    int s = 0;
    uint32_t par = 0;
    for (int i = 0; i < nk; i++) {
        MBAR_WAIT(mb + s * 8, (par >> s) & 1u);
        par ^= (1u << s);

        const uint32_t st = sb + s * STAGE;
#pragma unroll
        for (int half = 0; half < 2; half++) {
            const uint32_t abase = st + half * AT64;
            const uint32_t bbase = st + 2 * AT64 + half * BT64;
#pragma unroll
            for (int k16 = 0; k16 < 4; k16++) {
                uint32_t ah[4][4];
                const uint32_t acol = (uint32_t)(k16 * 16 + a_koff) * 2;
#pragma unroll
                for (int mt = 0; mt < 4; mt++) {
                    const uint32_t ad = abase +
                        (uint32_t)(a_row + mt * 16) * (PADH * 2) + acol;
                    ldsm4(ah[mt][0], ah[mt][1], ah[mt][2], ah[mt][3], ad);
                }
                uint32_t bh[8][2];
                const uint32_t bcol = (uint32_t)(k16 * 16 + b_koff) * 2;
#pragma unroll
                for (int pq = 0; pq < 4; pq++) {
                    const uint32_t bd = bbase +
                        (uint32_t)(b_row + pq * 16) * (PADH * 2) + bcol;
                    ldsm4(bh[2*pq][0], bh[2*pq][1], bh[2*pq+1][0], bh[2*pq+1][1], bd);
                }
#pragma unroll
                for (int mt = 0; mt < 4; mt++)
#pragma unroll
                    for (int nt = 0; nt < 8; nt++)
                        mma16816(acc[mt][nt], ah[mt], bh[nt]);
            }
        }

        __syncthreads();
        if (tid == 0 && i + 2 < nk) {
            MBAR_EXPECT_TX(mb + s * 8, STAGE);
            BULK_G2S(sb + s * STAGE,
                     gA + (size_t)(i + 2) * 2 * A_TILE_H, 2 * AT64, mb + s * 8);
            BULK_G2S(sb + s * STAGE + 2 * AT64,
                     gB + (size_t)(i + 2) * 2 * B_TILE_H, 2 * BT64, mb + s * 8);
        }
        s ^= 1;
    }

    // Epilogue: registers -> global
    const int row_base = m0 + wm * 64 + (lane >> 2);
    const int col_base = n0 + wn * 64 + (lane & 3) * 2;
#pragma unroll
    for (int mt = 0; mt < 4; mt++) {
#pragma unroll
        for (int h = 0; h < 2; h++) {
            const int row = row_base + mt * 16 + h * 8;
#pragma unroll
            for (int nt = 0; nt < 8; nt++) {
                float vx = acc[mt][nt][2 * h + 0];
                float vy = acc[mt][nt][2 * h + 1];
                const int col = col_base + nt * 8;
                const size_t off = (size_t)row * N + col;
                if (EPI == 0) {
                    *(float2*)(Cm + off) = make_float2(vx, vy);
                } else if (EPI == 1) {
                    float2 r = *(const float2*)(res0 + off);
                    *(float2*)(Cm + off) = make_float2(vx + r.x, vy + r.y);
                } else if (EPI == 2) {
                    vx = fmaxf(vx, 0.f); vx *= vx;
                    vy = fmaxf(vy, 0.f); vy *= vy;
                    *(uint32_t*)(Ohp + apack_off(row, col, N)) = pack2h(vx, vy);
                } else if (EPI == 4) {
                    *(uint32_t*)(Ohp + apack_off(row, col, N)) = pack2h(vx, vy);
                } else {
                    float2 r0 = *(const float2*)(res0 + off);
                    float2 r1 = *(const float2*)(res1 + off);
                    vx = r0.x + r1.x / (1.f + __expf(-vx));
                    vy = r0.y + r1.y / (1.f + __expf(-vy));
                    *(float2*)(Cm + off) = make_float2(vx, vy);
                }
            }
        }
    }
}

// ---------------------------------------------------------------------------
// Launch
// ---------------------------------------------------------------------------
extern "C" void kernel_launch(void* const* d_in, const int* in_sizes, int n_in,
                              void* d_out, int out_size)
{
    (void)in_sizes; (void)n_in; (void)out_size;
    const float* x    = (const float*)d_in[0];
    const float* ln1w = (const float*)d_in[1];
    const float* ln1b = (const float*)d_in[2];
    const float* ln2w = (const float*)d_in[3];
    const float* ln2b = (const float*)d_in[4];
    const float* tdec = (const float*)d_in[5];
    const float* tfir = (const float*)d_in[6];
    const float* tmk  = (const float*)d_in[7];
    const float* tmv  = (const float*)d_in[8];
    const float* tmr  = (const float*)d_in[9];
    const float* Wk   = (const float*)d_in[10];
    const float* Wv   = (const float*)d_in[11];
    const float* Wr   = (const float*)d_in[12];
    const float* Wo   = (const float*)d_in[13];
    const float* cmk  = (const float*)d_in[14];
    const float* cmr  = (const float*)d_in[15];
    const float* Wck  = (const float*)d_in[16];
    const float* Wcv  = (const float*)d_in[17];
    const float* Wcr  = (const float*)d_in[18];
    float* out = (float*)d_out;

    float *kf, *vf, *x1, *kv;
    __half *a0, *a1, *a2, *hb, *wp;
    cudaGetSymbolAddress((void**)&kf, g_k);
    cudaGetSymbolAddress((void**)&vf, g_v);
    cudaGetSymbolAddress((void**)&x1, g_x1);
    cudaGetSymbolAddress((void**)&kv, g_kv);
    cudaGetSymbolAddress((void**)&a0, g_a0);
    cudaGetSymbolAddress((void**)&a1, g_a1);
    cudaGetSymbolAddress((void**)&a2, g_a2);
    cudaGetSymbolAddress((void**)&hb, g_h);
    cudaGetSymbolAddress((void**)&wp, g_w);

    cudaFuncSetAttribute(gemmp<0>, cudaFuncAttributeMaxDynamicSharedMemorySize, SMEM_DYN);
    cudaFuncSetAttribute(gemmp<1>, cudaFuncAttributeMaxDynamicSharedMemorySize, SMEM_DYN);
    cudaFuncSetAttribute(gemmp<2>, cudaFuncAttributeMaxDynamicSharedMemorySize, SMEM_DYN);
    cudaFuncSetAttribute(gemmp<3>, cudaFuncAttributeMaxDynamicSharedMemorySize, SMEM_DYN);
    cudaFuncSetAttribute(gemmp<4>, cudaFuncAttributeMaxDynamicSharedMemorySize, SMEM_DYN);

    const int wCC = (Cn * Cn / 4) / 256;
    const int wHC = (Hn * Cn / 4) / 256;
    const dim3 gC(Cn / 256, Mn / 128);   // (8, 128)
    const dim3 gH(Hn / 256, Mn / 128);   // (32, 128)

    // --- time-mix attention ---
    ln_mix<3><<<Mn, 256>>>(x, ln1w, ln1b, tmk, tmv, tmr, a0, a1, a2);

    conv_w<<<wCC, 256>>>(Wk, wp, Cn);
    gemmp<0><<<gC, 256, SMEM_DYN>>>(a0, wp, kf, nullptr, Cn, Cn, nullptr, nullptr);
    conv_w<<<wCC, 256>>>(Wv, wp, Cn);
    gemmp<0><<<gC, 256, SMEM_DYN>>>(a1, wp, vf, nullptr, Cn, Cn, nullptr, nullptr);
    conv_w<<<wCC, 256>>>(Wr, wp, Cn);
    gemmp<4><<<gC, 256, SMEM_DYN>>>(a2, wp, nullptr, a0, Cn, Cn, nullptr, nullptr);

    wkv_gate_kernel<<<(Bn * Cn) / 64, 64>>>(kf, vf, a0, tdec, tfir, a1);

    conv_w<<<wCC, 256>>>(Wo, wp, Cn);
    gemmp<1><<<gC, 256, SMEM_DYN>>>(a1, wp, x1, nullptr, Cn, Cn, x, nullptr);

    // --- channel mix ---
    ln_mix<2><<<Mn, 256>>>(x1, ln2w, ln2b, cmk, cmr, nullptr, a0, a2, nullptr);

    conv_w<<<wHC, 256>>>(Wck, wp, Cn);
    gemmp<2><<<gH, 256, SMEM_DYN>>>(a0, wp, nullptr, hb, Hn, Cn, nullptr, nullptr);
    conv_w<<<wHC, 256>>>(Wcv, wp, Hn);
    gemmp<0><<<gC, 256, SMEM_DYN>>>(hb, wp, kv, nullptr, Cn, Hn, nullptr, nullptr);
    conv_w<<<wCC, 256>>>(Wcr, wp, Cn);
    gemmp<3><<<gC, 256, SMEM_DYN>>>(a2, wp, out, nullptr, Cn, Cn, x1, kv);
}

// round 11
// speedup vs baseline: 13.9429x; 1.0002x over previous
#include <cuda_runtime.h>
#include <cuda_fp16.h>
#include <math.h>
#include <stdint.h>

#define Bn 8
#define Tn 2048
#define Cn 2048
#define Hn 8192
#define Mn (Bn * Tn)   // 16384

// Packed-tile geometry: rows padded to 72 halfs (144B) for conflict-free ldsm.
#define PADH 72
#define A_TILE_H (128 * PADH)       // halfs per 128x64 A tile
#define B_TILE_H (256 * PADH)       // halfs per 256x64 B tile

// ---------------------------------------------------------------------------
// Scratch (device globals — allocation-free per harness rules)
// ---------------------------------------------------------------------------
__device__ float g_k [(size_t)Mn * Cn];
__device__ float g_v [(size_t)Mn * Cn];
__device__ float g_x1[(size_t)Mn * Cn];
__device__ float g_kv[(size_t)Mn * Cn];
__device__ __align__(128) __half g_a0[(size_t)Mn * Cn / 64 * PADH];
__device__ __align__(128) __half g_a1[(size_t)Mn * Cn / 64 * PADH];
__device__ __align__(128) __half g_a2[(size_t)Mn * Cn / 64 * PADH];
__device__ __align__(128) __half g_h [(size_t)Mn * Hn / 64 * PADH];
__device__ __align__(128) __half g_w [(size_t)Hn * Cn / 64 * PADH];

// ---------------------------------------------------------------------------
// Packed-offset helpers (half-element index)
// ---------------------------------------------------------------------------
__device__ __forceinline__ size_t apack_off(int m, int k, int K) {
    return ((size_t)(m >> 7) * (K >> 6) + (k >> 6)) * A_TILE_H
           + (size_t)(m & 127) * PADH + (k & 63);
}
__device__ __forceinline__ size_t bpack_off(int n, int k, int K) {
    return ((size_t)(n >> 8) * (K >> 6) + (k >> 6)) * B_TILE_H
           + (size_t)(n & 255) * PADH + (k & 63);
}

// ---------------------------------------------------------------------------
// PTX helpers (baseline sm_103 — NO "a"-suffix features)
// ---------------------------------------------------------------------------
__device__ __forceinline__ uint32_t smem_u32(const void* p) {
    uint32_t a;
    asm("{ .reg .u64 t; cvta.to.shared.u64 t, %1; cvt.u32.u64 %0, t; }"
        : "=r"(a) : "l"(p));
    return a;
}

#define MBAR_INIT(mb, cnt) \
    asm volatile("mbarrier.init.shared.b64 [%0], %1;" :: "r"(mb), "r"((uint32_t)(cnt)) : "memory")

#define MBAR_EXPECT_TX(mb, bytes) \
    asm volatile("mbarrier.arrive.expect_tx.shared.b64 _, [%0], %1;" \
                 :: "r"(mb), "r"((uint32_t)(bytes)) : "memory")

#define MBAR_WAIT(mb, ph) do {                                            \
    uint32_t _m = (mb); uint32_t _p = (uint32_t)(ph); uint32_t _d;        \
    asm volatile("{ .reg .pred p;"                                        \
        " mbarrier.try_wait.parity.acquire.cta.shared::cta.b64 p, [%1], %2;" \
        " selp.b32 %0, 1, 0, p; }"                                        \
        : "=r"(_d) : "r"(_m), "r"(_p) : "memory");                        \
    if (!_d) {                                                            \
        asm volatile("{ .reg .pred P1;"                                   \
            " WL_%=:"                                                     \
            " mbarrier.try_wait.parity.acquire.cta.shared::cta.b64 P1, [%0], %1, 0x989680;" \
            " @P1 bra.uni WD_%=;"                                         \
            " bra.uni WL_%=;"                                             \
            " WD_%=: }" :: "r"(_m), "r"(_p) : "memory");                  \
    }                                                                     \
} while (0)

#define BULK_G2S(dst, src, sz, mb) \
    asm volatile("cp.async.bulk.shared::cluster.global.mbarrier::complete_tx::bytes " \
                 "[%0], [%1], %2, [%3];" \
                 :: "r"(dst), "l"(src), "r"((uint32_t)(sz)), "r"(mb) : "memory")

__device__ __forceinline__ void ldsm4(uint32_t& r0, uint32_t& r1,
                                      uint32_t& r2, uint32_t& r3, uint32_t a) {
    asm volatile("ldmatrix.sync.aligned.m8n8.x4.shared.b16 {%0,%1,%2,%3}, [%4];"
                 : "=r"(r0), "=r"(r1), "=r"(r2), "=r"(r3) : "r"(a));
}

__device__ __forceinline__ void mma16816(float* d, const uint32_t* a,
                                         const uint32_t* b) {
    asm volatile(
        "mma.sync.aligned.m16n8k16.row.col.f32.f16.f16.f32 "
        "{%0,%1,%2,%3}, {%4,%5,%6,%7}, {%8,%9}, {%0,%1,%2,%3};"
        : "+f"(d[0]), "+f"(d[1]), "+f"(d[2]), "+f"(d[3])
        : "r"(a[0]), "r"(a[1]), "r"(a[2]), "r"(a[3]), "r"(b[0]), "r"(b[1]));
}

// ---------------------------------------------------------------------------
// fp16 pack helpers
// ---------------------------------------------------------------------------
__device__ __forceinline__ uint32_t pack2h(float x, float y) {
    __half2 t = __floats2half2_rn(x, y);
    return *reinterpret_cast<uint32_t*>(&t);
}

__device__ __forceinline__ void store_h4(float4 v, __half* p, size_t idx) {
    uint2 u;
    u.x = pack2h(v.x, v.y);
    u.y = pack2h(v.z, v.w);
    *(uint2*)(p + idx) = u;
}

__device__ __forceinline__ float4 lerp4(float4 cur, float4 prev, float4 m) {
    float4 r;
    r.x = cur.x * m.x + prev.x * (1.f - m.x);
    r.y = cur.y * m.y + prev.y * (1.f - m.y);
    r.z = cur.z * m.z + prev.z * (1.f - m.z);
    r.w = cur.w * m.w + prev.w * (1.f - m.w);
    return r;
}

// ---------------------------------------------------------------------------
// Fused LayerNorm + time-shift mix → packed fp16.
// ---------------------------------------------------------------------------
template <int NOUT>
__global__ __launch_bounds__(256) void ln_mix(
    const float* __restrict__ x, const float* __restrict__ w,
    const float* __restrict__ b,
    const float* __restrict__ m0p, const float* __restrict__ m1p,
    const float* __restrict__ m2p,
    __half* __restrict__ o0, __half* __restrict__ o1, __half* __restrict__ o2)
{
    const int row = blockIdx.x;
    const int t = row % Tn;
    const int tid = threadIdx.x;
    const float* xr = x + (size_t)row * Cn;

    float4 f0 = ((const float4*)xr)[tid];
    float4 f1 = ((const float4*)xr)[tid + 256];
    float v[8] = {f0.x, f0.y, f0.z, f0.w, f1.x, f1.y, f1.z, f1.w};
    float p[8] = {0.f, 0.f, 0.f, 0.f, 0.f, 0.f, 0.f, 0.f};
    if (t > 0) {
        const float* pr = xr - Cn;
        float4 g0 = ((const float4*)pr)[tid];
        float4 g1 = ((const float4*)pr)[tid + 256];
        p[0]=g0.x; p[1]=g0.y; p[2]=g0.z; p[3]=g0.w;
        p[4]=g1.x; p[5]=g1.y; p[6]=g1.z; p[7]=g1.w;
    }

    float sc = 0.f, sc2 = 0.f, sp = 0.f, sp2 = 0.f;
#pragma unroll
    for (int i = 0; i < 8; i++) {
        sc += v[i]; sc2 += v[i] * v[i];
        sp += p[i]; sp2 += p[i] * p[i];
    }
#pragma unroll
    for (int o = 16; o > 0; o >>= 1) {
        sc  += __shfl_xor_sync(0xFFFFFFFFu, sc,  o);
        sc2 += __shfl_xor_sync(0xFFFFFFFFu, sc2, o);
        sp  += __shfl_xor_sync(0xFFFFFFFFu, sp,  o);
        sp2 += __shfl_xor_sync(0xFFFFFFFFu, sp2, o);
    }
    __shared__ float sh[32];
    const int wid = tid >> 5, lane = tid & 31;
    if (lane == 0) {
        sh[wid] = sc; sh[wid + 8] = sc2; sh[wid + 16] = sp; sh[wid + 24] = sp2;
    }
    __syncthreads();
    if (tid < 32) {
        const int g = tid >> 3, l = tid & 7;   // 4 groups of 8
        float a = sh[g * 8 + l];
#pragma unroll
        for (int o = 4; o > 0; o >>= 1)
            a += __shfl_xor_sync(0xFFFFFFFFu, a, o);
        if (l == 0) sh[g] = a;
    }
    __syncthreads();

    const float mu_c  = sh[0] * (1.f / Cn);
    const float inv_c = rsqrtf(sh[1] * (1.f / Cn) - mu_c * mu_c + 1e-5f);
    const float mu_p  = sh[2] * (1.f / Cn);
    const float inv_p = rsqrtf(sh[3] * (1.f / Cn) - mu_p * mu_p + 1e-5f);

#pragma unroll
    for (int j = 0; j < 2; j++) {
        const int c = (tid + j * 256) * 4;
        float4 xn4, xx4;
        const float* vv = v + j * 4;
        const float* pp = p + j * 4;
        xn4.x = (vv[0] - mu_c) * inv_c * w[c + 0] + b[c + 0];
        xn4.y = (vv[1] - mu_c) * inv_c * w[c + 1] + b[c + 1];
        xn4.z = (vv[2] - mu_c) * inv_c * w[c + 2] + b[c + 2];
        xn4.w = (vv[3] - mu_c) * inv_c * w[c + 3] + b[c + 3];
        if (t > 0) {
            xx4.x = (pp[0] - mu_p) * inv_p * w[c + 0] + b[c + 0];
            xx4.y = (pp[1] - mu_p) * inv_p * w[c + 1] + b[c + 1];
            xx4.z = (pp[2] - mu_p) * inv_p * w[c + 2] + b[c + 2];
            xx4.w = (pp[3] - mu_p) * inv_p * w[c + 3] + b[c + 3];
        } else {
            xx4 = make_float4(0.f, 0.f, 0.f, 0.f);
        }
        const size_t po = apack_off(row, c, Cn);
        store_h4(lerp4(xn4, xx4, *(const float4*)(m0p + c)), o0, po);
        store_h4(lerp4(xn4, xx4, *(const float4*)(m1p + c)), o1, po);
        if (NOUT == 3)
            store_h4(lerp4(xn4, xx4, *(const float4*)(m2p + c)), o2, po);
    }
}

// Weight convert fp32 -> packed fp16 B layout. K = inner dim of W[N,K].
__global__ __launch_bounds__(256) void conv_w(
    const float* __restrict__ w, __half* __restrict__ h, int K)
{
    const size_t i4 = (size_t)blockIdx.x * blockDim.x + threadIdx.x;
    const size_t idx = i4 * 4;
    const int n = (int)(idx / K);
    const int k = (int)(idx % K);
    float4 v = *(const float4*)(w + idx);
    store_h4(v, h, bpack_off(n, k, K));
}

// ---------------------------------------------------------------------------
// WKV recurrence + sigmoid(r) gate. Block-level ping-pong prefetch (depth 8).
// ---------------------------------------------------------------------------
#define WKV_PF 8

__global__ __launch_bounds__(64) void wkv_gate_kernel(
    const float* __restrict__ k, const float* __restrict__ v,
    const __half* __restrict__ rp,
    const float* __restrict__ w_decay, const float* __restrict__ u_first,
    __half* __restrict__ g)
{
    const int idx = blockIdx.x * blockDim.x + threadIdx.x;
    const int c = idx % Cn;
    const int b = idx / Cn;
    const float w = -expf(w_decay[c]);
    const float u = u_first[c];

    const size_t off0 = (size_t)b * Tn * Cn + c;
    const int m0 = b * Tn;

    float kA[WKV_PF], vA[WKV_PF], rA[WKV_PF];
    float kB[WKV_PF], vB[WKV_PF], rB[WKV_PF];

#pragma unroll
    for (int j = 0; j < WKV_PF; j++) {
        kA[j] = k[off0 + (size_t)j * Cn];
        vA[j] = v[off0 + (size_t)j * Cn];
        rA[j] = __half2float(rp[apack_off(m0 + j, c, Cn)]);
    }

    float aa = 0.f, bb = 0.f, pp = -1e38f;
    for (int t0 = 0; t0 < Tn; t0 += WKV_PF) {
        const bool more = (t0 + WKV_PF) < Tn;
        if (more) {
            const size_t offn = off0 + (size_t)(t0 + WKV_PF) * Cn;
            const int mn = m0 + t0 + WKV_PF;
#pragma unroll
            for (int j = 0; j < WKV_PF; j++) {
                kB[j] = k[offn + (size_t)j * Cn];
                vB[j] = v[offn + (size_t)j * Cn];
                rB[j] = __half2float(rp[apack_off(mn + j, c, Cn)]);
            }
        }

#pragma unroll
        for (int j = 0; j < WKV_PF; j++) {
            const float kt = kA[j];
            const float vt = vA[j];
            const float rr = rA[j];

            const float ww = u + kt;
            const float pmx = fmaxf(pp, ww);
            const float e1 = __expf(pp - pmx);
            const float e2 = __expf(ww - pmx);
            const float y  = __fdividef(e1 * aa + e2 * vt, e1 * bb + e2);
            const float sg = __fdividef(1.f, 1.f + __expf(-rr));
            g[apack_off(m0 + t0 + j, c, Cn)] = __float2half_rn(y * sg);

            const float ww2 = pp + w;
            const float p2  = fmaxf(ww2, kt);
            const float e1b = __expf(ww2 - p2);
            const float e2b = __expf(kt - p2);
            aa = e1b * aa + e2b * vt;
            bb = e1b * bb + e2b;
            pp = p2;
        }

        if (more) {
#pragma unroll
            for (int j = 0; j < WKV_PF; j++) {
                kA[j] = kB[j];
                vA[j] = vB[j];
                rA[j] = rB[j];
            }
        }
    }
}

// ---------------------------------------------------------------------------
// HMMA fp16 GEMM over packed tiles:  C[M,N] = A[M,K] @ B[N,K]^T
// CTA 128x256, 8 warps (2x4) of 64x64, BK=128, 2-stage cp.async.bulk+mbarrier.
// Register-fragment double buffering: step n+1's ldmatrix issues before
// step n's mma block, hiding shared-memory latency under tensor work.
// EPI: 0 fp32; 1 +res0; 2 relu^2 -> packed fp16; 3 res0 + sigmoid*res1;
//      4 packed fp16 (plain)
// ---------------------------------------------------------------------------
static constexpr int AT64 = A_TILE_H * 2;     // 18432 B (one 64-k A tile)
static constexpr int BT64 = B_TILE_H * 2;     // 36864 B (one 64-k B tile)
static constexpr int STAGE = 2 * (AT64 + BT64);   // 110592 B (BK=128)
static constexpr int SMEM_DYN = 2 * STAGE;        // 221184 B

__device__ __forceinline__ void ld_frag_step(
    uint32_t st, int step, int a_row, int a_koff, int b_row, int b_koff,
    uint32_t (&ah)[4][4], uint32_t (&bh)[8][2])
{
    const uint32_t abase = st + (uint32_t)(step >> 2) * AT64;
    const uint32_t bbase = st + 2u * AT64 + (uint32_t)(step >> 2) * BT64;
    const int k16 = step & 3;
    const uint32_t acol = (uint32_t)(k16 * 16 + a_koff) * 2;
#pragma unroll
    for (int mt = 0; mt < 4; mt++) {
        const uint32_t ad = abase + (uint32_t)(a_row + mt * 16) * (PADH * 2) + acol;
        ldsm4(ah[mt][0], ah[mt][1], ah[mt][2], ah[mt][3], ad);
    }
    const uint32_t bcol = (uint32_t)(k16 * 16 + b_koff) * 2;
#pragma unroll
    for (int pq = 0; pq < 4; pq++) {
        const uint32_t bd = bbase + (uint32_t)(b_row + pq * 16) * (PADH * 2) + bcol;
        ldsm4(bh[2*pq][0], bh[2*pq][1], bh[2*pq+1][0], bh[2*pq+1][1], bd);
    }
}

template <int EPI>
__global__ __launch_bounds__(256, 1) void gemmp(
    const __half* __restrict__ Ap, const __half* __restrict__ Bp,
    float* __restrict__ Cm, __half* __restrict__ Ohp,
    int N, int K,
    const float* __restrict__ res0, const float* __restrict__ res1)
{
    extern __shared__ __align__(128) char dsm[];
    __shared__ __align__(8) uint64_t s_mbar[2];

    const uint32_t sb = smem_u32(dsm);
    const uint32_t mb = smem_u32(s_mbar);
    const int tid = threadIdx.x, wid = tid >> 5, lane = tid & 31;
    const int m0 = blockIdx.y * 128, n0 = blockIdx.x * 256;
    const int wm = wid >> 2, wn = wid & 3;   // 2 x 4 warps of 64x64

    const int nk = K >> 7;                   // BK = 128
    const __half* gA = Ap + (size_t)blockIdx.y * (K >> 6) * A_TILE_H;
    const __half* gB = Bp + (size_t)blockIdx.x * (K >> 6) * B_TILE_H;

    if (tid == 0) {
        MBAR_INIT(mb + 0, 1);
        MBAR_INIT(mb + 8, 1);
    }
    __syncthreads();

    if (tid == 0) {
#pragma unroll
        for (int s = 0; s < 2; s++) {
            MBAR_EXPECT_TX(mb + s * 8, STAGE);
            BULK_G2S(sb + s * STAGE,
                     gA + (size_t)s * 2 * A_TILE_H, 2 * AT64, mb + s * 8);
            BULK_G2S(sb + s * STAGE + 2 * AT64,
                     gB + (size_t)s * 2 * B_TILE_H, 2 * BT64, mb + s * 8);
        }
    }

    float acc[4][8][4];
#pragma unroll
    for (int a = 0; a < 4; a++)
#pragma unroll
        for (int b = 0; b < 8; b++)
#pragma unroll
            for (int c = 0; c < 4; c++) acc[a][b][c] = 0.f;

    const int a_row  = wm * 64 + (lane & 15);
    const int a_koff = (lane & 16) ? 8 : 0;
    const int b_row  = wn * 64 + (lane & 7) + ((lane & 16) ? 8 : 0);
    const int b_koff = (lane & 8) ? 8 : 0;

    uint32_t ah[2][4][4];
    uint32_t bh[2][8][2];

    int s = 0;
    uint32_t par = 0;
    for (int i = 0; i < nk; i++) {
        MBAR_WAIT(mb + s * 8, (par >> s) & 1u);
        par ^= (1u << s);

        const uint32_t st = sb + s * STAGE;

        ld_frag_step(st, 0, a_row, a_koff, b_row, b_koff, ah[0], bh[0]);
#pragma unroll
        for (int step = 0; step < 8; step++) {
            const int cur = step & 1;
            if (step < 7)
                ld_frag_step(st, step + 1, a_row, a_koff, b_row, b_koff,
                             ah[cur ^ 1], bh[cur ^ 1]);
#pragma unroll
            for (int mt = 0; mt < 4; mt++)
#pragma unroll
                for (int nt = 0; nt < 8; nt++)
                    mma16816(acc[mt][nt], ah[cur][mt], bh[cur][nt]);
        }

        __syncthreads();
        if (tid == 0 && i + 2 < nk) {
            MBAR_EXPECT_TX(mb + s * 8, STAGE);
            BULK_G2S(sb + s * STAGE,
                     gA + (size_t)(i + 2) * 2 * A_TILE_H, 2 * AT64, mb + s * 8);
            BULK_G2S(sb + s * STAGE + 2 * AT64,
                     gB + (size_t)(i + 2) * 2 * B_TILE_H, 2 * BT64, mb + s * 8);
        }
        s ^= 1;
    }

    // Epilogue: registers -> global
    const int row_base = m0 + wm * 64 + (lane >> 2);
    const int col_base = n0 + wn * 64 + (lane & 3) * 2;
#pragma unroll
    for (int mt = 0; mt < 4; mt++) {
#pragma unroll
        for (int h = 0; h < 2; h++) {
            const int row = row_base + mt * 16 + h * 8;
#pragma unroll
            for (int nt = 0; nt < 8; nt++) {
                float vx = acc[mt][nt][2 * h + 0];
                float vy = acc[mt][nt][2 * h + 1];
                const int col = col_base + nt * 8;
                const size_t off = (size_t)row * N + col;
                if (EPI == 0) {
                    *(float2*)(Cm + off) = make_float2(vx, vy);
                } else if (EPI == 1) {
                    float2 r = *(const float2*)(res0 + off);
                    *(float2*)(Cm + off) = make_float2(vx + r.x, vy + r.y);
                } else if (EPI == 2) {
                    vx = fmaxf(vx, 0.f); vx *= vx;
                    vy = fmaxf(vy, 0.f); vy *= vy;
                    *(uint32_t*)(Ohp + apack_off(row, col, N)) = pack2h(vx, vy);
                } else if (EPI == 4) {
                    *(uint32_t*)(Ohp + apack_off(row, col, N)) = pack2h(vx, vy);
                } else {
                    float2 r0 = *(const float2*)(res0 + off);
                    float2 r1 = *(const float2*)(res1 + off);
                    vx = r0.x + r1.x / (1.f + __expf(-vx));
                    vy = r0.y + r1.y / (1.f + __expf(-vy));
                    *(float2*)(Cm + off) = make_float2(vx, vy);
                }
            }
        }
    }
}

// ---------------------------------------------------------------------------
// Launch
// ---------------------------------------------------------------------------
extern "C" void kernel_launch(void* const* d_in, const int* in_sizes, int n_in,
                              void* d_out, int out_size)
{
    (void)in_sizes; (void)n_in; (void)out_size;
    const float* x    = (const float*)d_in[0];
    const float* ln1w = (const float*)d_in[1];
    const float* ln1b = (const float*)d_in[2];
    const float* ln2w = (const float*)d_in[3];
    const float* ln2b = (const float*)d_in[4];
    const float* tdec = (const float*)d_in[5];
    const float* tfir = (const float*)d_in[6];
    const float* tmk  = (const float*)d_in[7];
    const float* tmv  = (const float*)d_in[8];
    const float* tmr  = (const float*)d_in[9];
    const float* Wk   = (const float*)d_in[10];
    const float* Wv   = (const float*)d_in[11];
    const float* Wr   = (const float*)d_in[12];
    const float* Wo   = (const float*)d_in[13];
    const float* cmk  = (const float*)d_in[14];
    const float* cmr  = (const float*)d_in[15];
    const float* Wck  = (const float*)d_in[16];
    const float* Wcv  = (const float*)d_in[17];
    const float* Wcr  = (const float*)d_in[18];
    float* out = (float*)d_out;

    float *kf, *vf, *x1, *kv;
    __half *a0, *a1, *a2, *hb, *wp;
    cudaGetSymbolAddress((void**)&kf, g_k);
    cudaGetSymbolAddress((void**)&vf, g_v);
    cudaGetSymbolAddress((void**)&x1, g_x1);
    cudaGetSymbolAddress((void**)&kv, g_kv);
    cudaGetSymbolAddress((void**)&a0, g_a0);
    cudaGetSymbolAddress((void**)&a1, g_a1);
    cudaGetSymbolAddress((void**)&a2, g_a2);
    cudaGetSymbolAddress((void**)&hb, g_h);
    cudaGetSymbolAddress((void**)&wp, g_w);

    cudaFuncSetAttribute(gemmp<0>, cudaFuncAttributeMaxDynamicSharedMemorySize, SMEM_DYN);
    cudaFuncSetAttribute(gemmp<1>, cudaFuncAttributeMaxDynamicSharedMemorySize, SMEM_DYN);
    cudaFuncSetAttribute(gemmp<2>, cudaFuncAttributeMaxDynamicSharedMemorySize, SMEM_DYN);
    cudaFuncSetAttribute(gemmp<3>, cudaFuncAttributeMaxDynamicSharedMemorySize, SMEM_DYN);
    cudaFuncSetAttribute(gemmp<4>, cudaFuncAttributeMaxDynamicSharedMemorySize, SMEM_DYN);

    const int wCC = (Cn * Cn / 4) / 256;
    const int wHC = (Hn * Cn / 4) / 256;
    const dim3 gC(Cn / 256, Mn / 128);   // (8, 128)
    const dim3 gH(Hn / 256, Mn / 128);   // (32, 128)

    // --- time-mix attention ---
    ln_mix<3><<<Mn, 256>>>(x, ln1w, ln1b, tmk, tmv, tmr, a0, a1, a2);

    conv_w<<<wCC, 256>>>(Wk, wp, Cn);
    gemmp<0><<<gC, 256, SMEM_DYN>>>(a0, wp, kf, nullptr, Cn, Cn, nullptr, nullptr);
    conv_w<<<wCC, 256>>>(Wv, wp, Cn);
    gemmp<0><<<gC, 256, SMEM_DYN>>>(a1, wp, vf, nullptr, Cn, Cn, nullptr, nullptr);
    conv_w<<<wCC, 256>>>(Wr, wp, Cn);
    gemmp<4><<<gC, 256, SMEM_DYN>>>(a2, wp, nullptr, a0, Cn, Cn, nullptr, nullptr);

    wkv_gate_kernel<<<(Bn * Cn) / 64, 64>>>(kf, vf, a0, tdec, tfir, a1);

    conv_w<<<wCC, 256>>>(Wo, wp, Cn);
    gemmp<1><<<gC, 256, SMEM_DYN>>>(a1, wp, x1, nullptr, Cn, Cn, x, nullptr);

    // --- channel mix ---
    ln_mix<2><<<Mn, 256>>>(x1, ln2w, ln2b, cmk, cmr, nullptr, a0, a2, nullptr);

    conv_w<<<wHC, 256>>>(Wck, wp, Cn);
    gemmp<2><<<gH, 256, SMEM_DYN>>>(a0, wp, nullptr, hb, Hn, Cn, nullptr, nullptr);
    conv_w<<<wHC, 256>>>(Wcv, wp, Hn);
    gemmp<0><<<gC, 256, SMEM_DYN>>>(hb, wp, kv, nullptr, Cn, Hn, nullptr, nullptr);
    conv_w<<<wCC, 256>>>(Wcr, wp, Cn);
    gemmp<3><<<gC, 256, SMEM_DYN>>>(a2, wp, out, nullptr, Cn, Cn, x1, kv);
}

// round 14
// speedup vs baseline: 14.4487x; 1.0363x over previous
#include <cuda_runtime.h>
#include <cuda_fp16.h>
#include <math.h>
#include <stdint.h>

#define Bn 8
#define Tn 2048
#define Cn 2048
#define Hn 8192
#define Mn (Bn * Tn)   // 16384

// Packed-tile geometry: rows padded to 72 halfs (144B) for conflict-free ldsm.
#define PADH 72
#define A_TILE_H (128 * PADH)       // halfs per 128x64 A tile
#define B_TILE_H (256 * PADH)       // halfs per 256x64 B tile

// ---------------------------------------------------------------------------
// Scratch (device globals — allocation-free per harness rules)
// ---------------------------------------------------------------------------
__device__ float g_k [(size_t)Mn * Cn];
__device__ float g_v [(size_t)Mn * Cn];
__device__ float g_x1[(size_t)Mn * Cn];
__device__ float g_kv[(size_t)Mn * Cn];
__device__ __align__(128) __half g_a0[(size_t)Mn * Cn / 64 * PADH];
__device__ __align__(128) __half g_a1[(size_t)Mn * Cn / 64 * PADH];
__device__ __align__(128) __half g_a2[(size_t)Mn * Cn / 64 * PADH];
__device__ __align__(128) __half g_h [(size_t)Mn * Hn / 64 * PADH];
// dedicated packed weight buffers (converted once up-front each launch)
__device__ __align__(128) __half g_wk [(size_t)Cn * Cn / 64 * PADH];
__device__ __align__(128) __half g_wv [(size_t)Cn * Cn / 64 * PADH];
__device__ __align__(128) __half g_wr [(size_t)Cn * Cn / 64 * PADH];
__device__ __align__(128) __half g_wo [(size_t)Cn * Cn / 64 * PADH];
__device__ __align__(128) __half g_wck[(size_t)Hn * Cn / 64 * PADH];
__device__ __align__(128) __half g_wcv[(size_t)Hn * Cn / 64 * PADH];
__device__ __align__(128) __half g_wcr[(size_t)Cn * Cn / 64 * PADH];

// ---------------------------------------------------------------------------
// Packed-offset helpers (half-element index)
// ---------------------------------------------------------------------------
__device__ __forceinline__ size_t apack_off(int m, int k, int K) {
    return ((size_t)(m >> 7) * (K >> 6) + (k >> 6)) * A_TILE_H
           + (size_t)(m & 127) * PADH + (k & 63);
}
__device__ __forceinline__ size_t bpack_off(int n, int k, int K) {
    return ((size_t)(n >> 8) * (K >> 6) + (k >> 6)) * B_TILE_H
           + (size_t)(n & 255) * PADH + (k & 63);
}

// ---------------------------------------------------------------------------
// PTX helpers (baseline sm_103 — NO "a"-suffix features)
// ---------------------------------------------------------------------------
__device__ __forceinline__ uint32_t smem_u32(const void* p) {
    uint32_t a;
    asm("{ .reg .u64 t; cvta.to.shared.u64 t, %1; cvt.u32.u64 %0, t; }"
        : "=r"(a) : "l"(p));
    return a;
}

#define MBAR_INIT(mb, cnt) \
    asm volatile("mbarrier.init.shared.b64 [%0], %1;" :: "r"(mb), "r"((uint32_t)(cnt)) : "memory")

#define MBAR_EXPECT_TX(mb, bytes) \
    asm volatile("mbarrier.arrive.expect_tx.shared.b64 _, [%0], %1;" \
                 :: "r"(mb), "r"((uint32_t)(bytes)) : "memory")

#define MBAR_ARRIVE(mb) \
    asm volatile("mbarrier.arrive.shared.b64 _, [%0];" :: "r"(mb) : "memory")

#define MBAR_WAIT(mb, ph) do {                                            \
    uint32_t _m = (mb); uint32_t _p = (uint32_t)(ph); uint32_t _d;        \
    asm volatile("{ .reg .pred p;"                                        \
        " mbarrier.try_wait.parity.acquire.cta.shared::cta.b64 p, [%1], %2;" \
        " selp.b32 %0, 1, 0, p; }"                                        \
        : "=r"(_d) : "r"(_m), "r"(_p) : "memory");                        \
    if (!_d) {                                                            \
        asm volatile("{ .reg .pred P1;"                                   \
            " WL_%=:"                                                     \
            " mbarrier.try_wait.parity.acquire.cta.shared::cta.b64 P1, [%0], %1, 0x989680;" \
            " @P1 bra.uni WD_%=;"                                         \
            " bra.uni WL_%=;"                                             \
            " WD_%=: }" :: "r"(_m), "r"(_p) : "memory");                  \
    }                                                                     \
} while (0)

#define BULK_G2S(dst, src, sz, mb) \
    asm volatile("cp.async.bulk.shared::cluster.global.mbarrier::complete_tx::bytes " \
                 "[%0], [%1], %2, [%3];" \
                 :: "r"(dst), "l"(src), "r"((uint32_t)(sz)), "r"(mb) : "memory")

__device__ __forceinline__ void ldsm4(uint32_t& r0, uint32_t& r1,
                                      uint32_t& r2, uint32_t& r3, uint32_t a) {
    asm volatile("ldmatrix.sync.aligned.m8n8.x4.shared.b16 {%0,%1,%2,%3}, [%4];"
                 : "=r"(r0), "=r"(r1), "=r"(r2), "=r"(r3) : "r"(a));
}

__device__ __forceinline__ void mma16816(float* d, const uint32_t* a,
                                         const uint32_t* b) {
    asm volatile(
        "mma.sync.aligned.m16n8k16.row.col.f32.f16.f16.f32 "
        "{%0,%1,%2,%3}, {%4,%5,%6,%7}, {%8,%9}, {%0,%1,%2,%3};"
        : "+f"(d[0]), "+f"(d[1]), "+f"(d[2]), "+f"(d[3])
        : "r"(a[0]), "r"(a[1]), "r"(a[2]), "r"(a[3]), "r"(b[0]), "r"(b[1]));
}

// ---------------------------------------------------------------------------
// fp16 pack helpers
// ---------------------------------------------------------------------------
__device__ __forceinline__ uint32_t pack2h(float x, float y) {
    __half2 t = __floats2half2_rn(x, y);
    return *reinterpret_cast<uint32_t*>(&t);
}

__device__ __forceinline__ void store_h4(float4 v, __half* p, size_t idx) {
    uint2 u;
    u.x = pack2h(v.x, v.y);
    u.y = pack2h(v.z, v.w);
    *(uint2*)(p + idx) = u;
}

__device__ __forceinline__ float4 lerp4(float4 cur, float4 prev, float4 m) {
    float4 r;
    r.x = cur.x * m.x + prev.x * (1.f - m.x);
    r.y = cur.y * m.y + prev.y * (1.f - m.y);
    r.z = cur.z * m.z + prev.z * (1.f - m.z);
    r.w = cur.w * m.w + prev.w * (1.f - m.w);
    return r;
}

// ---------------------------------------------------------------------------
// Fused LayerNorm + time-shift mix → packed fp16.
// ---------------------------------------------------------------------------
template <int NOUT>
__global__ __launch_bounds__(256) void ln_mix(
    const float* __restrict__ x, const float* __restrict__ w,
    const float* __restrict__ b,
    const float* __restrict__ m0p, const float* __restrict__ m1p,
    const float* __restrict__ m2p,
    __half* __restrict__ o0, __half* __restrict__ o1, __half* __restrict__ o2)
{
    const int row = blockIdx.x;
    const int t = row % Tn;
    const int tid = threadIdx.x;
    const float* xr = x + (size_t)row * Cn;

    float4 f0 = ((const float4*)xr)[tid];
    float4 f1 = ((const float4*)xr)[tid + 256];
    float v[8] = {f0.x, f0.y, f0.z, f0.w, f1.x, f1.y, f1.z, f1.w};
    float p[8] = {0.f, 0.f, 0.f, 0.f, 0.f, 0.f, 0.f, 0.f};
    if (t > 0) {
        const float* pr = xr - Cn;
        float4 g0 = ((const float4*)pr)[tid];
        float4 g1 = ((const float4*)pr)[tid + 256];
        p[0]=g0.x; p[1]=g0.y; p[2]=g0.z; p[3]=g0.w;
        p[4]=g1.x; p[5]=g1.y; p[6]=g1.z; p[7]=g1.w;
    }

    float sc = 0.f, sc2 = 0.f, sp = 0.f, sp2 = 0.f;
#pragma unroll
    for (int i = 0; i < 8; i++) {
        sc += v[i]; sc2 += v[i] * v[i];
        sp += p[i]; sp2 += p[i] * p[i];
    }
#pragma unroll
    for (int o = 16; o > 0; o >>= 1) {
        sc  += __shfl_xor_sync(0xFFFFFFFFu, sc,  o);
        sc2 += __shfl_xor_sync(0xFFFFFFFFu, sc2, o);
        sp  += __shfl_xor_sync(0xFFFFFFFFu, sp,  o);
        sp2 += __shfl_xor_sync(0xFFFFFFFFu, sp2, o);
    }
    __shared__ float sh[32];
    const int wid = tid >> 5, lane = tid & 31;
    if (lane == 0) {
        sh[wid] = sc; sh[wid + 8] = sc2; sh[wid + 16] = sp; sh[wid + 24] = sp2;
    }
    __syncthreads();
    if (tid < 32) {
        const int g = tid >> 3, l = tid & 7;   // 4 groups of 8
        float a = sh[g * 8 + l];
#pragma unroll
        for (int o = 4; o > 0; o >>= 1)
            a += __shfl_xor_sync(0xFFFFFFFFu, a, o);
        if (l == 0) sh[g] = a;
    }
    __syncthreads();

    const float mu_c  = sh[0] * (1.f / Cn);
    const float inv_c = rsqrtf(sh[1] * (1.f / Cn) - mu_c * mu_c + 1e-5f);
    const float mu_p  = sh[2] * (1.f / Cn);
    const float inv_p = rsqrtf(sh[3] * (1.f / Cn) - mu_p * mu_p + 1e-5f);

#pragma unroll
    for (int j = 0; j < 2; j++) {
        const int c = (tid + j * 256) * 4;
        float4 xn4, xx4;
        const float* vv = v + j * 4;
        const float* pp = p + j * 4;
        xn4.x = (vv[0] - mu_c) * inv_c * w[c + 0] + b[c + 0];
        xn4.y = (vv[1] - mu_c) * inv_c * w[c + 1] + b[c + 1];
        xn4.z = (vv[2] - mu_c) * inv_c * w[c + 2] + b[c + 2];
        xn4.w = (vv[3] - mu_c) * inv_c * w[c + 3] + b[c + 3];
        if (t > 0) {
            xx4.x = (pp[0] - mu_p) * inv_p * w[c + 0] + b[c + 0];
            xx4.y = (pp[1] - mu_p) * inv_p * w[c + 1] + b[c + 1];
            xx4.z = (pp[2] - mu_p) * inv_p * w[c + 2] + b[c + 2];
            xx4.w = (pp[3] - mu_p) * inv_p * w[c + 3] + b[c + 3];
        } else {
            xx4 = make_float4(0.f, 0.f, 0.f, 0.f);
        }
        const size_t po = apack_off(row, c, Cn);
        store_h4(lerp4(xn4, xx4, *(const float4*)(m0p + c)), o0, po);
        store_h4(lerp4(xn4, xx4, *(const float4*)(m1p + c)), o1, po);
        if (NOUT == 3)
            store_h4(lerp4(xn4, xx4, *(const float4*)(m2p + c)), o2, po);
    }
}

// Weight convert fp32 -> packed fp16 B layout. K = inner dim of W[N,K].
__global__ __launch_bounds__(256) void conv_w(
    const float* __restrict__ w, __half* __restrict__ h, int K)
{
    const size_t i4 = (size_t)blockIdx.x * blockDim.x + threadIdx.x;
    const size_t idx = i4 * 4;
    const int n = (int)(idx / K);
    const int k = (int)(idx % K);
    float4 v = *(const float4*)(w + idx);
    store_h4(v, h, bpack_off(n, k, K));
}

// ---------------------------------------------------------------------------
// WKV recurrence + sigmoid(r) gate. Block-level ping-pong prefetch (depth 8).
// ---------------------------------------------------------------------------
#define WKV_PF 8

__global__ __launch_bounds__(64) void wkv_gate_kernel(
    const float* __restrict__ k, const float* __restrict__ v,
    const __half* __restrict__ rp,
    const float* __restrict__ w_decay, const float* __restrict__ u_first,
    __half* __restrict__ g)
{
    const int idx = blockIdx.x * blockDim.x + threadIdx.x;
    const int c = idx % Cn;
    const int b = idx / Cn;
    const float w = -expf(w_decay[c]);
    const float u = u_first[c];

    const size_t off0 = (size_t)b * Tn * Cn + c;
    const int m0 = b * Tn;

    float kA[WKV_PF], vA[WKV_PF], rA[WKV_PF];
    float kB[WKV_PF], vB[WKV_PF], rB[WKV_PF];

#pragma unroll
    for (int j = 0; j < WKV_PF; j++) {
        kA[j] = k[off0 + (size_t)j * Cn];
        vA[j] = v[off0 + (size_t)j * Cn];
        rA[j] = __half2float(rp[apack_off(m0 + j, c, Cn)]);
    }

    float aa = 0.f, bb = 0.f, pp = -1e38f;
    for (int t0 = 0; t0 < Tn; t0 += WKV_PF) {
        const bool more = (t0 + WKV_PF) < Tn;
        if (more) {
            const size_t offn = off0 + (size_t)(t0 + WKV_PF) * Cn;
            const int mn = m0 + t0 + WKV_PF;
#pragma unroll
            for (int j = 0; j < WKV_PF; j++) {
                kB[j] = k[offn + (size_t)j * Cn];
                vB[j] = v[offn + (size_t)j * Cn];
                rB[j] = __half2float(rp[apack_off(mn + j, c, Cn)]);
            }
        }

#pragma unroll
        for (int j = 0; j < WKV_PF; j++) {
            const float kt = kA[j];
            const float vt = vA[j];
            const float rr = rA[j];

            const float ww = u + kt;
            const float pmx = fmaxf(pp, ww);
            const float e1 = __expf(pp - pmx);
            const float e2 = __expf(ww - pmx);
            const float y  = __fdividef(e1 * aa + e2 * vt, e1 * bb + e2);
            const float sg = __fdividef(1.f, 1.f + __expf(-rr));
            g[apack_off(m0 + t0 + j, c, Cn)] = __float2half_rn(y * sg);

            const float ww2 = pp + w;
            const float p2  = fmaxf(ww2, kt);
            const float e1b = __expf(ww2 - p2);
            const float e2b = __expf(kt - p2);
            aa = e1b * aa + e2b * vt;
            bb = e1b * bb + e2b;
            pp = p2;
        }

        if (more) {
#pragma unroll
            for (int j = 0; j < WKV_PF; j++) {
                kA[j] = kB[j];
                vA[j] = vB[j];
                rA[j] = rB[j];
            }
        }
    }
}

// ---------------------------------------------------------------------------
// HMMA fp16 GEMM over packed tiles:  C[M,N] = A[M,K] @ B[N,K]^T
// CTA 128x256, 8 warps (2x4) of 64x64, BK=128, 2-stage cp.async.bulk.
// Producer-consumer sync: full mbarriers (tx-based) + empty mbarriers
// (256-thread arrive); only tid0 waits for empty before refilling, so
// warps never rendezvous inside the mainloop.
// EPI: 0 fp32; 1 +res0; 2 relu^2 -> packed fp16; 3 res0 + sigmoid*res1;
//      4 packed fp16 (plain)
// ---------------------------------------------------------------------------
static constexpr int AT64 = A_TILE_H * 2;     // 18432 B (one 64-k A tile)
static constexpr int BT64 = B_TILE_H * 2;     // 36864 B (one 64-k B tile)
static constexpr int STAGE = 2 * (AT64 + BT64);   // 110592 B (BK=128)
static constexpr int SMEM_DYN = 2 * STAGE;        // 221184 B

template <int EPI>
__global__ __launch_bounds__(256, 1) void gemmp(
    const __half* __restrict__ Ap, const __half* __restrict__ Bp,
    float* __restrict__ Cm, __half* __restrict__ Ohp,
    int N, int K,
    const float* __restrict__ res0, const float* __restrict__ res1)
{
    extern __shared__ __align__(128) char dsm[];
    __shared__ __align__(8) uint64_t s_mbar[4];   // full0, full1, empty0, empty1

    const uint32_t sb = smem_u32(dsm);
    const uint32_t mbf = smem_u32(s_mbar);
    const uint32_t mbe = mbf + 16;
    const int tid = threadIdx.x, wid = tid >> 5, lane = tid & 31;
    const int m0 = blockIdx.y * 128, n0 = blockIdx.x * 256;
    const int wm = wid >> 2, wn = wid & 3;   // 2 x 4 warps of 64x64

    const int nk = K >> 7;                   // BK = 128
    const __half* gA = Ap + (size_t)blockIdx.y * (K >> 6) * A_TILE_H;
    const __half* gB = Bp + (size_t)blockIdx.x * (K >> 6) * B_TILE_H;

    if (tid == 0) {
        MBAR_INIT(mbf + 0, 1);
        MBAR_INIT(mbf + 8, 1);
        MBAR_INIT(mbe + 0, 256);
        MBAR_INIT(mbe + 8, 256);
    }
    __syncthreads();

    if (tid == 0) {
#pragma unroll
        for (int s = 0; s < 2; s++) {
            MBAR_EXPECT_TX(mbf + s * 8, STAGE);
            BULK_G2S(sb + s * STAGE,
                     gA + (size_t)s * 2 * A_TILE_H, 2 * AT64, mbf + s * 8);
            BULK_G2S(sb + s * STAGE + 2 * AT64,
                     gB + (size_t)s * 2 * B_TILE_H, 2 * BT64, mbf + s * 8);
        }
    }

    float acc[4][8][4];
#pragma unroll
    for (int a = 0; a < 4; a++)
#pragma unroll
        for (int b = 0; b < 8; b++)
#pragma unroll
            for (int c = 0; c < 4; c++) acc[a][b][c] = 0.f;

    const int a_row  = wm * 64 + (lane & 15);
    const int a_koff = (lane & 16) ? 8 : 0;
    const int b_row  = wn * 64 + (lane & 7) + ((lane & 16) ? 8 : 0);
    const int b_koff = (lane & 8) ? 8 : 0;

    int s = 0;
    uint32_t parf = 0, pare = 0;
    for (int i = 0; i < nk; i++) {
        MBAR_WAIT(mbf + s * 8, (parf >> s) & 1u);
        parf ^= (1u << s);

        const uint32_t st = sb + s * STAGE;
#pragma unroll
        for (int half = 0; half < 2; half++) {
            const uint32_t abase = st + half * AT64;
            const uint32_t bbase = st + 2 * AT64 + half * BT64;
#pragma unroll
            for (int k16 = 0; k16 < 4; k16++) {
                uint32_t ah[4][4];
                const uint32_t acol = (uint32_t)(k16 * 16 + a_koff) * 2;
#pragma unroll
                for (int mt = 0; mt < 4; mt++) {
                    const uint32_t ad = abase +
                        (uint32_t)(a_row + mt * 16) * (PADH * 2) + acol;
                    ldsm4(ah[mt][0], ah[mt][1], ah[mt][2], ah[mt][3], ad);
                }
                uint32_t bh[8][2];
                const uint32_t bcol = (uint32_t)(k16 * 16 + b_koff) * 2;
#pragma unroll
                for (int pq = 0; pq < 4; pq++) {
                    const uint32_t bd = bbase +
                        (uint32_t)(b_row + pq * 16) * (PADH * 2) + bcol;
                    ldsm4(bh[2*pq][0], bh[2*pq][1], bh[2*pq+1][0], bh[2*pq+1][1], bd);
                }
#pragma unroll
                for (int mt = 0; mt < 4; mt++)
#pragma unroll
                    for (int nt = 0; nt < 8; nt++)
                        mma16816(acc[mt][nt], ah[mt], bh[nt]);
            }
        }

        // signal this stage consumed (per-thread arrive; no rendezvous)
        MBAR_ARRIVE(mbe + s * 8);

        if (tid == 0 && i + 2 < nk) {
            // producer: wait until all threads have consumed stage s, refill it
            MBAR_WAIT(mbe + s * 8, (pare >> s) & 1u);
            pare ^= (1u << s);
            MBAR_EXPECT_TX(mbf + s * 8, STAGE);
            BULK_G2S(sb + s * STAGE,
                     gA + (size_t)(i + 2) * 2 * A_TILE_H, 2 * AT64, mbf + s * 8);
            BULK_G2S(sb + s * STAGE + 2 * AT64,
                     gB + (size_t)(i + 2) * 2 * B_TILE_H, 2 * BT64, mbf + s * 8);
        }
        s ^= 1;
    }

    // Epilogue: registers -> global
    const int row_base = m0 + wm * 64 + (lane >> 2);
    const int col_base = n0 + wn * 64 + (lane & 3) * 2;
#pragma unroll
    for (int mt = 0; mt < 4; mt++) {
#pragma unroll
        for (int h = 0; h < 2; h++) {
            const int row = row_base + mt * 16 + h * 8;
#pragma unroll
            for (int nt = 0; nt < 8; nt++) {
                float vx = acc[mt][nt][2 * h + 0];
                float vy = acc[mt][nt][2 * h + 1];
                const int col = col_base + nt * 8;
                const size_t off = (size_t)row * N + col;
                if (EPI == 0) {
                    *(float2*)(Cm + off) = make_float2(vx, vy);
                } else if (EPI == 1) {
                    float2 r = *(const float2*)(res0 + off);
                    *(float2*)(Cm + off) = make_float2(vx + r.x, vy + r.y);
                } else if (EPI == 2) {
                    vx = fmaxf(vx, 0.f); vx *= vx;
                    vy = fmaxf(vy, 0.f); vy *= vy;
                    *(uint32_t*)(Ohp + apack_off(row, col, N)) = pack2h(vx, vy);
                } else if (EPI == 4) {
                    *(uint32_t*)(Ohp + apack_off(row, col, N)) = pack2h(vx, vy);
                } else {
                    float2 r0 = *(const float2*)(res0 + off);
                    float2 r1 = *(const float2*)(res1 + off);
                    vx = r0.x + r1.x / (1.f + __expf(-vx));
                    vy = r0.y + r1.y / (1.f + __expf(-vy));
                    *(float2*)(Cm + off) = make_float2(vx, vy);
                }
            }
        }
    }
}

// ---------------------------------------------------------------------------
// Launch
// ---------------------------------------------------------------------------
extern "C" void kernel_launch(void* const* d_in, const int* in_sizes, int n_in,
                              void* d_out, int out_size)
{
    (void)in_sizes; (void)n_in; (void)out_size;
    const float* x    = (const float*)d_in[0];
    const float* ln1w = (const float*)d_in[1];
    const float* ln1b = (const float*)d_in[2];
    const float* ln2w = (const float*)d_in[3];
    const float* ln2b = (const float*)d_in[4];
    const float* tdec = (const float*)d_in[5];
    const float* tfir = (const float*)d_in[6];
    const float* tmk  = (const float*)d_in[7];
    const float* tmv  = (const float*)d_in[8];
    const float* tmr  = (const float*)d_in[9];
    const float* Wk   = (const float*)d_in[10];
    const float* Wv   = (const float*)d_in[11];
    const float* Wr   = (const float*)d_in[12];
    const float* Wo   = (const float*)d_in[13];
    const float* cmk  = (const float*)d_in[14];
    const float* cmr  = (const float*)d_in[15];
    const float* Wck  = (const float*)d_in[16];
    const float* Wcv  = (const float*)d_in[17];
    const float* Wcr  = (const float*)d_in[18];
    float* out = (float*)d_out;

    float *kf, *vf, *x1, *kv;
    __half *a0, *a1, *a2, *hb;
    __half *wk, *wv, *wr, *wo, *wck, *wcv, *wcr;
    cudaGetSymbolAddress((void**)&kf, g_k);
    cudaGetSymbolAddress((void**)&vf, g_v);
    cudaGetSymbolAddress((void**)&x1, g_x1);
    cudaGetSymbolAddress((void**)&kv, g_kv);
    cudaGetSymbolAddress((void**)&a0, g_a0);
    cudaGetSymbolAddress((void**)&a1, g_a1);
    cudaGetSymbolAddress((void**)&a2, g_a2);
    cudaGetSymbolAddress((void**)&hb, g_h);
    cudaGetSymbolAddress((void**)&wk, g_wk);
    cudaGetSymbolAddress((void**)&wv, g_wv);
    cudaGetSymbolAddress((void**)&wr, g_wr);
    cudaGetSymbolAddress((void**)&wo, g_wo);
    cudaGetSymbolAddress((void**)&wck, g_wck);
    cudaGetSymbolAddress((void**)&wcv, g_wcv);
    cudaGetSymbolAddress((void**)&wcr, g_wcr);

    cudaFuncSetAttribute(gemmp<0>, cudaFuncAttributeMaxDynamicSharedMemorySize, SMEM_DYN);
    cudaFuncSetAttribute(gemmp<1>, cudaFuncAttributeMaxDynamicSharedMemorySize, SMEM_DYN);
    cudaFuncSetAttribute(gemmp<2>, cudaFuncAttributeMaxDynamicSharedMemorySize, SMEM_DYN);
    cudaFuncSetAttribute(gemmp<3>, cudaFuncAttributeMaxDynamicSharedMemorySize, SMEM_DYN);
    cudaFuncSetAttribute(gemmp<4>, cudaFuncAttributeMaxDynamicSharedMemorySize, SMEM_DYN);

    const int wCC = (Cn * Cn / 4) / 256;
    const int wHC = (Hn * Cn / 4) / 256;
    const dim3 gC(Cn / 256, Mn / 128);   // (8, 128)
    const dim3 gH(Hn / 256, Mn / 128);   // (32, 128)

    // --- all weight conversions up-front (independent of activations) ---
    conv_w<<<wCC, 256>>>(Wk,  wk,  Cn);
    conv_w<<<wCC, 256>>>(Wv,  wv,  Cn);
    conv_w<<<wCC, 256>>>(Wr,  wr,  Cn);
    conv_w<<<wCC, 256>>>(Wo,  wo,  Cn);
    conv_w<<<wHC, 256>>>(Wck, wck, Cn);
    conv_w<<<wHC, 256>>>(Wcv, wcv, Hn);
    conv_w<<<wCC, 256>>>(Wcr, wcr, Cn);

    // --- time-mix attention ---
    ln_mix<3><<<Mn, 256>>>(x, ln1w, ln1b, tmk, tmv, tmr, a0, a1, a2);

    gemmp<0><<<gC, 256, SMEM_DYN>>>(a0, wk, kf, nullptr, Cn, Cn, nullptr, nullptr);
    gemmp<0><<<gC, 256, SMEM_DYN>>>(a1, wv, vf, nullptr, Cn, Cn, nullptr, nullptr);
    gemmp<4><<<gC, 256, SMEM_DYN>>>(a2, wr, nullptr, a0, Cn, Cn, nullptr, nullptr);

    wkv_gate_kernel<<<(Bn * Cn) / 64, 64>>>(kf, vf, a0, tdec, tfir, a1);

    gemmp<1><<<gC, 256, SMEM_DYN>>>(a1, wo, x1, nullptr, Cn, Cn, x, nullptr);

    // --- channel mix ---
    ln_mix<2><<<Mn, 256>>>(x1, ln2w, ln2b, cmk, cmr, nullptr, a0, a2, nullptr);

    gemmp<2><<<gH, 256, SMEM_DYN>>>(a0, wck, nullptr, hb, Hn, Cn, nullptr, nullptr);
    gemmp<0><<<gC, 256, SMEM_DYN>>>(hb, wcv, kv, nullptr, Cn, Hn, nullptr, nullptr);
    gemmp<3><<<gC, 256, SMEM_DYN>>>(a2, wcr, out, nullptr, Cn, Cn, x1, kv);
}

// round 15
// speedup vs baseline: 14.6959x; 1.0171x over previous
#include <cuda_runtime.h>
#include <cuda_fp16.h>
#include <math.h>
#include <stdint.h>

#define Bn 8
#define Tn 2048
#define Cn 2048
#define Hn 8192
#define Mn (Bn * Tn)   // 16384

// Packed-tile geometry: rows padded to 72 halfs (144B) for conflict-free ldsm.
#define PADH 72
#define A_TILE_H (128 * PADH)       // halfs per 128x64 A tile
#define B_TILE_H (256 * PADH)       // halfs per 256x64 B tile

// ---------------------------------------------------------------------------
// Scratch (device globals — allocation-free per harness rules)
// ---------------------------------------------------------------------------
__device__ float g_k [(size_t)Mn * Cn];
__device__ float g_v [(size_t)Mn * Cn];
__device__ float g_x1[(size_t)Mn * Cn];
__device__ float g_kv[(size_t)Mn * Cn];
__device__ __align__(128) __half g_a0[(size_t)Mn * Cn / 64 * PADH];
__device__ __align__(128) __half g_a1[(size_t)Mn * Cn / 64 * PADH];
__device__ __align__(128) __half g_a2[(size_t)Mn * Cn / 64 * PADH];
__device__ __align__(128) __half g_h [(size_t)Mn * Hn / 64 * PADH];
// dedicated packed weight buffers (converted once up-front each launch)
__device__ __align__(128) __half g_wk [(size_t)Cn * Cn / 64 * PADH];
__device__ __align__(128) __half g_wv [(size_t)Cn * Cn / 64 * PADH];
__device__ __align__(128) __half g_wr [(size_t)Cn * Cn / 64 * PADH];
__device__ __align__(128) __half g_wo [(size_t)Cn * Cn / 64 * PADH];
__device__ __align__(128) __half g_wck[(size_t)Hn * Cn / 64 * PADH];
__device__ __align__(128) __half g_wcv[(size_t)Hn * Cn / 64 * PADH];
__device__ __align__(128) __half g_wcr[(size_t)Cn * Cn / 64 * PADH];

// ---------------------------------------------------------------------------
// Packed-offset helpers (half-element index)
// ---------------------------------------------------------------------------
__device__ __forceinline__ size_t apack_off(int m, int k, int K) {
    return ((size_t)(m >> 7) * (K >> 6) + (k >> 6)) * A_TILE_H
           + (size_t)(m & 127) * PADH + (k & 63);
}
__device__ __forceinline__ size_t bpack_off(int n, int k, int K) {
    return ((size_t)(n >> 8) * (K >> 6) + (k >> 6)) * B_TILE_H
           + (size_t)(n & 255) * PADH + (k & 63);
}

// ---------------------------------------------------------------------------
// PTX helpers (baseline sm_103 — NO "a"-suffix features)
// ---------------------------------------------------------------------------
__device__ __forceinline__ uint32_t smem_u32(const void* p) {
    uint32_t a;
    asm("{ .reg .u64 t; cvta.to.shared.u64 t, %1; cvt.u32.u64 %0, t; }"
        : "=r"(a) : "l"(p));
    return a;
}

#define MBAR_INIT(mb, cnt) \
    asm volatile("mbarrier.init.shared.b64 [%0], %1;" :: "r"(mb), "r"((uint32_t)(cnt)) : "memory")

#define MBAR_EXPECT_TX(mb, bytes) \
    asm volatile("mbarrier.arrive.expect_tx.shared.b64 _, [%0], %1;" \
                 :: "r"(mb), "r"((uint32_t)(bytes)) : "memory")

#define MBAR_ARRIVE(mb) \
    asm volatile("mbarrier.arrive.shared.b64 _, [%0];" :: "r"(mb) : "memory")

#define MBAR_WAIT(mb, ph) do {                                            \
    uint32_t _m = (mb); uint32_t _p = (uint32_t)(ph); uint32_t _d;        \
    asm volatile("{ .reg .pred p;"                                        \
        " mbarrier.try_wait.parity.acquire.cta.shared::cta.b64 p, [%1], %2;" \
        " selp.b32 %0, 1, 0, p; }"                                        \
        : "=r"(_d) : "r"(_m), "r"(_p) : "memory");                        \
    if (!_d) {                                                            \
        asm volatile("{ .reg .pred P1;"                                   \
            " WL_%=:"                                                     \
            " mbarrier.try_wait.parity.acquire.cta.shared::cta.b64 P1, [%0], %1, 0x989680;" \
            " @P1 bra.uni WD_%=;"                                         \
            " bra.uni WL_%=;"                                             \
            " WD_%=: }" :: "r"(_m), "r"(_p) : "memory");                  \
    }                                                                     \
} while (0)

#define BULK_G2S(dst, src, sz, mb) \
    asm volatile("cp.async.bulk.shared::cluster.global.mbarrier::complete_tx::bytes " \
                 "[%0], [%1], %2, [%3];" \
                 :: "r"(dst), "l"(src), "r"((uint32_t)(sz)), "r"(mb) : "memory")

__device__ __forceinline__ void ldsm4(uint32_t& r0, uint32_t& r1,
                                      uint32_t& r2, uint32_t& r3, uint32_t a) {
    asm volatile("ldmatrix.sync.aligned.m8n8.x4.shared.b16 {%0,%1,%2,%3}, [%4];"
                 : "=r"(r0), "=r"(r1), "=r"(r2), "=r"(r3) : "r"(a));
}

__device__ __forceinline__ void mma16816(float* d, const uint32_t* a,
                                         const uint32_t* b) {
    asm volatile(
        "mma.sync.aligned.m16n8k16.row.col.f32.f16.f16.f32 "
        "{%0,%1,%2,%3}, {%4,%5,%6,%7}, {%8,%9}, {%0,%1,%2,%3};"
        : "+f"(d[0]), "+f"(d[1]), "+f"(d[2]), "+f"(d[3])
        : "r"(a[0]), "r"(a[1]), "r"(a[2]), "r"(a[3]), "r"(b[0]), "r"(b[1]));
}

// ---------------------------------------------------------------------------
// fp16 pack helpers
// ---------------------------------------------------------------------------
__device__ __forceinline__ uint32_t pack2h(float x, float y) {
    __half2 t = __floats2half2_rn(x, y);
    return *reinterpret_cast<uint32_t*>(&t);
}

__device__ __forceinline__ void store_h4(float4 v, __half* p, size_t idx) {
    uint2 u;
    u.x = pack2h(v.x, v.y);
    u.y = pack2h(v.z, v.w);
    *(uint2*)(p + idx) = u;
}

__device__ __forceinline__ float4 lerp4(float4 cur, float4 prev, float4 m) {
    float4 r;
    r.x = cur.x * m.x + prev.x * (1.f - m.x);
    r.y = cur.y * m.y + prev.y * (1.f - m.y);
    r.z = cur.z * m.z + prev.z * (1.f - m.z);
    r.w = cur.w * m.w + prev.w * (1.f - m.w);
    return r;
}

// ---------------------------------------------------------------------------
// Fused LayerNorm + time-shift mix → packed fp16.
// ---------------------------------------------------------------------------
template <int NOUT>
__global__ __launch_bounds__(256) void ln_mix(
    const float* __restrict__ x, const float* __restrict__ w,
    const float* __restrict__ b,
    const float* __restrict__ m0p, const float* __restrict__ m1p,
    const float* __restrict__ m2p,
    __half* __restrict__ o0, __half* __restrict__ o1, __half* __restrict__ o2)
{
    const int row = blockIdx.x;
    const int t = row % Tn;
    const int tid = threadIdx.x;
    const float* xr = x + (size_t)row * Cn;

    float4 f0 = ((const float4*)xr)[tid];
    float4 f1 = ((const float4*)xr)[tid + 256];
    float v[8] = {f0.x, f0.y, f0.z, f0.w, f1.x, f1.y, f1.z, f1.w};
    float p[8] = {0.f, 0.f, 0.f, 0.f, 0.f, 0.f, 0.f, 0.f};
    if (t > 0) {
        const float* pr = xr - Cn;
        float4 g0 = ((const float4*)pr)[tid];
        float4 g1 = ((const float4*)pr)[tid + 256];
        p[0]=g0.x; p[1]=g0.y; p[2]=g0.z; p[3]=g0.w;
        p[4]=g1.x; p[5]=g1.y; p[6]=g1.z; p[7]=g1.w;
    }

    float sc = 0.f, sc2 = 0.f, sp = 0.f, sp2 = 0.f;
#pragma unroll
    for (int i = 0; i < 8; i++) {
        sc += v[i]; sc2 += v[i] * v[i];
        sp += p[i]; sp2 += p[i] * p[i];
    }
#pragma unroll
    for (int o = 16; o > 0; o >>= 1) {
        sc  += __shfl_xor_sync(0xFFFFFFFFu, sc,  o);
        sc2 += __shfl_xor_sync(0xFFFFFFFFu, sc2, o);
        sp  += __shfl_xor_sync(0xFFFFFFFFu, sp,  o);
        sp2 += __shfl_xor_sync(0xFFFFFFFFu, sp2, o);
    }
    __shared__ float sh[32];
    const int wid = tid >> 5, lane = tid & 31;
    if (lane == 0) {
        sh[wid] = sc; sh[wid + 8] = sc2; sh[wid + 16] = sp; sh[wid + 24] = sp2;
    }
    __syncthreads();
    if (tid < 32) {
        const int g = tid >> 3, l = tid & 7;   // 4 groups of 8
        float a = sh[g * 8 + l];
#pragma unroll
        for (int o = 4; o > 0; o >>= 1)
            a += __shfl_xor_sync(0xFFFFFFFFu, a, o);
        if (l == 0) sh[g] = a;
    }
    __syncthreads();

    const float mu_c  = sh[0] * (1.f / Cn);
    const float inv_c = rsqrtf(sh[1] * (1.f / Cn) - mu_c * mu_c + 1e-5f);
    const float mu_p  = sh[2] * (1.f / Cn);
    const float inv_p = rsqrtf(sh[3] * (1.f / Cn) - mu_p * mu_p + 1e-5f);

#pragma unroll
    for (int j = 0; j < 2; j++) {
        const int c = (tid + j * 256) * 4;
        float4 xn4, xx4;
        const float* vv = v + j * 4;
        const float* pp = p + j * 4;
        xn4.x = (vv[0] - mu_c) * inv_c * w[c + 0] + b[c + 0];
        xn4.y = (vv[1] - mu_c) * inv_c * w[c + 1] + b[c + 1];
        xn4.z = (vv[2] - mu_c) * inv_c * w[c + 2] + b[c + 2];
        xn4.w = (vv[3] - mu_c) * inv_c * w[c + 3] + b[c + 3];
        if (t > 0) {
            xx4.x = (pp[0] - mu_p) * inv_p * w[c + 0] + b[c + 0];
            xx4.y = (pp[1] - mu_p) * inv_p * w[c + 1] + b[c + 1];
            xx4.z = (pp[2] - mu_p) * inv_p * w[c + 2] + b[c + 2];
            xx4.w = (pp[3] - mu_p) * inv_p * w[c + 3] + b[c + 3];
        } else {
            xx4 = make_float4(0.f, 0.f, 0.f, 0.f);
        }
        const size_t po = apack_off(row, c, Cn);
        store_h4(lerp4(xn4, xx4, *(const float4*)(m0p + c)), o0, po);
        store_h4(lerp4(xn4, xx4, *(const float4*)(m1p + c)), o1, po);
        if (NOUT == 3)
            store_h4(lerp4(xn4, xx4, *(const float4*)(m2p + c)), o2, po);
    }
}

// Weight convert fp32 -> packed fp16 B layout. K = inner dim of W[N,K].
__global__ __launch_bounds__(256) void conv_w(
    const float* __restrict__ w, __half* __restrict__ h, int K)
{
    const size_t i4 = (size_t)blockIdx.x * blockDim.x + threadIdx.x;
    const size_t idx = i4 * 4;
    const int n = (int)(idx / K);
    const int k = (int)(idx % K);
    float4 v = *(const float4*)(w + idx);
    store_h4(v, h, bpack_off(n, k, K));
}

// ---------------------------------------------------------------------------
// WKV recurrence + sigmoid(r) gate. Block-level ping-pong prefetch (depth 8).
// ---------------------------------------------------------------------------
#define WKV_PF 8

__global__ __launch_bounds__(64) void wkv_gate_kernel(
    const float* __restrict__ k, const float* __restrict__ v,
    const __half* __restrict__ rp,
    const float* __restrict__ w_decay, const float* __restrict__ u_first,
    __half* __restrict__ g)
{
    const int idx = blockIdx.x * blockDim.x + threadIdx.x;
    const int c = idx % Cn;
    const int b = idx / Cn;
    const float w = -expf(w_decay[c]);
    const float u = u_first[c];

    const size_t off0 = (size_t)b * Tn * Cn + c;
    const int m0 = b * Tn;

    float kA[WKV_PF], vA[WKV_PF], rA[WKV_PF];
    float kB[WKV_PF], vB[WKV_PF], rB[WKV_PF];

#pragma unroll
    for (int j = 0; j < WKV_PF; j++) {
        kA[j] = k[off0 + (size_t)j * Cn];
        vA[j] = v[off0 + (size_t)j * Cn];
        rA[j] = __half2float(rp[apack_off(m0 + j, c, Cn)]);
    }

    float aa = 0.f, bb = 0.f, pp = -1e38f;
    for (int t0 = 0; t0 < Tn; t0 += WKV_PF) {
        const bool more = (t0 + WKV_PF) < Tn;
        if (more) {
            const size_t offn = off0 + (size_t)(t0 + WKV_PF) * Cn;
            const int mn = m0 + t0 + WKV_PF;
#pragma unroll
            for (int j = 0; j < WKV_PF; j++) {
                kB[j] = k[offn + (size_t)j * Cn];
                vB[j] = v[offn + (size_t)j * Cn];
                rB[j] = __half2float(rp[apack_off(mn + j, c, Cn)]);
            }
        }

#pragma unroll
        for (int j = 0; j < WKV_PF; j++) {
            const float kt = kA[j];
            const float vt = vA[j];
            const float rr = rA[j];

            const float ww = u + kt;
            const float pmx = fmaxf(pp, ww);
            const float e1 = __expf(pp - pmx);
            const float e2 = __expf(ww - pmx);
            const float y  = __fdividef(e1 * aa + e2 * vt, e1 * bb + e2);
            const float sg = __fdividef(1.f, 1.f + __expf(-rr));
            g[apack_off(m0 + t0 + j, c, Cn)] = __float2half_rn(y * sg);

            const float ww2 = pp + w;
            const float p2  = fmaxf(ww2, kt);
            const float e1b = __expf(ww2 - p2);
            const float e2b = __expf(kt - p2);
            aa = e1b * aa + e2b * vt;
            bb = e1b * bb + e2b;
            pp = p2;
        }

        if (more) {
#pragma unroll
            for (int j = 0; j < WKV_PF; j++) {
                kA[j] = kB[j];
                vA[j] = vB[j];
                rA[j] = rB[j];
            }
        }
    }
}

// ---------------------------------------------------------------------------
// Persistent HMMA fp16 GEMM over packed tiles:  C[M,N] = A[M,K] @ B[N,K]^T
// 148 persistent CTAs each loop over 128x256 output tiles; the 2-stage
// cp.async.bulk pipeline runs as one continuous chunk sequence ACROSS tile
// boundaries, so prologue latency is paid once per CTA and epilogues overlap
// with the next tile's loads. 8 warps (2x4) of 64x64, BK=128.
// Producer-consumer sync: full mbarriers (tx) + empty mbarriers (256 arrives).
// EPI: 0 fp32; 1 +res0; 2 relu^2 -> packed fp16; 3 res0 + sigmoid*res1;
//      4 packed fp16 (plain)
// ---------------------------------------------------------------------------
static constexpr int AT64 = A_TILE_H * 2;     // 18432 B (one 64-k A tile)
static constexpr int BT64 = B_TILE_H * 2;     // 36864 B (one 64-k B tile)
static constexpr int STAGE = 2 * (AT64 + BT64);   // 110592 B (BK=128)
static constexpr int SMEM_DYN = 2 * STAGE;        // 221184 B
static constexpr int GPERS = 148;                 // persistent grid size

template <int EPI>
__global__ __launch_bounds__(256, 1) void gemmp(
    const __half* __restrict__ Ap, const __half* __restrict__ Bp,
    float* __restrict__ Cm, __half* __restrict__ Ohp,
    int N, int K, int ntiles,
    const float* __restrict__ res0, const float* __restrict__ res1)
{
    extern __shared__ __align__(128) char dsm[];
    __shared__ __align__(8) uint64_t s_mbar[4];   // full0, full1, empty0, empty1

    const uint32_t sb = smem_u32(dsm);
    const uint32_t mbf = smem_u32(s_mbar);
    const uint32_t mbe = mbf + 16;
    const int tid = threadIdx.x, wid = tid >> 5, lane = tid & 31;
    const int wm = wid >> 2, wn = wid & 3;   // 2 x 4 warps of 64x64
    const int bid = blockIdx.x;
    const int nbx = N >> 8;                  // tiles along N
    const int nk = K >> 7;                   // BK = 128 chunks per tile
    const int kt64 = K >> 6;                 // 64-k tiles per row/col

    // tiles assigned to this CTA: t = bid + j*GPERS, j = 0..ntpc-1
    const int ntpc = (ntiles - bid + GPERS - 1) / GPERS;
    if (ntpc <= 0) return;
    const int total = ntpc * nk;             // total chunk sequence length

    if (tid == 0) {
        MBAR_INIT(mbf + 0, 1);
        MBAR_INIT(mbf + 8, 1);
        MBAR_INIT(mbe + 0, 256);
        MBAR_INIT(mbe + 8, 256);
    }
    __syncthreads();

    // prologue: load chunk seq 0 and 1 (both belong to first tile; nk >= 2)
    if (tid == 0) {
        const int t0i = bid;
        const int by0 = t0i / nbx, bx0 = t0i % nbx;
#pragma unroll
        for (int s = 0; s < 2; s++) {
            MBAR_EXPECT_TX(mbf + s * 8, STAGE);
            BULK_G2S(sb + s * STAGE,
                     Ap + ((size_t)by0 * kt64 + 2 * s) * A_TILE_H, 2 * AT64, mbf + s * 8);
            BULK_G2S(sb + s * STAGE + 2 * AT64,
                     Bp + ((size_t)bx0 * kt64 + 2 * s) * B_TILE_H, 2 * BT64, mbf + s * 8);
        }
    }

    const int a_row  = wm * 64 + (lane & 15);
    const int a_koff = (lane & 16) ? 8 : 0;
    const int b_row  = wn * 64 + (lane & 7) + ((lane & 16) ? 8 : 0);
    const int b_koff = (lane & 8) ? 8 : 0;

    int s = 0;
    uint32_t parf = 0, pare = 0;
    int seq = 0;

    for (int j = 0; j < ntpc; j++) {
        const int t = bid + j * GPERS;
        const int by = t / nbx, bx = t % nbx;
        const int m0 = by * 128, n0 = bx * 256;

        float acc[4][8][4];
#pragma unroll
        for (int a = 0; a < 4; a++)
#pragma unroll
            for (int b = 0; b < 8; b++)
#pragma unroll
                for (int c = 0; c < 4; c++) acc[a][b][c] = 0.f;

        for (int i = 0; i < nk; i++, seq++) {
            MBAR_WAIT(mbf + s * 8, (parf >> s) & 1u);
            parf ^= (1u << s);

            const uint32_t st = sb + s * STAGE;
#pragma unroll
            for (int half = 0; half < 2; half++) {
                const uint32_t abase = st + half * AT64;
                const uint32_t bbase = st + 2 * AT64 + half * BT64;
#pragma unroll
                for (int k16 = 0; k16 < 4; k16++) {
                    uint32_t ah[4][4];
                    const uint32_t acol = (uint32_t)(k16 * 16 + a_koff) * 2;
#pragma unroll
                    for (int mt = 0; mt < 4; mt++) {
                        const uint32_t ad = abase +
                            (uint32_t)(a_row + mt * 16) * (PADH * 2) + acol;
                        ldsm4(ah[mt][0], ah[mt][1], ah[mt][2], ah[mt][3], ad);
                    }
                    uint32_t bh[8][2];
                    const uint32_t bcol = (uint32_t)(k16 * 16 + b_koff) * 2;
#pragma unroll
                    for (int pq = 0; pq < 4; pq++) {
                        const uint32_t bd = bbase +
                            (uint32_t)(b_row + pq * 16) * (PADH * 2) + bcol;
                        ldsm4(bh[2*pq][0], bh[2*pq][1], bh[2*pq+1][0], bh[2*pq+1][1], bd);
                    }
#pragma unroll
                    for (int mt = 0; mt < 4; mt++)
#pragma unroll
                        for (int nt = 0; nt < 8; nt++)
                            mma16816(acc[mt][nt], ah[mt], bh[nt]);
                }
            }

            // signal this stage consumed (per-thread arrive; no rendezvous)
            MBAR_ARRIVE(mbe + s * 8);

            if (tid == 0 && seq + 2 < total) {
                // producer: wait until all threads consumed stage s, refill it
                MBAR_WAIT(mbe + s * 8, (pare >> s) & 1u);
                pare ^= (1u << s);
                const int sq = seq + 2;
                const int j2 = sq / nk, i2 = sq - j2 * nk;
                const int t2 = bid + j2 * GPERS;
                const int by2 = t2 / nbx, bx2 = t2 % nbx;
                MBAR_EXPECT_TX(mbf + s * 8, STAGE);
                BULK_G2S(sb + s * STAGE,
                         Ap + ((size_t)by2 * kt64 + 2 * i2) * A_TILE_H,
                         2 * AT64, mbf + s * 8);
                BULK_G2S(sb + s * STAGE + 2 * AT64,
                         Bp + ((size_t)bx2 * kt64 + 2 * i2) * B_TILE_H,
                         2 * BT64, mbf + s * 8);
            }
            s ^= 1;
        }

        // Epilogue for tile t (overlaps with next tile's in-flight loads)
        const int row_base = m0 + wm * 64 + (lane >> 2);
        const int col_base = n0 + wn * 64 + (lane & 3) * 2;
#pragma unroll
        for (int mt = 0; mt < 4; mt++) {
#pragma unroll
            for (int h = 0; h < 2; h++) {
                const int row = row_base + mt * 16 + h * 8;
#pragma unroll
                for (int nt = 0; nt < 8; nt++) {
                    float vx = acc[mt][nt][2 * h + 0];
                    float vy = acc[mt][nt][2 * h + 1];
                    const int col = col_base + nt * 8;
                    const size_t off = (size_t)row * N + col;
                    if (EPI == 0) {
                        *(float2*)(Cm + off) = make_float2(vx, vy);
                    } else if (EPI == 1) {
                        float2 r = *(const float2*)(res0 + off);
                        *(float2*)(Cm + off) = make_float2(vx + r.x, vy + r.y);
                    } else if (EPI == 2) {
                        vx = fmaxf(vx, 0.f); vx *= vx;
                        vy = fmaxf(vy, 0.f); vy *= vy;
                        *(uint32_t*)(Ohp + apack_off(row, col, N)) = pack2h(vx, vy);
                    } else if (EPI == 4) {
                        *(uint32_t*)(Ohp + apack_off(row, col, N)) = pack2h(vx, vy);
                    } else {
                        float2 r0 = *(const float2*)(res0 + off);
                        float2 r1 = *(const float2*)(res1 + off);
                        vx = r0.x + r1.x / (1.f + __expf(-vx));
                        vy = r0.y + r1.y / (1.f + __expf(-vy));
                        *(float2*)(Cm + off) = make_float2(vx, vy);
                    }
                }
            }
        }
    }
}

// ---------------------------------------------------------------------------
// Launch
// ---------------------------------------------------------------------------
extern "C" void kernel_launch(void* const* d_in, const int* in_sizes, int n_in,
                              void* d_out, int out_size)
{
    (void)in_sizes; (void)n_in; (void)out_size;
    const float* x    = (const float*)d_in[0];
    const float* ln1w = (const float*)d_in[1];
    const float* ln1b = (const float*)d_in[2];
    const float* ln2w = (const float*)d_in[3];
    const float* ln2b = (const float*)d_in[4];
    const float* tdec = (const float*)d_in[5];
    const float* tfir = (const float*)d_in[6];
    const float* tmk  = (const float*)d_in[7];
    const float* tmv  = (const float*)d_in[8];
    const float* tmr  = (const float*)d_in[9];
    const float* Wk   = (const float*)d_in[10];
    const float* Wv   = (const float*)d_in[11];
    const float* Wr   = (const float*)d_in[12];
    const float* Wo   = (const float*)d_in[13];
    const float* cmk  = (const float*)d_in[14];
    const float* cmr  = (const float*)d_in[15];
    const float* Wck  = (const float*)d_in[16];
    const float* Wcv  = (const float*)d_in[17];
    const float* Wcr  = (const float*)d_in[18];
    float* out = (float*)d_out;

    float *kf, *vf, *x1, *kv;
    __half *a0, *a1, *a2, *hb;
    __half *wk, *wv, *wr, *wo, *wck, *wcv, *wcr;
    cudaGetSymbolAddress((void**)&kf, g_k);
    cudaGetSymbolAddress((void**)&vf, g_v);
    cudaGetSymbolAddress((void**)&x1, g_x1);
    cudaGetSymbolAddress((void**)&kv, g_kv);
    cudaGetSymbolAddress((void**)&a0, g_a0);
    cudaGetSymbolAddress((void**)&a1, g_a1);
    cudaGetSymbolAddress((void**)&a2, g_a2);
    cudaGetSymbolAddress((void**)&hb, g_h);
    cudaGetSymbolAddress((void**)&wk, g_wk);
    cudaGetSymbolAddress((void**)&wv, g_wv);
    cudaGetSymbolAddress((void**)&wr, g_wr);
    cudaGetSymbolAddress((void**)&wo, g_wo);
    cudaGetSymbolAddress((void**)&wck, g_wck);
    cudaGetSymbolAddress((void**)&wcv, g_wcv);
    cudaGetSymbolAddress((void**)&wcr, g_wcr);

    cudaFuncSetAttribute(gemmp<0>, cudaFuncAttributeMaxDynamicSharedMemorySize, SMEM_DYN);
    cudaFuncSetAttribute(gemmp<1>, cudaFuncAttributeMaxDynamicSharedMemorySize, SMEM_DYN);
    cudaFuncSetAttribute(gemmp<2>, cudaFuncAttributeMaxDynamicSharedMemorySize, SMEM_DYN);
    cudaFuncSetAttribute(gemmp<3>, cudaFuncAttributeMaxDynamicSharedMemorySize, SMEM_DYN);
    cudaFuncSetAttribute(gemmp<4>, cudaFuncAttributeMaxDynamicSharedMemorySize, SMEM_DYN);

    const int wCC = (Cn * Cn / 4) / 256;
    const int wHC = (Hn * Cn / 4) / 256;
    const int tC = (Mn / 128) * (Cn / 256);   // 1024 tiles
    const int tH = (Mn / 128) * (Hn / 256);   // 4096 tiles

    // --- all weight conversions up-front (independent of activations) ---
    conv_w<<<wCC, 256>>>(Wk,  wk,  Cn);
    conv_w<<<wCC, 256>>>(Wv,  wv,  Cn);
    conv_w<<<wCC, 256>>>(Wr,  wr,  Cn);
    conv_w<<<wCC, 256>>>(Wo,  wo,  Cn);
    conv_w<<<wHC, 256>>>(Wck, wck, Cn);
    conv_w<<<wHC, 256>>>(Wcv, wcv, Hn);
    conv_w<<<wCC, 256>>>(Wcr, wcr, Cn);

    // --- time-mix attention ---
    ln_mix<3><<<Mn, 256>>>(x, ln1w, ln1b, tmk, tmv, tmr, a0, a1, a2);

    gemmp<0><<<GPERS, 256, SMEM_DYN>>>(a0, wk, kf, nullptr, Cn, Cn, tC, nullptr, nullptr);
    gemmp<0><<<GPERS, 256, SMEM_DYN>>>(a1, wv, vf, nullptr, Cn, Cn, tC, nullptr, nullptr);
    gemmp<4><<<GPERS, 256, SMEM_DYN>>>(a2, wr, nullptr, a0, Cn, Cn, tC, nullptr, nullptr);

    wkv_gate_kernel<<<(Bn * Cn) / 64, 64>>>(kf, vf, a0, tdec, tfir, a1);

    gemmp<1><<<GPERS, 256, SMEM_DYN>>>(a1, wo, x1, nullptr, Cn, Cn, tC, x, nullptr);

    // --- channel mix ---
    ln_mix<2><<<Mn, 256>>>(x1, ln2w, ln2b, cmk, cmr, nullptr, a0, a2, nullptr);

    gemmp<2><<<GPERS, 256, SMEM_DYN>>>(a0, wck, nullptr, hb, Hn, Cn, tH, nullptr, nullptr);
    gemmp<0><<<GPERS, 256, SMEM_DYN>>>(hb, wcv, kv, nullptr, Cn, Hn, tC, nullptr, nullptr);
    gemmp<3><<<GPERS, 256, SMEM_DYN>>>(a2, wcr, out, nullptr, Cn, Cn, tC, x1, kv);
}

// round 16
// speedup vs baseline: 14.7282x; 1.0022x over previous
#include <cuda_runtime.h>
#include <cuda_fp16.h>
#include <math.h>
#include <stdint.h>

#define Bn 8
#define Tn 2048
#define Cn 2048
#define Hn 8192
#define Mn (Bn * Tn)   // 16384

// Packed-tile geometry: rows padded to 72 halfs (144B) for conflict-free ldsm.
#define PADH 72
#define A_TILE_H (128 * PADH)       // halfs per 128x64 A tile
#define B_TILE_H (256 * PADH)       // halfs per 256x64 B tile

// ---------------------------------------------------------------------------
// Scratch (device globals — allocation-free per harness rules)
// ---------------------------------------------------------------------------
__device__ float g_k [(size_t)Mn * Cn];
__device__ float g_v [(size_t)Mn * Cn];
__device__ float g_x1[(size_t)Mn * Cn];
__device__ float g_kv[(size_t)Mn * Cn];
__device__ __align__(128) __half g_a0[(size_t)Mn * Cn / 64 * PADH];
__device__ __align__(128) __half g_a1[(size_t)Mn * Cn / 64 * PADH];
__device__ __align__(128) __half g_a2[(size_t)Mn * Cn / 64 * PADH];
__device__ __align__(128) __half g_h [(size_t)Mn * Hn / 64 * PADH];
// dedicated packed weight buffers (converted once up-front each launch)
__device__ __align__(128) __half g_wk [(size_t)Cn * Cn / 64 * PADH];
__device__ __align__(128) __half g_wv [(size_t)Cn * Cn / 64 * PADH];
__device__ __align__(128) __half g_wr [(size_t)Cn * Cn / 64 * PADH];
__device__ __align__(128) __half g_wo [(size_t)Cn * Cn / 64 * PADH];
__device__ __align__(128) __half g_wck[(size_t)Hn * Cn / 64 * PADH];
__device__ __align__(128) __half g_wcv[(size_t)Hn * Cn / 64 * PADH];
__device__ __align__(128) __half g_wcr[(size_t)Cn * Cn / 64 * PADH];

// ---------------------------------------------------------------------------
// Packed-offset helpers (half-element index)
// ---------------------------------------------------------------------------
__device__ __forceinline__ size_t apack_off(int m, int k, int K) {
    return ((size_t)(m >> 7) * (K >> 6) + (k >> 6)) * A_TILE_H
           + (size_t)(m & 127) * PADH + (k & 63);
}
__device__ __forceinline__ size_t bpack_off(int n, int k, int K) {
    return ((size_t)(n >> 8) * (K >> 6) + (k >> 6)) * B_TILE_H
           + (size_t)(n & 255) * PADH + (k & 63);
}

// ---------------------------------------------------------------------------
// PTX helpers (baseline sm_103 — NO "a"-suffix features)
// ---------------------------------------------------------------------------
__device__ __forceinline__ uint32_t smem_u32(const void* p) {
    uint32_t a;
    asm("{ .reg .u64 t; cvta.to.shared.u64 t, %1; cvt.u32.u64 %0, t; }"
        : "=r"(a) : "l"(p));
    return a;
}

#define MBAR_INIT(mb, cnt) \
    asm volatile("mbarrier.init.shared.b64 [%0], %1;" :: "r"(mb), "r"((uint32_t)(cnt)) : "memory")

#define MBAR_EXPECT_TX(mb, bytes) \
    asm volatile("mbarrier.arrive.expect_tx.shared.b64 _, [%0], %1;" \
                 :: "r"(mb), "r"((uint32_t)(bytes)) : "memory")

#define MBAR_ARRIVE(mb) \
    asm volatile("mbarrier.arrive.shared.b64 _, [%0];" :: "r"(mb) : "memory")

#define MBAR_WAIT(mb, ph) do {                                            \
    uint32_t _m = (mb); uint32_t _p = (uint32_t)(ph); uint32_t _d;        \
    asm volatile("{ .reg .pred p;"                                        \
        " mbarrier.try_wait.parity.acquire.cta.shared::cta.b64 p, [%1], %2;" \
        " selp.b32 %0, 1, 0, p; }"                                        \
        : "=r"(_d) : "r"(_m), "r"(_p) : "memory");                        \
    if (!_d) {                                                            \
        asm volatile("{ .reg .pred P1;"                                   \
            " WL_%=:"                                                     \
            " mbarrier.try_wait.parity.acquire.cta.shared::cta.b64 P1, [%0], %1, 0x989680;" \
            " @P1 bra.uni WD_%=;"                                         \
            " bra.uni WL_%=;"                                             \
            " WD_%=: }" :: "r"(_m), "r"(_p) : "memory");                  \
    }                                                                     \
} while (0)

#define BULK_G2S(dst, src, sz, mb) \
    asm volatile("cp.async.bulk.shared::cluster.global.mbarrier::complete_tx::bytes " \
                 "[%0], [%1], %2, [%3];" \
                 :: "r"(dst), "l"(src), "r"((uint32_t)(sz)), "r"(mb) : "memory")

__device__ __forceinline__ void ldsm4(uint32_t& r0, uint32_t& r1,
                                      uint32_t& r2, uint32_t& r3, uint32_t a) {
    asm volatile("ldmatrix.sync.aligned.m8n8.x4.shared.b16 {%0,%1,%2,%3}, [%4];"
                 : "=r"(r0), "=r"(r1), "=r"(r2), "=r"(r3) : "r"(a));
}

__device__ __forceinline__ void mma16816(float* d, const uint32_t* a,
                                         const uint32_t* b) {
    asm volatile(
        "mma.sync.aligned.m16n8k16.row.col.f32.f16.f16.f32 "
        "{%0,%1,%2,%3}, {%4,%5,%6,%7}, {%8,%9}, {%0,%1,%2,%3};"
        : "+f"(d[0]), "+f"(d[1]), "+f"(d[2]), "+f"(d[3])
        : "r"(a[0]), "r"(a[1]), "r"(a[2]), "r"(a[3]), "r"(b[0]), "r"(b[1]));
}

// ---------------------------------------------------------------------------
// fp16 pack helpers
// ---------------------------------------------------------------------------
__device__ __forceinline__ uint32_t pack2h(float x, float y) {
    __half2 t = __floats2half2_rn(x, y);
    return *reinterpret_cast<uint32_t*>(&t);
}

__device__ __forceinline__ void store_h4(float4 v, __half* p, size_t idx) {
    uint2 u;
    u.x = pack2h(v.x, v.y);
    u.y = pack2h(v.z, v.w);
    *(uint2*)(p + idx) = u;
}

__device__ __forceinline__ float4 lerp4(float4 cur, float4 prev, float4 m) {
    float4 r;
    r.x = cur.x * m.x + prev.x * (1.f - m.x);
    r.y = cur.y * m.y + prev.y * (1.f - m.y);
    r.z = cur.z * m.z + prev.z * (1.f - m.z);
    r.w = cur.w * m.w + prev.w * (1.f - m.w);
    return r;
}

// ---------------------------------------------------------------------------
// Fused LayerNorm + time-shift mix → packed fp16.
// ---------------------------------------------------------------------------
template <int NOUT>
__global__ __launch_bounds__(256) void ln_mix(
    const float* __restrict__ x, const float* __restrict__ w,
    const float* __restrict__ b,
    const float* __restrict__ m0p, const float* __restrict__ m1p,
    const float* __restrict__ m2p,
    __half* __restrict__ o0, __half* __restrict__ o1, __half* __restrict__ o2)
{
    const int row = blockIdx.x;
    const int t = row % Tn;
    const int tid = threadIdx.x;
    const float* xr = x + (size_t)row * Cn;

    float4 f0 = ((const float4*)xr)[tid];
    float4 f1 = ((const float4*)xr)[tid + 256];
    float v[8] = {f0.x, f0.y, f0.z, f0.w, f1.x, f1.y, f1.z, f1.w};
    float p[8] = {0.f, 0.f, 0.f, 0.f, 0.f, 0.f, 0.f, 0.f};
    if (t > 0) {
        const float* pr = xr - Cn;
        float4 g0 = ((const float4*)pr)[tid];
        float4 g1 = ((const float4*)pr)[tid + 256];
        p[0]=g0.x; p[1]=g0.y; p[2]=g0.z; p[3]=g0.w;
        p[4]=g1.x; p[5]=g1.y; p[6]=g1.z; p[7]=g1.w;
    }

    float sc = 0.f, sc2 = 0.f, sp = 0.f, sp2 = 0.f;
#pragma unroll
    for (int i = 0; i < 8; i++) {
        sc += v[i]; sc2 += v[i] * v[i];
        sp += p[i]; sp2 += p[i] * p[i];
    }
#pragma unroll
    for (int o = 16; o > 0; o >>= 1) {
        sc  += __shfl_xor_sync(0xFFFFFFFFu, sc,  o);
        sc2 += __shfl_xor_sync(0xFFFFFFFFu, sc2, o);
        sp  += __shfl_xor_sync(0xFFFFFFFFu, sp,  o);
        sp2 += __shfl_xor_sync(0xFFFFFFFFu, sp2, o);
    }
    __shared__ float sh[32];
    const int wid = tid >> 5, lane = tid & 31;
    if (lane == 0) {
        sh[wid] = sc; sh[wid + 8] = sc2; sh[wid + 16] = sp; sh[wid + 24] = sp2;
    }
    __syncthreads();
    if (tid < 32) {
        const int g = tid >> 3, l = tid & 7;   // 4 groups of 8
        float a = sh[g * 8 + l];
#pragma unroll
        for (int o = 4; o > 0; o >>= 1)
            a += __shfl_xor_sync(0xFFFFFFFFu, a, o);
        if (l == 0) sh[g] = a;
    }
    __syncthreads();

    const float mu_c  = sh[0] * (1.f / Cn);
    const float inv_c = rsqrtf(sh[1] * (1.f / Cn) - mu_c * mu_c + 1e-5f);
    const float mu_p  = sh[2] * (1.f / Cn);
    const float inv_p = rsqrtf(sh[3] * (1.f / Cn) - mu_p * mu_p + 1e-5f);

#pragma unroll
    for (int j = 0; j < 2; j++) {
        const int c = (tid + j * 256) * 4;
        float4 xn4, xx4;
        const float* vv = v + j * 4;
        const float* pp = p + j * 4;
        xn4.x = (vv[0] - mu_c) * inv_c * w[c + 0] + b[c + 0];
        xn4.y = (vv[1] - mu_c) * inv_c * w[c + 1] + b[c + 1];
        xn4.z = (vv[2] - mu_c) * inv_c * w[c + 2] + b[c + 2];
        xn4.w = (vv[3] - mu_c) * inv_c * w[c + 3] + b[c + 3];
        if (t > 0) {
            xx4.x = (pp[0] - mu_p) * inv_p * w[c + 0] + b[c + 0];
            xx4.y = (pp[1] - mu_p) * inv_p * w[c + 1] + b[c + 1];
            xx4.z = (pp[2] - mu_p) * inv_p * w[c + 2] + b[c + 2];
            xx4.w = (pp[3] - mu_p) * inv_p * w[c + 3] + b[c + 3];
        } else {
            xx4 = make_float4(0.f, 0.f, 0.f, 0.f);
        }
        const size_t po = apack_off(row, c, Cn);
        store_h4(lerp4(xn4, xx4, *(const float4*)(m0p + c)), o0, po);
        store_h4(lerp4(xn4, xx4, *(const float4*)(m1p + c)), o1, po);
        if (NOUT == 3)
            store_h4(lerp4(xn4, xx4, *(const float4*)(m2p + c)), o2, po);
    }
}

// ---------------------------------------------------------------------------
// All 7 weight conversions fp32 -> packed fp16 in ONE kernel.
// Quad ranges: 5 x C*C (2^20 quads each), then Wck (2^22, K=Cn),
// then Wcv (2^22, K=Hn). Per-block branch is uniform (ranges are multiples
// of the block size).
// ---------------------------------------------------------------------------
__global__ __launch_bounds__(256) void conv_all(
    const float* __restrict__ Wk_, const float* __restrict__ Wv_,
    const float* __restrict__ Wr_, const float* __restrict__ Wo_,
    const float* __restrict__ Wcr_,
    const float* __restrict__ Wck_, const float* __restrict__ Wcv_,
    __half* __restrict__ wk, __half* __restrict__ wv, __half* __restrict__ wr,
    __half* __restrict__ wo, __half* __restrict__ wcr,
    __half* __restrict__ wck, __half* __restrict__ wcv)
{
    const size_t q = (size_t)blockIdx.x * 256 + threadIdx.x;
    const float* s;
    __half* d;
    int K;
    size_t lq;
    const int w = (int)(q >> 20);               // Q_CC = 2^20 quads
    if (w < 5) {
        lq = q & 0xFFFFFu;
        K = Cn;
        if      (w == 0) { s = Wk_;  d = wk;  }
        else if (w == 1) { s = Wv_;  d = wv;  }
        else if (w == 2) { s = Wr_;  d = wr;  }
        else if (w == 3) { s = Wo_;  d = wo;  }
        else             { s = Wcr_; d = wcr; }
    } else if (q < (5ull << 20) + (1ull << 22)) {  // Wck: 2^22 quads
        lq = q - (5ull << 20);
        s = Wck_; d = wck; K = Cn;
    } else {                                        // Wcv: 2^22 quads
        lq = q - (5ull << 20) - (1ull << 22);
        s = Wcv_; d = wcv; K = Hn;
    }
    const size_t idx = lq * 4;
    const int n = (int)(idx / K);
    const int k = (int)(idx % K);
    float4 v = *(const float4*)(s + idx);
    store_h4(v, d, bpack_off(n, k, K));
}

// ---------------------------------------------------------------------------
// WKV recurrence + sigmoid(r) gate. Block-level ping-pong prefetch (depth 8).
// ---------------------------------------------------------------------------
#define WKV_PF 8

__global__ __launch_bounds__(64) void wkv_gate_kernel(
    const float* __restrict__ k, const float* __restrict__ v,
    const __half* __restrict__ rp,
    const float* __restrict__ w_decay, const float* __restrict__ u_first,
    __half* __restrict__ g)
{
    const int idx = blockIdx.x * blockDim.x + threadIdx.x;
    const int c = idx % Cn;
    const int b = idx / Cn;
    const float w = -expf(w_decay[c]);
    const float u = u_first[c];

    const size_t off0 = (size_t)b * Tn * Cn + c;
    const int m0 = b * Tn;

    float kA[WKV_PF], vA[WKV_PF], rA[WKV_PF];
    float kB[WKV_PF], vB[WKV_PF], rB[WKV_PF];

#pragma unroll
    for (int j = 0; j < WKV_PF; j++) {
        kA[j] = k[off0 + (size_t)j * Cn];
        vA[j] = v[off0 + (size_t)j * Cn];
        rA[j] = __half2float(rp[apack_off(m0 + j, c, Cn)]);
    }

    float aa = 0.f, bb = 0.f, pp = -1e38f;
    for (int t0 = 0; t0 < Tn; t0 += WKV_PF) {
        const bool more = (t0 + WKV_PF) < Tn;
        if (more) {
            const size_t offn = off0 + (size_t)(t0 + WKV_PF) * Cn;
            const int mn = m0 + t0 + WKV_PF;
#pragma unroll
            for (int j = 0; j < WKV_PF; j++) {
                kB[j] = k[offn + (size_t)j * Cn];
                vB[j] = v[offn + (size_t)j * Cn];
                rB[j] = __half2float(rp[apack_off(mn + j, c, Cn)]);
            }
        }

#pragma unroll
        for (int j = 0; j < WKV_PF; j++) {
            const float kt = kA[j];
            const float vt = vA[j];
            const float rr = rA[j];

            const float ww = u + kt;
            const float pmx = fmaxf(pp, ww);
            const float e1 = __expf(pp - pmx);
            const float e2 = __expf(ww - pmx);
            const float y  = __fdividef(e1 * aa + e2 * vt, e1 * bb + e2);
            const float sg = __fdividef(1.f, 1.f + __expf(-rr));
            g[apack_off(m0 + t0 + j, c, Cn)] = __float2half_rn(y * sg);

            const float ww2 = pp + w;
            const float p2  = fmaxf(ww2, kt);
            const float e1b = __expf(ww2 - p2);
            const float e2b = __expf(kt - p2);
            aa = e1b * aa + e2b * vt;
            bb = e1b * bb + e2b;
            pp = p2;
        }

        if (more) {
#pragma unroll
            for (int j = 0; j < WKV_PF; j++) {
                kA[j] = kB[j];
                vA[j] = vB[j];
                rA[j] = rB[j];
            }
        }
    }
}

// ---------------------------------------------------------------------------
// GEMM constants (shared by both persistent GEMM kernels)
// ---------------------------------------------------------------------------
static constexpr int AT64 = A_TILE_H * 2;     // 18432 B (one 64-k A tile)
static constexpr int BT64 = B_TILE_H * 2;     // 36864 B (one 64-k B tile)
static constexpr int STAGE = 2 * (AT64 + BT64);   // 110592 B (BK=128)
static constexpr int SMEM_DYN = 2 * STAGE;        // 221184 B
static constexpr int GPERS = 148;                 // persistent grid size

// ---------------------------------------------------------------------------
// Persistent HMMA fp16 GEMM over packed tiles:  C[M,N] = A[M,K] @ B[N,K]^T
// 148 persistent CTAs; 128x256 tiles; 2-stage cp.async.bulk pipeline runs as
// one continuous chunk sequence across tile boundaries. 8 warps (2x4) 64x64.
// EPI: 0 fp32; 1 +res0; 2 relu^2 -> packed fp16; 3 res0 + sigmoid*res1;
//      4 packed fp16 (plain)
// ---------------------------------------------------------------------------
template <int EPI>
__global__ __launch_bounds__(256, 1) void gemmp(
    const __half* __restrict__ Ap, const __half* __restrict__ Bp,
    float* __restrict__ Cm, __half* __restrict__ Ohp,
    int N, int K, int ntiles,
    const float* __restrict__ res0, const float* __restrict__ res1)
{
    extern __shared__ __align__(128) char dsm[];
    __shared__ __align__(8) uint64_t s_mbar[4];   // full0, full1, empty0, empty1

    const uint32_t sb = smem_u32(dsm);
    const uint32_t mbf = smem_u32(s_mbar);
    const uint32_t mbe = mbf + 16;
    const int tid = threadIdx.x, wid = tid >> 5, lane = tid & 31;
    const int wm = wid >> 2, wn = wid & 3;   // 2 x 4 warps of 64x64
    const int bid = blockIdx.x;
    const int nbx = N >> 8;
    const int nk = K >> 7;
    const int kt64 = K >> 6;

    const int ntpc = (ntiles - bid + GPERS - 1) / GPERS;
    if (ntpc <= 0) return;
    const int total = ntpc * nk;

    if (tid == 0) {
        MBAR_INIT(mbf + 0, 1);
        MBAR_INIT(mbf + 8, 1);
        MBAR_INIT(mbe + 0, 256);
        MBAR_INIT(mbe + 8, 256);
    }
    __syncthreads();

    if (tid == 0) {
        const int by0 = bid / nbx, bx0 = bid % nbx;
#pragma unroll
        for (int s = 0; s < 2; s++) {
            MBAR_EXPECT_TX(mbf + s * 8, STAGE);
            BULK_G2S(sb + s * STAGE,
                     Ap + ((size_t)by0 * kt64 + 2 * s) * A_TILE_H, 2 * AT64, mbf + s * 8);
            BULK_G2S(sb + s * STAGE + 2 * AT64,
                     Bp + ((size_t)bx0 * kt64 + 2 * s) * B_TILE_H, 2 * BT64, mbf + s * 8);
        }
    }

    const int a_row  = wm * 64 + (lane & 15);
    const int a_koff = (lane & 16) ? 8 : 0;
    const int b_row  = wn * 64 + (lane & 7) + ((lane & 16) ? 8 : 0);
    const int b_koff = (lane & 8) ? 8 : 0;

    int s = 0;
    uint32_t parf = 0, pare = 0;
    int seq = 0;

    for (int j = 0; j < ntpc; j++) {
        const int t = bid + j * GPERS;
        const int by = t / nbx, bx = t % nbx;
        const int m0 = by * 128, n0 = bx * 256;

        float acc[4][8][4];
#pragma unroll
        for (int a = 0; a < 4; a++)
#pragma unroll
            for (int b = 0; b < 8; b++)
#pragma unroll
                for (int c = 0; c < 4; c++) acc[a][b][c] = 0.f;

        for (int i = 0; i < nk; i++, seq++) {
            MBAR_WAIT(mbf + s * 8, (parf >> s) & 1u);
            parf ^= (1u << s);

            const uint32_t st = sb + s * STAGE;
#pragma unroll
            for (int half = 0; half < 2; half++) {
                const uint32_t abase = st + half * AT64;
                const uint32_t bbase = st + 2 * AT64 + half * BT64;
#pragma unroll
                for (int k16 = 0; k16 < 4; k16++) {
                    uint32_t ah[4][4];
                    const uint32_t acol = (uint32_t)(k16 * 16 + a_koff) * 2;
#pragma unroll
                    for (int mt = 0; mt < 4; mt++) {
                        const uint32_t ad = abase +
                            (uint32_t)(a_row + mt * 16) * (PADH * 2) + acol;
                        ldsm4(ah[mt][0], ah[mt][1], ah[mt][2], ah[mt][3], ad);
                    }
                    uint32_t bh[8][2];
                    const uint32_t bcol = (uint32_t)(k16 * 16 + b_koff) * 2;
#pragma unroll
                    for (int pq = 0; pq < 4; pq++) {
                        const uint32_t bd = bbase +
                            (uint32_t)(b_row + pq * 16) * (PADH * 2) + bcol;
                        ldsm4(bh[2*pq][0], bh[2*pq][1], bh[2*pq+1][0], bh[2*pq+1][1], bd);
                    }
#pragma unroll
                    for (int mt = 0; mt < 4; mt++)
#pragma unroll
                        for (int nt = 0; nt < 8; nt++)
                            mma16816(acc[mt][nt], ah[mt], bh[nt]);
                }
            }

            MBAR_ARRIVE(mbe + s * 8);

            if (tid == 0 && seq + 2 < total) {
                MBAR_WAIT(mbe + s * 8, (pare >> s) & 1u);
                pare ^= (1u << s);
                const int sq = seq + 2;
                const int j2 = sq / nk, i2 = sq - j2 * nk;
                const int t2 = bid + j2 * GPERS;
                const int by2 = t2 / nbx, bx2 = t2 % nbx;
                MBAR_EXPECT_TX(mbf + s * 8, STAGE);
                BULK_G2S(sb + s * STAGE,
                         Ap + ((size_t)by2 * kt64 + 2 * i2) * A_TILE_H,
                         2 * AT64, mbf + s * 8);
                BULK_G2S(sb + s * STAGE + 2 * AT64,
                         Bp + ((size_t)bx2 * kt64 + 2 * i2) * B_TILE_H,
                         2 * BT64, mbf + s * 8);
            }
            s ^= 1;
        }

        const int row_base = m0 + wm * 64 + (lane >> 2);
        const int col_base = n0 + wn * 64 + (lane & 3) * 2;
#pragma unroll
        for (int mt = 0; mt < 4; mt++) {
#pragma unroll
            for (int h = 0; h < 2; h++) {
                const int row = row_base + mt * 16 + h * 8;
#pragma unroll
                for (int nt = 0; nt < 8; nt++) {
                    float vx = acc[mt][nt][2 * h + 0];
                    float vy = acc[mt][nt][2 * h + 1];
                    const int col = col_base + nt * 8;
                    const size_t off = (size_t)row * N + col;
                    if (EPI == 0) {
                        *(float2*)(Cm + off) = make_float2(vx, vy);
                    } else if (EPI == 1) {
                        float2 r = *(const float2*)(res0 + off);
                        *(float2*)(Cm + off) = make_float2(vx + r.x, vy + r.y);
                    } else if (EPI == 2) {
                        vx = fmaxf(vx, 0.f); vx *= vx;
                        vy = fmaxf(vy, 0.f); vy *= vy;
                        *(uint32_t*)(Ohp + apack_off(row, col, N)) = pack2h(vx, vy);
                    } else if (EPI == 4) {
                        *(uint32_t*)(Ohp + apack_off(row, col, N)) = pack2h(vx, vy);
                    } else {
                        float2 r0 = *(const float2*)(res0 + off);
                        float2 r1 = *(const float2*)(res1 + off);
                        vx = r0.x + r1.x / (1.f + __expf(-vx));
                        vy = r0.y + r1.y / (1.f + __expf(-vy));
                        *(float2*)(Cm + off) = make_float2(vx, vy);
                    }
                }
            }
        }
    }
}

// ---------------------------------------------------------------------------
// Merged persistent GEMM for the three independent time-mix projections:
//   op0: kf = a0 @ Wk^T (fp32)   op1: vf = a1 @ Wv^T (fp32)
//   op2: rp = a2 @ Wr^T (packed fp16)
// 3072 tiles total (1024 per op), N=K=Cn everywhere. One continuous chunk
// sequence across op AND tile boundaries — two kernel boundaries and two
// pipeline prologues removed.
// ---------------------------------------------------------------------------
__device__ __forceinline__ void kvr_resolve(
    int t, const __half* A0, const __half* A1, const __half* A2,
    const __half* W0, const __half* W1, const __half* W2,
    const __half*& Ap, const __half*& Bp, int& op, int& by, int& bx)
{
    op = t >> 10;                 // 1024 tiles per op
    const int tt = t & 1023;
    by = tt >> 3;                 // nbx = 8
    bx = tt & 7;
    Ap = (op == 0) ? A0 : (op == 1) ? A1 : A2;
    Bp = (op == 0) ? W0 : (op == 1) ? W1 : W2;
}

__global__ __launch_bounds__(256, 1) void gemm_kvr(
    const __half* __restrict__ A0, const __half* __restrict__ A1,
    const __half* __restrict__ A2,
    const __half* __restrict__ W0, const __half* __restrict__ W1,
    const __half* __restrict__ W2,
    float* __restrict__ kf, float* __restrict__ vf, __half* __restrict__ rp)
{
    extern __shared__ __align__(128) char dsm[];
    __shared__ __align__(8) uint64_t s_mbar[4];

    const uint32_t sb = smem_u32(dsm);
    const uint32_t mbf = smem_u32(s_mbar);
    const uint32_t mbe = mbf + 16;
    const int tid = threadIdx.x, wid = tid >> 5, lane = tid & 31;
    const int wm = wid >> 2, wn = wid & 3;
    const int bid = blockIdx.x;
    const int nk = Cn >> 7;        // 16
    const int kt64 = Cn >> 6;      // 32
    const int ntiles = 3072;

    const int ntpc = (ntiles - bid + GPERS - 1) / GPERS;
    const int total = ntpc * nk;

    if (tid == 0) {
        MBAR_INIT(mbf + 0, 1);
        MBAR_INIT(mbf + 8, 1);
        MBAR_INIT(mbe + 0, 256);
        MBAR_INIT(mbe + 8, 256);
    }
    __syncthreads();

    if (tid == 0) {
        const __half *Ap, *Bp;
        int op, by0, bx0;
        kvr_resolve(bid, A0, A1, A2, W0, W1, W2, Ap, Bp, op, by0, bx0);
#pragma unroll
        for (int s = 0; s < 2; s++) {
            MBAR_EXPECT_TX(mbf + s * 8, STAGE);
            BULK_G2S(sb + s * STAGE,
                     Ap + ((size_t)by0 * kt64 + 2 * s) * A_TILE_H, 2 * AT64, mbf + s * 8);
            BULK_G2S(sb + s * STAGE + 2 * AT64,
                     Bp + ((size_t)bx0 * kt64 + 2 * s) * B_TILE_H, 2 * BT64, mbf + s * 8);
        }
    }

    const int a_row  = wm * 64 + (lane & 15);
    const int a_koff = (lane & 16) ? 8 : 0;
    const int b_row  = wn * 64 + (lane & 7) + ((lane & 16) ? 8 : 0);
    const int b_koff = (lane & 8) ? 8 : 0;

    int s = 0;
    uint32_t parf = 0, pare = 0;
    int seq = 0;

    for (int j = 0; j < ntpc; j++) {
        const int t = bid + j * GPERS;
        const __half *ApT, *BpT;
        int op, by, bx;
        kvr_resolve(t, A0, A1, A2, W0, W1, W2, ApT, BpT, op, by, bx);
        const int m0 = by * 128, n0 = bx * 256;

        float acc[4][8][4];
#pragma unroll
        for (int a = 0; a < 4; a++)
#pragma unroll
            for (int b = 0; b < 8; b++)
#pragma unroll
                for (int c = 0; c < 4; c++) acc[a][b][c] = 0.f;

        for (int i = 0; i < nk; i++, seq++) {
            MBAR_WAIT(mbf + s * 8, (parf >> s) & 1u);
            parf ^= (1u << s);

            const uint32_t st = sb + s * STAGE;
#pragma unroll
            for (int half = 0; half < 2; half++) {
                const uint32_t abase = st + half * AT64;
                const uint32_t bbase = st + 2 * AT64 + half * BT64;
#pragma unroll
                for (int k16 = 0; k16 < 4; k16++) {
                    uint32_t ah[4][4];
                    const uint32_t acol = (uint32_t)(k16 * 16 + a_koff) * 2;
#pragma unroll
                    for (int mt = 0; mt < 4; mt++) {
                        const uint32_t ad = abase +
                            (uint32_t)(a_row + mt * 16) * (PADH * 2) + acol;
                        ldsm4(ah[mt][0], ah[mt][1], ah[mt][2], ah[mt][3], ad);
                    }
                    uint32_t bh[8][2];
                    const uint32_t bcol = (uint32_t)(k16 * 16 + b_koff) * 2;
#pragma unroll
                    for (int pq = 0; pq < 4; pq++) {
                        const uint32_t bd = bbase +
                            (uint32_t)(b_row + pq * 16) * (PADH * 2) + bcol;
                        ldsm4(bh[2*pq][0], bh[2*pq][1], bh[2*pq+1][0], bh[2*pq+1][1], bd);
                    }
#pragma unroll
                    for (int mt = 0; mt < 4; mt++)
#pragma unroll
                        for (int nt = 0; nt < 8; nt++)
                            mma16816(acc[mt][nt], ah[mt], bh[nt]);
                }
            }

            MBAR_ARRIVE(mbe + s * 8);

            if (tid == 0 && seq + 2 < total) {
                MBAR_WAIT(mbe + s * 8, (pare >> s) & 1u);
                pare ^= (1u << s);
                const int sq = seq + 2;
                const int j2 = sq / nk, i2 = sq - j2 * nk;
                const int t2 = bid + j2 * GPERS;
                const __half *Ap2, *Bp2;
                int op2, by2, bx2;
                kvr_resolve(t2, A0, A1, A2, W0, W1, W2, Ap2, Bp2, op2, by2, bx2);
                MBAR_EXPECT_TX(mbf + s * 8, STAGE);
                BULK_G2S(sb + s * STAGE,
                         Ap2 + ((size_t)by2 * kt64 + 2 * i2) * A_TILE_H,
                         2 * AT64, mbf + s * 8);
                BULK_G2S(sb + s * STAGE + 2 * AT64,
                         Bp2 + ((size_t)bx2 * kt64 + 2 * i2) * B_TILE_H,
                         2 * BT64, mbf + s * 8);
            }
            s ^= 1;
        }

        // Epilogue for tile t
        const int row_base = m0 + wm * 64 + (lane >> 2);
        const int col_base = n0 + wn * 64 + (lane & 3) * 2;
        if (op < 2) {
            float* Cm = (op == 0) ? kf : vf;
#pragma unroll
            for (int mt = 0; mt < 4; mt++)
#pragma unroll
                for (int h = 0; h < 2; h++) {
                    const int row = row_base + mt * 16 + h * 8;
#pragma unroll
                    for (int nt = 0; nt < 8; nt++) {
                        const size_t off = (size_t)row * Cn + col_base + nt * 8;
                        *(float2*)(Cm + off) =
                            make_float2(acc[mt][nt][2 * h + 0], acc[mt][nt][2 * h + 1]);
                    }
                }
        } else {
#pragma unroll
            for (int mt = 0; mt < 4; mt++)
#pragma unroll
                for (int h = 0; h < 2; h++) {
                    const int row = row_base + mt * 16 + h * 8;
#pragma unroll
                    for (int nt = 0; nt < 8; nt++) {
                        const int col = col_base + nt * 8;
                        *(uint32_t*)(rp + apack_off(row, col, Cn)) =
                            pack2h(acc[mt][nt][2 * h + 0], acc[mt][nt][2 * h + 1]);
                    }
                }
        }
    }
}

// ---------------------------------------------------------------------------
// Launch
// ---------------------------------------------------------------------------
extern "C" void kernel_launch(void* const* d_in, const int* in_sizes, int n_in,
                              void* d_out, int out_size)
{
    (void)in_sizes; (void)n_in; (void)out_size;
    const float* x    = (const float*)d_in[0];
    const float* ln1w = (const float*)d_in[1];
    const float* ln1b = (const float*)d_in[2];
    const float* ln2w = (const float*)d_in[3];
    const float* ln2b = (const float*)d_in[4];
    const float* tdec = (const float*)d_in[5];
    const float* tfir = (const float*)d_in[6];
    const float* tmk  = (const float*)d_in[7];
    const float* tmv  = (const float*)d_in[8];
    const float* tmr  = (const float*)d_in[9];
    const float* Wk   = (const float*)d_in[10];
    const float* Wv   = (const float*)d_in[11];
    const float* Wr   = (const float*)d_in[12];
    const float* Wo   = (const float*)d_in[13];
    const float* cmk  = (const float*)d_in[14];
    const float* cmr  = (const float*)d_in[15];
    const float* Wck  = (const float*)d_in[16];
    const float* Wcv  = (const float*)d_in[17];
    const float* Wcr  = (const float*)d_in[18];
    float* out = (float*)d_out;

    float *kf, *vf, *x1, *kv;
    __half *a0, *a1, *a2, *hb;
    __half *wk, *wv, *wr, *wo, *wck, *wcv, *wcr;
    cudaGetSymbolAddress((void**)&kf, g_k);
    cudaGetSymbolAddress((void**)&vf, g_v);
    cudaGetSymbolAddress((void**)&x1, g_x1);
    cudaGetSymbolAddress((void**)&kv, g_kv);
    cudaGetSymbolAddress((void**)&a0, g_a0);
    cudaGetSymbolAddress((void**)&a1, g_a1);
    cudaGetSymbolAddress((void**)&a2, g_a2);
    cudaGetSymbolAddress((void**)&hb, g_h);
    cudaGetSymbolAddress((void**)&wk, g_wk);
    cudaGetSymbolAddress((void**)&wv, g_wv);
    cudaGetSymbolAddress((void**)&wr, g_wr);
    cudaGetSymbolAddress((void**)&wo, g_wo);
    cudaGetSymbolAddress((void**)&wck, g_wck);
    cudaGetSymbolAddress((void**)&wcv, g_wcv);
    cudaGetSymbolAddress((void**)&wcr, g_wcr);

    cudaFuncSetAttribute(gemmp<0>, cudaFuncAttributeMaxDynamicSharedMemorySize, SMEM_DYN);
    cudaFuncSetAttribute(gemmp<1>, cudaFuncAttributeMaxDynamicSharedMemorySize, SMEM_DYN);
    cudaFuncSetAttribute(gemmp<2>, cudaFuncAttributeMaxDynamicSharedMemorySize, SMEM_DYN);
    cudaFuncSetAttribute(gemmp<3>, cudaFuncAttributeMaxDynamicSharedMemorySize, SMEM_DYN);
    cudaFuncSetAttribute(gemm_kvr, cudaFuncAttributeMaxDynamicSharedMemorySize, SMEM_DYN);

    const int tC = (Mn / 128) * (Cn / 256);   // 1024 tiles
    const int tH = (Mn / 128) * (Hn / 256);   // 4096 tiles
    const int convBlocks = (5 * (1 << 20) + 2 * (1 << 22)) / 256;  // 53248

    // --- all weight conversions in one launch ---
    conv_all<<<convBlocks, 256>>>(Wk, Wv, Wr, Wo, Wcr, Wck, Wcv,
                                  wk, wv, wr, wo, wcr, wck, wcv);

    // --- time-mix attention ---
    ln_mix<3><<<Mn, 256>>>(x, ln1w, ln1b, tmk, tmv, tmr, a0, a1, a2);

    gemm_kvr<<<GPERS, 256, SMEM_DYN>>>(a0, a1, a2, wk, wv, wr, kf, vf, a0);

    wkv_gate_kernel<<<(Bn * Cn) / 64, 64>>>(kf, vf, a0, tdec, tfir, a1);

    gemmp<1><<<GPERS, 256, SMEM_DYN>>>(a1, wo, x1, nullptr, Cn, Cn, tC, x, nullptr);

    // --- channel mix ---
    ln_mix<2><<<Mn, 256>>>(x1, ln2w, ln2b, cmk, cmr, nullptr, a0, a2, nullptr);

    gemmp<2><<<GPERS, 256, SMEM_DYN>>>(a0, wck, nullptr, hb, Hn, Cn, tH, nullptr, nullptr);
    gemmp<0><<<GPERS, 256, SMEM_DYN>>>(hb, wcv, kv, nullptr, Cn, Hn, tC, nullptr, nullptr);
    gemmp<3><<<GPERS, 256, SMEM_DYN>>>(a2, wcr, out, nullptr, Cn, Cn, tC, x1, kv);
}

// round 17
// speedup vs baseline: 15.8481x; 1.0760x over previous
#include <cuda_runtime.h>
#include <cuda_fp16.h>
#include <math.h>
#include <stdint.h>

#define Bn 8
#define Tn 2048
#define Cn 2048
#define Hn 8192
#define Mn (Bn * Tn)   // 16384

// WKV chunked-scan geometry
#define NCHUNK 16
#define CLEN   128     // Tn / NCHUNK
#define NLANE  (Bn * Cn)   // 16384

// Packed-tile geometry: rows padded to 72 halfs (144B) for conflict-free ldsm.
#define PADH 72
#define A_TILE_H (128 * PADH)
#define B_TILE_H (256 * PADH)

// ---------------------------------------------------------------------------
// Scratch (device globals — allocation-free per harness rules)
// ---------------------------------------------------------------------------
__device__ float g_k [(size_t)Mn * Cn];
__device__ float g_v [(size_t)Mn * Cn];
__device__ float g_x1[(size_t)Mn * Cn];
__device__ float g_kv[(size_t)Mn * Cn];
__device__ __align__(128) __half g_a0[(size_t)Mn * Cn / 64 * PADH];
__device__ __align__(128) __half g_a1[(size_t)Mn * Cn / 64 * PADH];
__device__ __align__(128) __half g_a2[(size_t)Mn * Cn / 64 * PADH];
__device__ __align__(128) __half g_h [(size_t)Mn * Hn / 64 * PADH];
__device__ __align__(128) __half g_wk [(size_t)Cn * Cn / 64 * PADH];
__device__ __align__(128) __half g_wv [(size_t)Cn * Cn / 64 * PADH];
__device__ __align__(128) __half g_wr [(size_t)Cn * Cn / 64 * PADH];
__device__ __align__(128) __half g_wo [(size_t)Cn * Cn / 64 * PADH];
__device__ __align__(128) __half g_wck[(size_t)Hn * Cn / 64 * PADH];
__device__ __align__(128) __half g_wcv[(size_t)Hn * Cn / 64 * PADH];
__device__ __align__(128) __half g_wcr[(size_t)Cn * Cn / 64 * PADH];
// WKV chunk-scan scratch
__device__ float g_cA[NLANE * NCHUNK], g_cB[NLANE * NCHUNK], g_cP[NLANE * NCHUNK];
__device__ float g_iA[NLANE * NCHUNK], g_iB[NLANE * NCHUNK], g_iP[NLANE * NCHUNK];

// ---------------------------------------------------------------------------
// Packed-offset helpers (half-element index)
// ---------------------------------------------------------------------------
__device__ __forceinline__ size_t apack_off(int m, int k, int K) {
    return ((size_t)(m >> 7) * (K >> 6) + (k >> 6)) * A_TILE_H
           + (size_t)(m & 127) * PADH + (k & 63);
}
__device__ __forceinline__ size_t bpack_off(int n, int k, int K) {
    return ((size_t)(n >> 8) * (K >> 6) + (k >> 6)) * B_TILE_H
           + (size_t)(n & 255) * PADH + (k & 63);
}

// ---------------------------------------------------------------------------
// PTX helpers (baseline sm_103 — NO "a"-suffix features)
// ---------------------------------------------------------------------------
__device__ __forceinline__ uint32_t smem_u32(const void* p) {
    uint32_t a;
    asm("{ .reg .u64 t; cvta.to.shared.u64 t, %1; cvt.u32.u64 %0, t; }"
        : "=r"(a) : "l"(p));
    return a;
}

#define MBAR_INIT(mb, cnt) \
    asm volatile("mbarrier.init.shared.b64 [%0], %1;" :: "r"(mb), "r"((uint32_t)(cnt)) : "memory")

#define MBAR_EXPECT_TX(mb, bytes) \
    asm volatile("mbarrier.arrive.expect_tx.shared.b64 _, [%0], %1;" \
                 :: "r"(mb), "r"((uint32_t)(bytes)) : "memory")

#define MBAR_ARRIVE(mb) \
    asm volatile("mbarrier.arrive.shared.b64 _, [%0];" :: "r"(mb) : "memory")

#define MBAR_WAIT(mb, ph) do {                                            \
    uint32_t _m = (mb); uint32_t _p = (uint32_t)(ph); uint32_t _d;        \
    asm volatile("{ .reg .pred p;"                                        \
        " mbarrier.try_wait.parity.acquire.cta.shared::cta.b64 p, [%1], %2;" \
        " selp.b32 %0, 1, 0, p; }"                                        \
        : "=r"(_d) : "r"(_m), "r"(_p) : "memory");                        \
    if (!_d) {                                                            \
        asm volatile("{ .reg .pred P1;"                                   \
            " WL_%=:"                                                     \
            " mbarrier.try_wait.parity.acquire.cta.shared::cta.b64 P1, [%0], %1, 0x989680;" \
            " @P1 bra.uni WD_%=;"                                         \
            " bra.uni WL_%=;"                                             \
            " WD_%=: }" :: "r"(_m), "r"(_p) : "memory");                  \
    }                                                                     \
} while (0)

#define BULK_G2S(dst, src, sz, mb) \
    asm volatile("cp.async.bulk.shared::cluster.global.mbarrier::complete_tx::bytes " \
                 "[%0], [%1], %2, [%3];" \
                 :: "r"(dst), "l"(src), "r"((uint32_t)(sz)), "r"(mb) : "memory")

__device__ __forceinline__ void ldsm4(uint32_t& r0, uint32_t& r1,
                                      uint32_t& r2, uint32_t& r3, uint32_t a) {
    asm volatile("ldmatrix.sync.aligned.m8n8.x4.shared.b16 {%0,%1,%2,%3}, [%4];"
                 : "=r"(r0), "=r"(r1), "=r"(r2), "=r"(r3) : "r"(a));
}

__device__ __forceinline__ void mma16816(float* d, const uint32_t* a,
                                         const uint32_t* b) {
    asm volatile(
        "mma.sync.aligned.m16n8k16.row.col.f32.f16.f16.f32 "
        "{%0,%1,%2,%3}, {%4,%5,%6,%7}, {%8,%9}, {%0,%1,%2,%3};"
        : "+f"(d[0]), "+f"(d[1]), "+f"(d[2]), "+f"(d[3])
        : "r"(a[0]), "r"(a[1]), "r"(a[2]), "r"(a[3]), "r"(b[0]), "r"(b[1]));
}

// ---------------------------------------------------------------------------
// fp16 pack helpers
// ---------------------------------------------------------------------------
__device__ __forceinline__ uint32_t pack2h(float x, float y) {
    __half2 t = __floats2half2_rn(x, y);
    return *reinterpret_cast<uint32_t*>(&t);
}

__device__ __forceinline__ void store_h4(float4 v, __half* p, size_t idx) {
    uint2 u;
    u.x = pack2h(v.x, v.y);
    u.y = pack2h(v.z, v.w);
    *(uint2*)(p + idx) = u;
}

__device__ __forceinline__ float4 lerp4(float4 cur, float4 prev, float4 m) {
    float4 r;
    r.x = cur.x * m.x + prev.x * (1.f - m.x);
    r.y = cur.y * m.y + prev.y * (1.f - m.y);
    r.z = cur.z * m.z + prev.z * (1.f - m.z);
    r.w = cur.w * m.w + prev.w * (1.f - m.w);
    return r;
}

// ---------------------------------------------------------------------------
// Fused LayerNorm + time-shift mix → packed fp16.
// ---------------------------------------------------------------------------
template <int NOUT>
__global__ __launch_bounds__(256) void ln_mix(
    const float* __restrict__ x, const float* __restrict__ w,
    const float* __restrict__ b,
    const float* __restrict__ m0p, const float* __restrict__ m1p,
    const float* __restrict__ m2p,
    __half* __restrict__ o0, __half* __restrict__ o1, __half* __restrict__ o2)
{
    const int row = blockIdx.x;
    const int t = row % Tn;
    const int tid = threadIdx.x;
    const float* xr = x + (size_t)row * Cn;

    float4 f0 = ((const float4*)xr)[tid];
    float4 f1 = ((const float4*)xr)[tid + 256];
    float v[8] = {f0.x, f0.y, f0.z, f0.w, f1.x, f1.y, f1.z, f1.w};
    float p[8] = {0.f, 0.f, 0.f, 0.f, 0.f, 0.f, 0.f, 0.f};
    if (t > 0) {
        const float* pr = xr - Cn;
        float4 g0 = ((const float4*)pr)[tid];
        float4 g1 = ((const float4*)pr)[tid + 256];
        p[0]=g0.x; p[1]=g0.y; p[2]=g0.z; p[3]=g0.w;
        p[4]=g1.x; p[5]=g1.y; p[6]=g1.z; p[7]=g1.w;
    }

    float sc = 0.f, sc2 = 0.f, sp = 0.f, sp2 = 0.f;
#pragma unroll
    for (int i = 0; i < 8; i++) {
        sc += v[i]; sc2 += v[i] * v[i];
        sp += p[i]; sp2 += p[i] * p[i];
    }
#pragma unroll
    for (int o = 16; o > 0; o >>= 1) {
        sc  += __shfl_xor_sync(0xFFFFFFFFu, sc,  o);
        sc2 += __shfl_xor_sync(0xFFFFFFFFu, sc2, o);
        sp  += __shfl_xor_sync(0xFFFFFFFFu, sp,  o);
        sp2 += __shfl_xor_sync(0xFFFFFFFFu, sp2, o);
    }
    __shared__ float sh[32];
    const int wid = tid >> 5, lane = tid & 31;
    if (lane == 0) {
        sh[wid] = sc; sh[wid + 8] = sc2; sh[wid + 16] = sp; sh[wid + 24] = sp2;
    }
    __syncthreads();
    if (tid < 32) {
        const int g = tid >> 3, l = tid & 7;
        float a = sh[g * 8 + l];
#pragma unroll
        for (int o = 4; o > 0; o >>= 1)
            a += __shfl_xor_sync(0xFFFFFFFFu, a, o);
        if (l == 0) sh[g] = a;
    }
    __syncthreads();

    const float mu_c  = sh[0] * (1.f / Cn);
    const float inv_c = rsqrtf(sh[1] * (1.f / Cn) - mu_c * mu_c + 1e-5f);
    const float mu_p  = sh[2] * (1.f / Cn);
    const float inv_p = rsqrtf(sh[3] * (1.f / Cn) - mu_p * mu_p + 1e-5f);

#pragma unroll
    for (int j = 0; j < 2; j++) {
        const int c = (tid + j * 256) * 4;
        float4 xn4, xx4;
        const float* vv = v + j * 4;
        const float* pp = p + j * 4;
        xn4.x = (vv[0] - mu_c) * inv_c * w[c + 0] + b[c + 0];
        xn4.y = (vv[1] - mu_c) * inv_c * w[c + 1] + b[c + 1];
        xn4.z = (vv[2] - mu_c) * inv_c * w[c + 2] + b[c + 2];
        xn4.w = (vv[3] - mu_c) * inv_c * w[c + 3] + b[c + 3];
        if (t > 0) {
            xx4.x = (pp[0] - mu_p) * inv_p * w[c + 0] + b[c + 0];
            xx4.y = (pp[1] - mu_p) * inv_p * w[c + 1] + b[c + 1];
            xx4.z = (pp[2] - mu_p) * inv_p * w[c + 2] + b[c + 2];
            xx4.w = (pp[3] - mu_p) * inv_p * w[c + 3] + b[c + 3];
        } else {
            xx4 = make_float4(0.f, 0.f, 0.f, 0.f);
        }
        const size_t po = apack_off(row, c, Cn);
        store_h4(lerp4(xn4, xx4, *(const float4*)(m0p + c)), o0, po);
        store_h4(lerp4(xn4, xx4, *(const float4*)(m1p + c)), o1, po);
        if (NOUT == 3)
            store_h4(lerp4(xn4, xx4, *(const float4*)(m2p + c)), o2, po);
    }
}

// ---------------------------------------------------------------------------
// All 7 weight conversions fp32 -> packed fp16 in ONE kernel.
// ---------------------------------------------------------------------------
__global__ __launch_bounds__(256) void conv_all(
    const float* __restrict__ Wk_, const float* __restrict__ Wv_,
    const float* __restrict__ Wr_, const float* __restrict__ Wo_,
    const float* __restrict__ Wcr_,
    const float* __restrict__ Wck_, const float* __restrict__ Wcv_,
    __half* __restrict__ wk, __half* __restrict__ wv, __half* __restrict__ wr,
    __half* __restrict__ wo, __half* __restrict__ wcr,
    __half* __restrict__ wck, __half* __restrict__ wcv)
{
    const size_t q = (size_t)blockIdx.x * 256 + threadIdx.x;
    const float* s;
    __half* d;
    int K;
    size_t lq;
    const int w = (int)(q >> 20);
    if (w < 5) {
        lq = q & 0xFFFFFu;
        K = Cn;
        if      (w == 0) { s = Wk_;  d = wk;  }
        else if (w == 1) { s = Wv_;  d = wv;  }
        else if (w == 2) { s = Wr_;  d = wr;  }
        else if (w == 3) { s = Wo_;  d = wo;  }
        else             { s = Wcr_; d = wcr; }
    } else if (q < (5ull << 20) + (1ull << 22)) {
        lq = q - (5ull << 20);
        s = Wck_; d = wck; K = Cn;
    } else {
        lq = q - (5ull << 20) - (1ull << 22);
        s = Wcv_; d = wcv; K = Hn;
    }
    const size_t idx = lq * 4;
    const int n = (int)(idx / K);
    const int k = (int)(idx % K);
    float4 v = *(const float4*)(s + idx);
    store_h4(v, d, bpack_off(n, k, K));
}

// ---------------------------------------------------------------------------
// Chunked-scan WKV (3 phases). The un-stabilized recurrence is linear in
// (a,b), so a length-L chunk is an affine transform; phase 1 computes each
// chunk's transform from the zero state (fully parallel over 16 chunks x
// 16384 lanes), phase 2 does a tiny 16-step sequential composition per lane,
// phase 3 replays chunks from their correct initial states emitting the
// sigmoid(r)-gated outputs.
// ---------------------------------------------------------------------------
__global__ __launch_bounds__(256) void wkv_p1(
    const float* __restrict__ k, const float* __restrict__ v,
    const float* __restrict__ w_decay,
    float* __restrict__ cA, float* __restrict__ cB, float* __restrict__ cP)
{
    const int gid = blockIdx.x * 256 + threadIdx.x;   // 0..NLANE*NCHUNK-1
    const int lane = gid & (NLANE - 1);
    const int chunk = gid >> 14;
    const int c = lane & (Cn - 1);
    const int b = lane >> 11;
    const float w = -expf(w_decay[c]);

    size_t off = (size_t)b * Tn * Cn + (size_t)(chunk * CLEN) * Cn + c;
    float aa = 0.f, bb = 0.f, pp = -1e38f;
#pragma unroll 4
    for (int t = 0; t < CLEN; t++, off += Cn) {
        const float kt = k[off];
        const float vt = v[off];
        const float ww2 = pp + w;
        const float p2  = fmaxf(ww2, kt);
        const float e1b = __expf(ww2 - p2);
        const float e2b = __expf(kt - p2);
        aa = e1b * aa + e2b * vt;
        bb = e1b * bb + e2b;
        pp = p2;
    }
    cA[gid] = aa; cB[gid] = bb; cP[gid] = pp;
}

__global__ __launch_bounds__(256) void wkv_p2(
    const float* __restrict__ w_decay,
    const float* __restrict__ cA, const float* __restrict__ cB,
    const float* __restrict__ cP,
    float* __restrict__ iA, float* __restrict__ iB, float* __restrict__ iP)
{
    const int lane = blockIdx.x * 256 + threadIdx.x;  // 0..NLANE-1
    const int c = lane & (Cn - 1);
    const float Lw = (float)CLEN * (-expf(w_decay[c]));

    float aa = 0.f, bb = 0.f, pp = -1e38f;
#pragma unroll
    for (int ch = 0; ch < NCHUNK; ch++) {
        const int idx = lane + ch * NLANE;
        iA[idx] = aa; iB[idx] = bb; iP[idx] = pp;
        const float A = cA[idx], B = cB[idx], P = cP[idx];
        const float pd = pp + Lw;
        const float pn = fmaxf(pd, P);
        const float ea = __expf(pd - pn);
        const float eb = __expf(P - pn);
        aa = aa * ea + A * eb;
        bb = bb * ea + B * eb;
        pp = pn;
    }
}

__global__ __launch_bounds__(256) void wkv_p3(
    const float* __restrict__ k, const float* __restrict__ v,
    const __half* __restrict__ rp,
    const float* __restrict__ w_decay, const float* __restrict__ u_first,
    const float* __restrict__ iA, const float* __restrict__ iB,
    const float* __restrict__ iP,
    __half* __restrict__ g)
{
    const int gid = blockIdx.x * 256 + threadIdx.x;
    const int lane = gid & (NLANE - 1);
    const int chunk = gid >> 14;
    const int c = lane & (Cn - 1);
    const int b = lane >> 11;
    const float w = -expf(w_decay[c]);
    const float u = u_first[c];

    float aa = iA[gid], bb = iB[gid], pp = iP[gid];
    int m = b * Tn + chunk * CLEN;
    size_t off = (size_t)b * Tn * Cn + (size_t)(chunk * CLEN) * Cn + c;
#pragma unroll 4
    for (int t = 0; t < CLEN; t++, off += Cn, m++) {
        const float kt = k[off];
        const float vt = v[off];
        const float rr = __half2float(rp[apack_off(m, c, Cn)]);

        const float ww = u + kt;
        const float pmx = fmaxf(pp, ww);
        const float e1 = __expf(pp - pmx);
        const float e2 = __expf(ww - pmx);
        const float y  = __fdividef(e1 * aa + e2 * vt, e1 * bb + e2);
        const float sg = __fdividef(1.f, 1.f + __expf(-rr));
        g[apack_off(m, c, Cn)] = __float2half_rn(y * sg);

        const float ww2 = pp + w;
        const float p2  = fmaxf(ww2, kt);
        const float e1b = __expf(ww2 - p2);
        const float e2b = __expf(kt - p2);
        aa = e1b * aa + e2b * vt;
        bb = e1b * bb + e2b;
        pp = p2;
    }
}

// ---------------------------------------------------------------------------
// GEMM constants (shared by both persistent GEMM kernels)
// ---------------------------------------------------------------------------
static constexpr int AT64 = A_TILE_H * 2;
static constexpr int BT64 = B_TILE_H * 2;
static constexpr int STAGE = 2 * (AT64 + BT64);   // 110592 B (BK=128)
static constexpr int SMEM_DYN = 2 * STAGE;        // 221184 B
static constexpr int GPERS = 148;

// ---------------------------------------------------------------------------
// Persistent HMMA fp16 GEMM over packed tiles (as in R16).
// ---------------------------------------------------------------------------
template <int EPI>
__global__ __launch_bounds__(256, 1) void gemmp(
    const __half* __restrict__ Ap, const __half* __restrict__ Bp,
    float* __restrict__ Cm, __half* __restrict__ Ohp,
    int N, int K, int ntiles,
    const float* __restrict__ res0, const float* __restrict__ res1)
{
    extern __shared__ __align__(128) char dsm[];
    __shared__ __align__(8) uint64_t s_mbar[4];

    const uint32_t sb = smem_u32(dsm);
    const uint32_t mbf = smem_u32(s_mbar);
    const uint32_t mbe = mbf + 16;
    const int tid = threadIdx.x, wid = tid >> 5, lane = tid & 31;
    const int wm = wid >> 2, wn = wid & 3;
    const int bid = blockIdx.x;
    const int nbx = N >> 8;
    const int nk = K >> 7;
    const int kt64 = K >> 6;

    const int ntpc = (ntiles - bid + GPERS - 1) / GPERS;
    if (ntpc <= 0) return;
    const int total = ntpc * nk;

    if (tid == 0) {
        MBAR_INIT(mbf + 0, 1);
        MBAR_INIT(mbf + 8, 1);
        MBAR_INIT(mbe + 0, 256);
        MBAR_INIT(mbe + 8, 256);
    }
    __syncthreads();

    if (tid == 0) {
        const int by0 = bid / nbx, bx0 = bid % nbx;
#pragma unroll
        for (int s = 0; s < 2; s++) {
            MBAR_EXPECT_TX(mbf + s * 8, STAGE);
            BULK_G2S(sb + s * STAGE,
                     Ap + ((size_t)by0 * kt64 + 2 * s) * A_TILE_H, 2 * AT64, mbf + s * 8);
            BULK_G2S(sb + s * STAGE + 2 * AT64,
                     Bp + ((size_t)bx0 * kt64 + 2 * s) * B_TILE_H, 2 * BT64, mbf + s * 8);
        }
    }

    const int a_row  = wm * 64 + (lane & 15);
    const int a_koff = (lane & 16) ? 8 : 0;
    const int b_row  = wn * 64 + (lane & 7) + ((lane & 16) ? 8 : 0);
    const int b_koff = (lane & 8) ? 8 : 0;

    int s = 0;
    uint32_t parf = 0, pare = 0;
    int seq = 0;

    for (int j = 0; j < ntpc; j++) {
        const int t = bid + j * GPERS;
        const int by = t / nbx, bx = t % nbx;
        const int m0 = by * 128, n0 = bx * 256;

        float acc[4][8][4];
#pragma unroll
        for (int a = 0; a < 4; a++)
#pragma unroll
            for (int b = 0; b < 8; b++)
#pragma unroll
                for (int c = 0; c < 4; c++) acc[a][b][c] = 0.f;

        for (int i = 0; i < nk; i++, seq++) {
            MBAR_WAIT(mbf + s * 8, (parf >> s) & 1u);
            parf ^= (1u << s);

            const uint32_t st = sb + s * STAGE;
#pragma unroll
            for (int half = 0; half < 2; half++) {
                const uint32_t abase = st + half * AT64;
                const uint32_t bbase = st + 2 * AT64 + half * BT64;
#pragma unroll
                for (int k16 = 0; k16 < 4; k16++) {
                    uint32_t ah[4][4];
                    const uint32_t acol = (uint32_t)(k16 * 16 + a_koff) * 2;
#pragma unroll
                    for (int mt = 0; mt < 4; mt++) {
                        const uint32_t ad = abase +
                            (uint32_t)(a_row + mt * 16) * (PADH * 2) + acol;
                        ldsm4(ah[mt][0], ah[mt][1], ah[mt][2], ah[mt][3], ad);
                    }
                    uint32_t bh[8][2];
                    const uint32_t bcol = (uint32_t)(k16 * 16 + b_koff) * 2;
#pragma unroll
                    for (int pq = 0; pq < 4; pq++) {
                        const uint32_t bd = bbase +
                            (uint32_t)(b_row + pq * 16) * (PADH * 2) + bcol;
                        ldsm4(bh[2*pq][0], bh[2*pq][1], bh[2*pq+1][0], bh[2*pq+1][1], bd);
                    }
#pragma unroll
                    for (int mt = 0; mt < 4; mt++)
#pragma unroll
                        for (int nt = 0; nt < 8; nt++)
                            mma16816(acc[mt][nt], ah[mt], bh[nt]);
                }
            }

            MBAR_ARRIVE(mbe + s * 8);

            if (tid == 0 && seq + 2 < total) {
                MBAR_WAIT(mbe + s * 8, (pare >> s) & 1u);
                pare ^= (1u << s);
                const int sq = seq + 2;
                const int j2 = sq / nk, i2 = sq - j2 * nk;
                const int t2 = bid + j2 * GPERS;
                const int by2 = t2 / nbx, bx2 = t2 % nbx;
                MBAR_EXPECT_TX(mbf + s * 8, STAGE);
                BULK_G2S(sb + s * STAGE,
                         Ap + ((size_t)by2 * kt64 + 2 * i2) * A_TILE_H,
                         2 * AT64, mbf + s * 8);
                BULK_G2S(sb + s * STAGE + 2 * AT64,
                         Bp + ((size_t)bx2 * kt64 + 2 * i2) * B_TILE_H,
                         2 * BT64, mbf + s * 8);
            }
            s ^= 1;
        }

        const int row_base = m0 + wm * 64 + (lane >> 2);
        const int col_base = n0 + wn * 64 + (lane & 3) * 2;
#pragma unroll
        for (int mt = 0; mt < 4; mt++) {
#pragma unroll
            for (int h = 0; h < 2; h++) {
                const int row = row_base + mt * 16 + h * 8;
#pragma unroll
                for (int nt = 0; nt < 8; nt++) {
                    float vx = acc[mt][nt][2 * h + 0];
                    float vy = acc[mt][nt][2 * h + 1];
                    const int col = col_base + nt * 8;
                    const size_t off = (size_t)row * N + col;
                    if (EPI == 0) {
                        *(float2*)(Cm + off) = make_float2(vx, vy);
                    } else if (EPI == 1) {
                        float2 r = *(const float2*)(res0 + off);
                        *(float2*)(Cm + off) = make_float2(vx + r.x, vy + r.y);
                    } else if (EPI == 2) {
                        vx = fmaxf(vx, 0.f); vx *= vx;
                        vy = fmaxf(vy, 0.f); vy *= vy;
                        *(uint32_t*)(Ohp + apack_off(row, col, N)) = pack2h(vx, vy);
                    } else if (EPI == 4) {
                        *(uint32_t*)(Ohp + apack_off(row, col, N)) = pack2h(vx, vy);
                    } else {
                        float2 r0 = *(const float2*)(res0 + off);
                        float2 r1 = *(const float2*)(res1 + off);
                        vx = r0.x + r1.x / (1.f + __expf(-vx));
                        vy = r0.y + r1.y / (1.f + __expf(-vy));
                        *(float2*)(Cm + off) = make_float2(vx, vy);
                    }
                }
            }
        }
    }
}

// ---------------------------------------------------------------------------
// Merged persistent GEMM for the three time-mix projections (as in R16).
// ---------------------------------------------------------------------------
__device__ __forceinline__ void kvr_resolve(
    int t, const __half* A0, const __half* A1, const __half* A2,
    const __half* W0, const __half* W1, const __half* W2,
    const __half*& Ap, const __half*& Bp, int& op, int& by, int& bx)
{
    op = t >> 10;
    const int tt = t & 1023;
    by = tt >> 3;
    bx = tt & 7;
    Ap = (op == 0) ? A0 : (op == 1) ? A1 : A2;
    Bp = (op == 0) ? W0 : (op == 1) ? W1 : W2;
}

__global__ __launch_bounds__(256, 1) void gemm_kvr(
    const __half* __restrict__ A0, const __half* __restrict__ A1,
    const __half* __restrict__ A2,
    const __half* __restrict__ W0, const __half* __restrict__ W1,
    const __half* __restrict__ W2,
    float* __restrict__ kf, float* __restrict__ vf, __half* __restrict__ rp)
{
    extern __shared__ __align__(128) char dsm[];
    __shared__ __align__(8) uint64_t s_mbar[4];

    const uint32_t sb = smem_u32(dsm);
    const uint32_t mbf = smem_u32(s_mbar);
    const uint32_t mbe = mbf + 16;
    const int tid = threadIdx.x, wid = tid >> 5, lane = tid & 31;
    const int wm = wid >> 2, wn = wid & 3;
    const int bid = blockIdx.x;
    const int nk = Cn >> 7;
    const int kt64 = Cn >> 6;
    const int ntiles = 3072;

    const int ntpc = (ntiles - bid + GPERS - 1) / GPERS;
    const int total = ntpc * nk;

    if (tid == 0) {
        MBAR_INIT(mbf + 0, 1);
        MBAR_INIT(mbf + 8, 1);
        MBAR_INIT(mbe + 0, 256);
        MBAR_INIT(mbe + 8, 256);
    }
    __syncthreads();

    if (tid == 0) {
        const __half *Ap, *Bp;
        int op, by0, bx0;
        kvr_resolve(bid, A0, A1, A2, W0, W1, W2, Ap, Bp, op, by0, bx0);
#pragma unroll
        for (int s = 0; s < 2; s++) {
            MBAR_EXPECT_TX(mbf + s * 8, STAGE);
            BULK_G2S(sb + s * STAGE,
                     Ap + ((size_t)by0 * kt64 + 2 * s) * A_TILE_H, 2 * AT64, mbf + s * 8);
            BULK_G2S(sb + s * STAGE + 2 * AT64,
                     Bp + ((size_t)bx0 * kt64 + 2 * s) * B_TILE_H, 2 * BT64, mbf + s * 8);
        }
    }

    const int a_row  = wm * 64 + (lane & 15);
    const int a_koff = (lane & 16) ? 8 : 0;
    const int b_row  = wn * 64 + (lane & 7) + ((lane & 16) ? 8 : 0);
    const int b_koff = (lane & 8) ? 8 : 0;

    int s = 0;
    uint32_t parf = 0, pare = 0;
    int seq = 0;

    for (int j = 0; j < ntpc; j++) {
        const int t = bid + j * GPERS;
        const __half *ApT, *BpT;
        int op, by, bx;
        kvr_resolve(t, A0, A1, A2, W0, W1, W2, ApT, BpT, op, by, bx);
        const int m0 = by * 128, n0 = bx * 256;

        float acc[4][8][4];
#pragma unroll
        for (int a = 0; a < 4; a++)
#pragma unroll
            for (int b = 0; b < 8; b++)
#pragma unroll
                for (int c = 0; c < 4; c++) acc[a][b][c] = 0.f;

        for (int i = 0; i < nk; i++, seq++) {
            MBAR_WAIT(mbf + s * 8, (parf >> s) & 1u);
            parf ^= (1u << s);

            const uint32_t st = sb + s * STAGE;
#pragma unroll
            for (int half = 0; half < 2; half++) {
                const uint32_t abase = st + half * AT64;
                const uint32_t bbase = st + 2 * AT64 + half * BT64;
#pragma unroll
                for (int k16 = 0; k16 < 4; k16++) {
                    uint32_t ah[4][4];
                    const uint32_t acol = (uint32_t)(k16 * 16 + a_koff) * 2;
#pragma unroll
                    for (int mt = 0; mt < 4; mt++) {
                        const uint32_t ad = abase +
                            (uint32_t)(a_row + mt * 16) * (PADH * 2) + acol;
                        ldsm4(ah[mt][0], ah[mt][1], ah[mt][2], ah[mt][3], ad);
                    }
                    uint32_t bh[8][2];
                    const uint32_t bcol = (uint32_t)(k16 * 16 + b_koff) * 2;
#pragma unroll
                    for (int pq = 0; pq < 4; pq++) {
                        const uint32_t bd = bbase +
                            (uint32_t)(b_row + pq * 16) * (PADH * 2) + bcol;
                        ldsm4(bh[2*pq][0], bh[2*pq][1], bh[2*pq+1][0], bh[2*pq+1][1], bd);
                    }
#pragma unroll
                    for (int mt = 0; mt < 4; mt++)
#pragma unroll
                        for (int nt = 0; nt < 8; nt++)
                            mma16816(acc[mt][nt], ah[mt], bh[nt]);
                }
            }

            MBAR_ARRIVE(mbe + s * 8);

            if (tid == 0 && seq + 2 < total) {
                MBAR_WAIT(mbe + s * 8, (pare >> s) & 1u);
                pare ^= (1u << s);
                const int sq = seq + 2;
                const int j2 = sq / nk, i2 = sq - j2 * nk;
                const int t2 = bid + j2 * GPERS;
                const __half *Ap2, *Bp2;
                int op2, by2, bx2;
                kvr_resolve(t2, A0, A1, A2, W0, W1, W2, Ap2, Bp2, op2, by2, bx2);
                MBAR_EXPECT_TX(mbf + s * 8, STAGE);
                BULK_G2S(sb + s * STAGE,
                         Ap2 + ((size_t)by2 * kt64 + 2 * i2) * A_TILE_H,
                         2 * AT64, mbf + s * 8);
                BULK_G2S(sb + s * STAGE + 2 * AT64,
                         Bp2 + ((size_t)bx2 * kt64 + 2 * i2) * B_TILE_H,
                         2 * BT64, mbf + s * 8);
            }
            s ^= 1;
        }

        const int row_base = m0 + wm * 64 + (lane >> 2);
        const int col_base = n0 + wn * 64 + (lane & 3) * 2;
        if (op < 2) {
            float* Cm = (op == 0) ? kf : vf;
#pragma unroll
            for (int mt = 0; mt < 4; mt++)
#pragma unroll
                for (int h = 0; h < 2; h++) {
                    const int row = row_base + mt * 16 + h * 8;
#pragma unroll
                    for (int nt = 0; nt < 8; nt++) {
                        const size_t off = (size_t)row * Cn + col_base + nt * 8;
                        *(float2*)(Cm + off) =
                            make_float2(acc[mt][nt][2 * h + 0], acc[mt][nt][2 * h + 1]);
                    }
                }
        } else {
#pragma unroll
            for (int mt = 0; mt < 4; mt++)
#pragma unroll
                for (int h = 0; h < 2; h++) {
                    const int row = row_base + mt * 16 + h * 8;
#pragma unroll
                    for (int nt = 0; nt < 8; nt++) {
                        const int col = col_base + nt * 8;
                        *(uint32_t*)(rp + apack_off(row, col, Cn)) =
                            pack2h(acc[mt][nt][2 * h + 0], acc[mt][nt][2 * h + 1]);
                    }
                }
        }
    }
}

// ---------------------------------------------------------------------------
// Launch
// ---------------------------------------------------------------------------
extern "C" void kernel_launch(void* const* d_in, const int* in_sizes, int n_in,
                              void* d_out, int out_size)
{
    (void)in_sizes; (void)n_in; (void)out_size;
    const float* x    = (const float*)d_in[0];
    const float* ln1w = (const float*)d_in[1];
    const float* ln1b = (const float*)d_in[2];
    const float* ln2w = (const float*)d_in[3];
    const float* ln2b = (const float*)d_in[4];
    const float* tdec = (const float*)d_in[5];
    const float* tfir = (const float*)d_in[6];
    const float* tmk  = (const float*)d_in[7];
    const float* tmv  = (const float*)d_in[8];
    const float* tmr  = (const float*)d_in[9];
    const float* Wk   = (const float*)d_in[10];
    const float* Wv   = (const float*)d_in[11];
    const float* Wr   = (const float*)d_in[12];
    const float* Wo   = (const float*)d_in[13];
    const float* cmk  = (const float*)d_in[14];
    const float* cmr  = (const float*)d_in[15];
    const float* Wck  = (const float*)d_in[16];
    const float* Wcv  = (const float*)d_in[17];
    const float* Wcr  = (const float*)d_in[18];
    float* out = (float*)d_out;

    float *kf, *vf, *x1, *kv;
    __half *a0, *a1, *a2, *hb;
    __half *wk, *wv, *wr, *wo, *wck, *wcv, *wcr;
    float *cA, *cB, *cP, *iA, *iB, *iP;
    cudaGetSymbolAddress((void**)&kf, g_k);
    cudaGetSymbolAddress((void**)&vf, g_v);
    cudaGetSymbolAddress((void**)&x1, g_x1);
    cudaGetSymbolAddress((void**)&kv, g_kv);
    cudaGetSymbolAddress((void**)&a0, g_a0);
    cudaGetSymbolAddress((void**)&a1, g_a1);
    cudaGetSymbolAddress((void**)&a2, g_a2);
    cudaGetSymbolAddress((void**)&hb, g_h);
    cudaGetSymbolAddress((void**)&wk, g_wk);
    cudaGetSymbolAddress((void**)&wv, g_wv);
    cudaGetSymbolAddress((void**)&wr, g_wr);
    cudaGetSymbolAddress((void**)&wo, g_wo);
    cudaGetSymbolAddress((void**)&wck, g_wck);
    cudaGetSymbolAddress((void**)&wcv, g_wcv);
    cudaGetSymbolAddress((void**)&wcr, g_wcr);
    cudaGetSymbolAddress((void**)&cA, g_cA);
    cudaGetSymbolAddress((void**)&cB, g_cB);
    cudaGetSymbolAddress((void**)&cP, g_cP);
    cudaGetSymbolAddress((void**)&iA, g_iA);
    cudaGetSymbolAddress((void**)&iB, g_iB);
    cudaGetSymbolAddress((void**)&iP, g_iP);

    cudaFuncSetAttribute(gemmp<0>, cudaFuncAttributeMaxDynamicSharedMemorySize, SMEM_DYN);
    cudaFuncSetAttribute(gemmp<1>, cudaFuncAttributeMaxDynamicSharedMemorySize, SMEM_DYN);
    cudaFuncSetAttribute(gemmp<2>, cudaFuncAttributeMaxDynamicSharedMemorySize, SMEM_DYN);
    cudaFuncSetAttribute(gemmp<3>, cudaFuncAttributeMaxDynamicSharedMemorySize, SMEM_DYN);
    cudaFuncSetAttribute(gemm_kvr, cudaFuncAttributeMaxDynamicSharedMemorySize, SMEM_DYN);

    const int tC = (Mn / 128) * (Cn / 256);   // 1024 tiles
    const int tH = (Mn / 128) * (Hn / 256);   // 4096 tiles
    const int convBlocks = (5 * (1 << 20) + 2 * (1 << 22)) / 256;

    conv_all<<<convBlocks, 256>>>(Wk, Wv, Wr, Wo, Wcr, Wck, Wcv,
                                  wk, wv, wr, wo, wcr, wck, wcv);

    // --- time-mix attention ---
    ln_mix<3><<<Mn, 256>>>(x, ln1w, ln1b, tmk, tmv, tmr, a0, a1, a2);

    gemm_kvr<<<GPERS, 256, SMEM_DYN>>>(a0, a1, a2, wk, wv, wr, kf, vf, a0);

    // chunked-scan WKV (3 phases)
    wkv_p1<<<(NLANE * NCHUNK) / 256, 256>>>(kf, vf, tdec, cA, cB, cP);
    wkv_p2<<<NLANE / 256, 256>>>(tdec, cA, cB, cP, iA, iB, iP);
    wkv_p3<<<(NLANE * NCHUNK) / 256, 256>>>(kf, vf, a0, tdec, tfir,
                                            iA, iB, iP, a1);

    gemmp<1><<<GPERS, 256, SMEM_DYN>>>(a1, wo, x1, nullptr, Cn, Cn, tC, x, nullptr);

    // --- channel mix ---
    ln_mix<2><<<Mn, 256>>>(x1, ln2w, ln2b, cmk, cmr, nullptr, a0, a2, nullptr);

    gemmp<2><<<GPERS, 256, SMEM_DYN>>>(a0, wck, nullptr, hb, Hn, Cn, tH, nullptr, nullptr);
    gemmp<0><<<GPERS, 256, SMEM_DYN>>>(hb, wcv, kv, nullptr, Cn, Hn, tC, nullptr, nullptr);
    gemmp<3><<<GPERS, 256, SMEM_DYN>>>(a2, wcr, out, nullptr, Cn, Cn, tC, x1, kv);
}